// round 1
// baseline (speedup 1.0000x reference)
#include <cuda_runtime.h>
#include <cuda_bf16.h>
#include <cstdint>

// Problem constants
#define Bq   4
#define Sq   2048
#define Dq   512
#define Hq   8
#define DKq  64
#define DVq  64
#define LN_EPS 1e-5f

// Scratch (device globals: allocation-free rule)
__device__ float g_Q[(size_t)Bq*Hq*Sq*DKq];     // [B,H,S,64]
__device__ float g_K[(size_t)Bq*Hq*Sq*DKq];
__device__ float g_V[(size_t)Bq*Hq*Sq*DVq];
__device__ float g_ctx[(size_t)Bq*Sq*Dq];       // [B,S,512]
__device__ float g_pre[(size_t)Bq*Sq*Dq];       // fc out + residual

// ---------------------------------------------------------------------------
// Tiled fp32 GEMM: C[M=8192, N=512] = A[M,512] @ W[512,512]
// BM=64 BN=64 BK=32, 256 threads, 4x4 micro-tile.
// MODE 0: out permuted to [B,H,S,64] (QKV projection)
// MODE 1: out[m*512+n] = acc + resid[m*512+n]   (fc + residual)
// ---------------------------------------------------------------------------
template <int MODE>
__global__ __launch_bounds__(256)
void gemm64(const float* __restrict__ A, const float* __restrict__ W,
            float* __restrict__ out, const float* __restrict__ resid)
{
    __shared__ float As[32 * 68];   // [k][m], padded row 68
    __shared__ float Bs[32 * 68];   // [k][n], padded row 68

    const int tid = threadIdx.x;
    const int tx  = tid & 15;       // 0..15  (n)
    const int ty  = tid >> 4;       // 0..15  (m)
    const int n0  = blockIdx.x * 64;
    const int m0b = blockIdx.y * 64;

    float acc[4][4];
#pragma unroll
    for (int i = 0; i < 4; i++)
#pragma unroll
        for (int j = 0; j < 4; j++) acc[i][j] = 0.f;

    for (int k0 = 0; k0 < 512; k0 += 32) {
        // load A tile (64m x 32k) transposed into As[k][m]
#pragma unroll
        for (int l = tid; l < 512; l += 256) {        // 512 float4
            int m_l = l >> 3;                          // 8 float4 per row
            int kq  = (l & 7) * 4;
            float4 v = *(const float4*)(A + (size_t)(m0b + m_l) * 512 + k0 + kq);
            As[(kq + 0) * 68 + m_l] = v.x;
            As[(kq + 1) * 68 + m_l] = v.y;
            As[(kq + 2) * 68 + m_l] = v.z;
            As[(kq + 3) * 68 + m_l] = v.w;
        }
        // load W tile (32k x 64n) into Bs[k][n]
#pragma unroll
        for (int l = tid; l < 512; l += 256) {
            int k_l = l >> 4;                          // 16 float4 per row
            int nq  = (l & 15) * 4;
            float4 v = *(const float4*)(W + (size_t)(k0 + k_l) * 512 + n0 + nq);
            *(float4*)&Bs[k_l * 68 + nq] = v;
        }
        __syncthreads();

#pragma unroll
        for (int k = 0; k < 32; k++) {
            float4 a = *(float4*)&As[k * 68 + ty * 4];
            float4 b = *(float4*)&Bs[k * 68 + tx * 4];
            acc[0][0] += a.x * b.x; acc[0][1] += a.x * b.y; acc[0][2] += a.x * b.z; acc[0][3] += a.x * b.w;
            acc[1][0] += a.y * b.x; acc[1][1] += a.y * b.y; acc[1][2] += a.y * b.z; acc[1][3] += a.y * b.w;
            acc[2][0] += a.z * b.x; acc[2][1] += a.z * b.y; acc[2][2] += a.z * b.z; acc[2][3] += a.z * b.w;
            acc[3][0] += a.w * b.x; acc[3][1] += a.w * b.y; acc[3][2] += a.w * b.z; acc[3][3] += a.w * b.w;
        }
        __syncthreads();
    }

    if (MODE == 0) {
        // n in [n0, n0+64) -> single head h = blockIdx.x, e = tx*4..+3
        const int h  = blockIdx.x;
        const int e0 = tx * 4;
#pragma unroll
        for (int i = 0; i < 4; i++) {
            int m = m0b + ty * 4 + i;
            int b = m >> 11;            // /2048
            int s = m & 2047;
            float4 r = make_float4(acc[i][0], acc[i][1], acc[i][2], acc[i][3]);
            *(float4*)&out[(((size_t)b * Hq + h) * Sq + s) * 64 + e0] = r;
        }
    } else {
#pragma unroll
        for (int i = 0; i < 4; i++) {
            int m = m0b + ty * 4 + i;
            float4 rv = *(const float4*)&resid[(size_t)m * 512 + n0 + tx * 4];
            float4 r = make_float4(acc[i][0] + rv.x, acc[i][1] + rv.y,
                                   acc[i][2] + rv.z, acc[i][3] + rv.w);
            *(float4*)&out[(size_t)m * 512 + n0 + tx * 4] = r;
        }
    }
}

// ---------------------------------------------------------------------------
// Fused attention: one CTA per (b*H+h, q-tile of 16).
// smem: qsT[64][20], ks/vs[64][65], scores[16][2048]  -> 152832 B dynamic
// ---------------------------------------------------------------------------
__global__ __launch_bounds__(256)
void attn_kernel(const float* __restrict__ Qm, const float* __restrict__ Km,
                 const float* __restrict__ Vm, const unsigned* __restrict__ mask,
                 float* __restrict__ attn_out, float* __restrict__ ctx)
{
    extern __shared__ float sm[];
    float* qsT    = sm;                       // 64*20
    float* ks     = sm + 64 * 20;             // 64*65
    float* scores = sm + 64 * 20 + 64 * 65;   // 16*2048

    const int bh  = blockIdx.x;               // 0..31
    const int qt  = blockIdx.y;               // 0..127
    const int b   = bh >> 3;
    const int tid = threadIdx.x;
    const int kloc = tid & 63;                 // k (phase2) / d (phase5)
    const int qb   = (tid >> 6) * 4;           // 0,4,8,12

    const float* Qbase = Qm + ((size_t)bh * Sq + qt * 16) * 64;

    // Q tile -> transposed smem
    for (int i = tid; i < 16 * 64; i += 256) {
        int q = i >> 6, d = i & 63;
        qsT[d * 20 + q] = Qbase[q * 64 + d];
    }
    __syncthreads();

    // ---- phase 2: raw scores ----
    for (int kt = 0; kt < 32; kt++) {
        const float* Kb = Km + ((size_t)bh * Sq + kt * 64) * 64;
        for (int i = tid * 4; i < 64 * 64; i += 1024) {
            float4 v = *(const float4*)(Kb + i);
            int r = i >> 6, c = i & 63;
            ks[r * 65 + c + 0] = v.x; ks[r * 65 + c + 1] = v.y;
            ks[r * 65 + c + 2] = v.z; ks[r * 65 + c + 3] = v.w;
        }
        __syncthreads();

        float a0 = 0.f, a1 = 0.f, a2 = 0.f, a3 = 0.f;
#pragma unroll
        for (int d = 0; d < 64; d++) {
            float kv = ks[kloc * 65 + d];
            float4 qv = *(float4*)&qsT[d * 20 + qb];
            a0 += qv.x * kv; a1 += qv.y * kv; a2 += qv.z * kv; a3 += qv.w * kv;
        }
        int col = kt * 64 + kloc;
        scores[(qb + 0) * 2048 + col] = a0;
        scores[(qb + 1) * 2048 + col] = a1;
        scores[(qb + 2) * 2048 + col] = a2;
        scores[(qb + 3) * 2048 + col] = a3;
        __syncthreads();
    }

    // ---- phase 3/4: mask + softmax + attn write ----
    {
        const int warp = tid >> 5, lane = tid & 31;
#pragma unroll
        for (int rr = 0; rr < 2; rr++) {
            int row = warp * 2 + rr;
            int qg = qt * 16 + row;
            const unsigned* mrow = mask + ((size_t)b * Sq + qg) * Sq;
            float* srow = scores + row * 2048;

            float mx = -1e30f;
            for (int k = lane; k < 2048; k += 32) {
                float s = srow[k];
                s = mrow[k] ? -1e9f : s * 0.125f;   // 1/sqrt(64)
                srow[k] = s;
                mx = fmaxf(mx, s);
            }
#pragma unroll
            for (int o = 16; o; o >>= 1) mx = fmaxf(mx, __shfl_xor_sync(0xffffffffu, mx, o));

            float sum = 0.f;
            for (int k = lane; k < 2048; k += 32) {
                float p = __expf(srow[k] - mx);
                srow[k] = p;
                sum += p;
            }
#pragma unroll
            for (int o = 16; o; o >>= 1) sum += __shfl_xor_sync(0xffffffffu, sum, o);
            float inv = 1.0f / sum;

            if (attn_out) {
                float* arow = attn_out + ((size_t)bh * Sq + qg) * Sq;
                for (int k = lane; k < 2048; k += 32) {
                    float p = srow[k] * inv;
                    srow[k] = p;
                    arow[k] = p;
                }
            } else {
                for (int k = lane; k < 2048; k += 32) srow[k] *= inv;
            }
        }
    }
    __syncthreads();

    // ---- phase 5: context = attn @ V ----
    float c0 = 0.f, c1 = 0.f, c2 = 0.f, c3 = 0.f;
    for (int kt = 0; kt < 32; kt++) {
        const float* Vb = Vm + ((size_t)bh * Sq + kt * 64) * 64;
        for (int i = tid * 4; i < 64 * 64; i += 1024) {
            float4 v = *(const float4*)(Vb + i);
            int r = i >> 6, c = i & 63;
            ks[r * 65 + c + 0] = v.x; ks[r * 65 + c + 1] = v.y;
            ks[r * 65 + c + 2] = v.z; ks[r * 65 + c + 3] = v.w;
        }
        __syncthreads();
#pragma unroll
        for (int kl = 0; kl < 64; kl++) {
            float v = ks[kl * 65 + kloc];
            int kg = kt * 64 + kl;
            c0 += scores[(qb + 0) * 2048 + kg] * v;
            c1 += scores[(qb + 1) * 2048 + kg] * v;
            c2 += scores[(qb + 2) * 2048 + kg] * v;
            c3 += scores[(qb + 3) * 2048 + kg] * v;
        }
        __syncthreads();
    }
    {
        const int h = bh & 7;
        int qg = qt * 16 + qb;
        ctx[((size_t)b * Sq + qg + 0) * Dq + h * 64 + kloc] = c0;
        ctx[((size_t)b * Sq + qg + 1) * Dq + h * 64 + kloc] = c1;
        ctx[((size_t)b * Sq + qg + 2) * Dq + h * 64 + kloc] = c2;
        ctx[((size_t)b * Sq + qg + 3) * Dq + h * 64 + kloc] = c3;
    }
}

// ---------------------------------------------------------------------------
// LayerNorm over last dim (512). One 128-thread block per row.
// ---------------------------------------------------------------------------
__global__ __launch_bounds__(128)
void ln_kernel(const float* __restrict__ x, const float* __restrict__ gamma,
               const float* __restrict__ beta, float* __restrict__ out)
{
    const int row = blockIdx.x;
    const int tid = threadIdx.x;
    const float* xr = x + (size_t)row * 512;

    float4 v = *(const float4*)(xr + tid * 4);
    float s  = v.x + v.y + v.z + v.w;
    float ss = v.x * v.x + v.y * v.y + v.z * v.z + v.w * v.w;

    const int lane = tid & 31, warp = tid >> 5;
#pragma unroll
    for (int o = 16; o; o >>= 1) {
        s  += __shfl_xor_sync(0xffffffffu, s, o);
        ss += __shfl_xor_sync(0xffffffffu, ss, o);
    }
    __shared__ float sh_s[4], sh_ss[4];
    if (lane == 0) { sh_s[warp] = s; sh_ss[warp] = ss; }
    __syncthreads();
    float tot  = sh_s[0] + sh_s[1] + sh_s[2] + sh_s[3];
    float tots = sh_ss[0] + sh_ss[1] + sh_ss[2] + sh_ss[3];

    float mu   = tot * (1.0f / 512.0f);
    float var  = tots * (1.0f / 512.0f) - mu * mu;
    float rstd = rsqrtf(var + LN_EPS);

    float4 g  = *(const float4*)(gamma + tid * 4);
    float4 be = *(const float4*)(beta + tid * 4);
    float4 r;
    r.x = (v.x - mu) * rstd * g.x + be.x;
    r.y = (v.y - mu) * rstd * g.y + be.y;
    r.z = (v.z - mu) * rstd * g.z + be.z;
    r.w = (v.w - mu) * rstd * g.w + be.w;
    *(float4*)&out[(size_t)row * 512 + tid * 4] = r;
}

// ---------------------------------------------------------------------------
extern "C" void kernel_launch(void* const* d_in, const int* in_sizes, int n_in,
                              void* d_out, int out_size)
{
    const float*    inQ   = (const float*)d_in[0];
    const float*    inK   = (const float*)d_in[1];
    const float*    inV   = (const float*)d_in[2];
    const unsigned* mask  = (const unsigned*)d_in[3];  // bool promoted to 4-byte: nonzero test works for f32 or i32
    const float*    WQ    = (const float*)d_in[4];
    const float*    WK    = (const float*)d_in[5];
    const float*    WV    = (const float*)d_in[6];
    const float*    Wfc   = (const float*)d_in[7];
    const float*    gamma = (const float*)d_in[8];
    const float*    beta  = (const float*)d_in[9];
    float* out = (float*)d_out;

    float *gQ, *gK, *gV, *gctx, *gpre;
    cudaGetSymbolAddress((void**)&gQ,   g_Q);
    cudaGetSymbolAddress((void**)&gK,   g_K);
    cudaGetSymbolAddress((void**)&gV,   g_V);
    cudaGetSymbolAddress((void**)&gctx, g_ctx);
    cudaGetSymbolAddress((void**)&gpre, g_pre);

    dim3 ggrid(8, 128), gblk(256);
    gemm64<0><<<ggrid, gblk>>>(inQ, WQ, gQ, nullptr);
    gemm64<0><<<ggrid, gblk>>>(inK, WK, gK, nullptr);
    gemm64<0><<<ggrid, gblk>>>(inV, WV, gV, nullptr);

    const size_t BSD  = (size_t)Bq * Sq * Dq;          // 4,194,304
    const size_t BHSS = (size_t)Bq * Hq * Sq * Sq;     // 134,217,728
    float* attn_ptr = ((size_t)out_size >= BSD + BHSS) ? (out + BSD) : nullptr;

    size_t smem = (size_t)(64 * 20 + 64 * 65 + 16 * 2048) * sizeof(float);  // 152832
    cudaFuncSetAttribute(attn_kernel, cudaFuncAttributeMaxDynamicSharedMemorySize, (int)smem);
    attn_kernel<<<dim3(32, 128), 256, smem>>>(gQ, gK, gV, mask, attn_ptr, gctx);

    gemm64<1><<<ggrid, gblk>>>(gctx, Wfc, gpre, inQ);
    ln_kernel<<<Bq * Sq, 128>>>(gpre, gamma, beta, out);
}

// round 2
// speedup vs baseline: 1.2438x; 1.2438x over previous
#include <cuda_runtime.h>
#include <cuda_bf16.h>
#include <cstdint>

// Problem constants
#define Bq   4
#define Sq   2048
#define Dq   512
#define Hq   8
#define DKq  64
#define DVq  64
#define LN_EPS 1e-5f

// attn smem layout constants
#define SST  2056   // scores row stride (floats), 2048+8 -> 2-way max conflicts
#define KSP  68     // K/V tile row stride (floats), 64+4 -> conflict-free B-frag loads

// Scratch (device globals: allocation-free rule)
__device__ float g_Q[(size_t)Bq*Hq*Sq*DKq];     // [B,H,S,64]
__device__ float g_K[(size_t)Bq*Hq*Sq*DKq];
__device__ float g_V[(size_t)Bq*Hq*Sq*DVq];
__device__ float g_ctx[(size_t)Bq*Sq*Dq];       // [B,S,512]
__device__ float g_pre[(size_t)Bq*Sq*Dq];       // fc out + residual

// ---------------------------------------------------------------------------
// fp32 -> tf32 (round to nearest) ; result is fp32-bit-layout with truncated mantissa
// ---------------------------------------------------------------------------
__device__ __forceinline__ uint32_t f2tf(float x) {
    uint32_t r;
    asm("cvt.rna.tf32.f32 %0, %1;" : "=r"(r) : "f"(x));
    return r;
}

// mma.sync m16n8k8 tf32: D = A(16x8) * B(8x8) + D
__device__ __forceinline__ void mma8(float* c, const uint32_t* a, uint32_t b0, uint32_t b1) {
    asm volatile(
        "mma.sync.aligned.m16n8k8.row.col.f32.tf32.tf32.f32 "
        "{%0,%1,%2,%3}, {%4,%5,%6,%7}, {%8,%9}, {%0,%1,%2,%3};"
        : "+f"(c[0]), "+f"(c[1]), "+f"(c[2]), "+f"(c[3])
        : "r"(a[0]), "r"(a[1]), "r"(a[2]), "r"(a[3]), "r"(b0), "r"(b1));
}

// ---------------------------------------------------------------------------
// Tiled fp32 GEMM: C[M=8192, N=512] = A[M,512] @ W[512,512]
// MODE 0: out permuted to [B,H,S,64] (QKV projection)
// MODE 1: out[m*512+n] = acc + resid[m*512+n]   (fc + residual)
// ---------------------------------------------------------------------------
template <int MODE>
__global__ __launch_bounds__(256)
void gemm64(const float* __restrict__ A, const float* __restrict__ W,
            float* __restrict__ out, const float* __restrict__ resid)
{
    __shared__ float As[32 * 68];   // [k][m]
    __shared__ float Bs[32 * 68];   // [k][n]

    const int tid = threadIdx.x;
    const int tx  = tid & 15;
    const int ty  = tid >> 4;
    const int n0  = blockIdx.x * 64;
    const int m0b = blockIdx.y * 64;

    float acc[4][4];
#pragma unroll
    for (int i = 0; i < 4; i++)
#pragma unroll
        for (int j = 0; j < 4; j++) acc[i][j] = 0.f;

    for (int k0 = 0; k0 < 512; k0 += 32) {
#pragma unroll
        for (int l = tid; l < 512; l += 256) {
            int m_l = l >> 3;
            int kq  = (l & 7) * 4;
            float4 v = *(const float4*)(A + (size_t)(m0b + m_l) * 512 + k0 + kq);
            As[(kq + 0) * 68 + m_l] = v.x;
            As[(kq + 1) * 68 + m_l] = v.y;
            As[(kq + 2) * 68 + m_l] = v.z;
            As[(kq + 3) * 68 + m_l] = v.w;
        }
#pragma unroll
        for (int l = tid; l < 512; l += 256) {
            int k_l = l >> 4;
            int nq  = (l & 15) * 4;
            float4 v = *(const float4*)(W + (size_t)(k0 + k_l) * 512 + n0 + nq);
            *(float4*)&Bs[k_l * 68 + nq] = v;
        }
        __syncthreads();

#pragma unroll
        for (int k = 0; k < 32; k++) {
            float4 a = *(float4*)&As[k * 68 + ty * 4];
            float4 b = *(float4*)&Bs[k * 68 + tx * 4];
            acc[0][0] += a.x * b.x; acc[0][1] += a.x * b.y; acc[0][2] += a.x * b.z; acc[0][3] += a.x * b.w;
            acc[1][0] += a.y * b.x; acc[1][1] += a.y * b.y; acc[1][2] += a.y * b.z; acc[1][3] += a.y * b.w;
            acc[2][0] += a.z * b.x; acc[2][1] += a.z * b.y; acc[2][2] += a.z * b.z; acc[2][3] += a.z * b.w;
            acc[3][0] += a.w * b.x; acc[3][1] += a.w * b.y; acc[3][2] += a.w * b.z; acc[3][3] += a.w * b.w;
        }
        __syncthreads();
    }

    if (MODE == 0) {
        const int h  = blockIdx.x;
        const int e0 = tx * 4;
#pragma unroll
        for (int i = 0; i < 4; i++) {
            int m = m0b + ty * 4 + i;
            int b = m >> 11;
            int s = m & 2047;
            float4 r = make_float4(acc[i][0], acc[i][1], acc[i][2], acc[i][3]);
            *(float4*)&out[(((size_t)b * Hq + h) * Sq + s) * 64 + e0] = r;
        }
    } else {
#pragma unroll
        for (int i = 0; i < 4; i++) {
            int m = m0b + ty * 4 + i;
            float4 rv = *(const float4*)&resid[(size_t)m * 512 + n0 + tx * 4];
            float4 r = make_float4(acc[i][0] + rv.x, acc[i][1] + rv.y,
                                   acc[i][2] + rv.z, acc[i][3] + rv.w);
            *(float4*)&out[(size_t)m * 512 + n0 + tx * 4] = r;
        }
    }
}

// ---------------------------------------------------------------------------
// Fused attention with mma.sync tf32.
// One CTA per (b*H+h, q-tile of 16). 256 threads = 8 warps.
//   phase 2: scores = Q @ K^T via 3xTF32 (fp32-grade accuracy)
//   phase 3: masked softmax, exact fp32 attn written to global,
//            tf32-rounded P stored in smem
//   phase 5: ctx = P @ V via single tf32
// smem: scores[16][SST] + kv tile[64][KSP] + q stage[16][KSP]
// ---------------------------------------------------------------------------
__global__ __launch_bounds__(256, 1)
void attn_kernel(const float* __restrict__ Qm, const float* __restrict__ Km,
                 const float* __restrict__ Vm, const unsigned* __restrict__ mask,
                 float* __restrict__ attn_out, float* __restrict__ ctx)
{
    extern __shared__ float sm[];
    float* scores = sm;                          // 16*SST
    float* ks     = sm + 16 * SST;               // 64*KSP (K tile, then V tile)
    float* qs     = ks + 64 * KSP;               // 16*KSP

    const int bh  = blockIdx.x;                  // 0..31
    const int qt  = blockIdx.y;                  // 0..127
    const int b   = bh >> 3;
    const int h   = bh & 7;
    const int tid = threadIdx.x;
    const int warp = tid >> 5;
    const int lane = tid & 31;
    const int g = lane >> 2;                     // group id 0..7
    const int t = lane & 3;                      // thread-in-group 0..3

    // ---- stage Q tile [16,64] ----
    const float* Qbase = Qm + ((size_t)bh * Sq + qt * 16) * 64;
    for (int i = tid; i < 16 * 64; i += 256) {
        int r = i >> 6, d = i & 63;
        qs[r * KSP + d] = Qbase[i];
    }
    __syncthreads();

    // ---- Q fragments (hi/lo tf32 split), 8 k-subtiles ----
    uint32_t qhi[8][4], qlo[8][4];
#pragma unroll
    for (int sub = 0; sub < 8; sub++) {
        int d0 = sub * 8;
        float f0 = qs[g * KSP + d0 + t];
        float f1 = qs[(g + 8) * KSP + d0 + t];
        float f2 = qs[g * KSP + d0 + t + 4];
        float f3 = qs[(g + 8) * KSP + d0 + t + 4];
        qhi[sub][0] = f2tf(f0); qlo[sub][0] = f2tf(f0 - __uint_as_float(qhi[sub][0]));
        qhi[sub][1] = f2tf(f1); qlo[sub][1] = f2tf(f1 - __uint_as_float(qhi[sub][1]));
        qhi[sub][2] = f2tf(f2); qlo[sub][2] = f2tf(f2 - __uint_as_float(qhi[sub][2]));
        qhi[sub][3] = f2tf(f3); qlo[sub][3] = f2tf(f3 - __uint_as_float(qhi[sub][3]));
    }

    // ---- phase 2: scores = Q @ K^T (3xTF32) ----
    const int n0 = warp * 8;                     // this warp's k-position slice within tile
    for (int kt = 0; kt < 32; kt++) {
        const int kb = kt * 64;
        const float* Kb = Km + ((size_t)bh * Sq + kb) * 64;
        __syncthreads();                          // ks consumed by previous iter
        for (int i = tid * 4; i < 64 * 64; i += 1024) {
            float4 v = *(const float4*)(Kb + i);
            *(float4*)&ks[(i >> 6) * KSP + (i & 63)] = v;
        }
        __syncthreads();

        float acc[2][4] = {{0.f,0.f,0.f,0.f},{0.f,0.f,0.f,0.f}};
#pragma unroll
        for (int sub = 0; sub < 8; sub++) {
            int d0 = sub * 8;
            float bf0 = ks[(n0 + g) * KSP + d0 + t];
            float bf1 = ks[(n0 + g) * KSP + d0 + t + 4];
            uint32_t bH0 = f2tf(bf0), bH1 = f2tf(bf1);
            uint32_t bL0 = f2tf(bf0 - __uint_as_float(bH0));
            uint32_t bL1 = f2tf(bf1 - __uint_as_float(bH1));
            mma8(acc[sub & 1], qhi[sub], bH0, bH1);
            mma8(acc[sub & 1], qlo[sub], bH0, bH1);
            mma8(acc[sub & 1], qhi[sub], bL0, bL1);
        }
        int col = kb + n0 + 2 * t;
        float2 r0 = make_float2(acc[0][0] + acc[1][0], acc[0][1] + acc[1][1]);
        float2 r1 = make_float2(acc[0][2] + acc[1][2], acc[0][3] + acc[1][3]);
        *(float2*)&scores[g * SST + col]       = r0;
        *(float2*)&scores[(g + 8) * SST + col] = r1;
    }
    __syncthreads();

    // ---- phase 3/4: mask + softmax; exact fp32 attn out; tf32 P into smem ----
    {
#pragma unroll
        for (int rr = 0; rr < 2; rr++) {
            int row = warp * 2 + rr;
            int qg  = qt * 16 + row;
            const unsigned* mrow = mask + ((size_t)b * Sq + qg) * Sq;
            float* srow = scores + row * SST;

            float mx = -1e30f;
            for (int k = lane; k < 2048; k += 32) {
                float s = srow[k];
                s = mrow[k] ? -1e9f : s * 0.125f;   // 1/sqrt(64)
                srow[k] = s;
                mx = fmaxf(mx, s);
            }
#pragma unroll
            for (int o = 16; o; o >>= 1) mx = fmaxf(mx, __shfl_xor_sync(0xffffffffu, mx, o));

            float sum = 0.f;
            for (int k = lane; k < 2048; k += 32) {
                float p = __expf(srow[k] - mx);
                srow[k] = p;
                sum += p;
            }
#pragma unroll
            for (int o = 16; o; o >>= 1) sum += __shfl_xor_sync(0xffffffffu, sum, o);
            float inv = 1.0f / sum;

            if (attn_out) {
                float* arow = attn_out + ((size_t)bh * Sq + qg) * Sq;
                for (int k = lane; k < 2048; k += 32) {
                    float p = srow[k] * inv;
                    arow[k] = p;                                  // exact fp32
                    srow[k] = __uint_as_float(f2tf(p));           // tf32 for phase 5
                }
            } else {
                for (int k = lane; k < 2048; k += 32) {
                    float p = srow[k] * inv;
                    srow[k] = __uint_as_float(f2tf(p));
                }
            }
        }
    }

    // ---- phase 5: ctx = P @ V (single tf32) ----
    float cacc[2][4] = {{0.f,0.f,0.f,0.f},{0.f,0.f,0.f,0.f}};
    const int d0w = warp * 8;                    // this warp's output d-slice
    for (int kt = 0; kt < 32; kt++) {
        const int kb = kt * 64;
        const float* Vb = Vm + ((size_t)bh * Sq + kb) * 64;
        __syncthreads();                          // ks consumed by previous iter / softmax done
        for (int i = tid * 4; i < 64 * 64; i += 1024) {
            float4 v = *(const float4*)(Vb + i);
            *(float4*)&ks[(i >> 6) * KSP + (i & 63)] = v;
        }
        __syncthreads();

#pragma unroll
        for (int sub = 0; sub < 8; sub++) {
            int k0 = kb + sub * 8;                // global score col base
            uint32_t a[4];
            a[0] = __float_as_uint(scores[g * SST + k0 + t]);
            a[1] = __float_as_uint(scores[(g + 8) * SST + k0 + t]);
            a[2] = __float_as_uint(scores[g * SST + k0 + t + 4]);
            a[3] = __float_as_uint(scores[(g + 8) * SST + k0 + t + 4]);
            uint32_t b0 = f2tf(ks[(sub * 8 + t) * KSP + d0w + g]);
            uint32_t b1 = f2tf(ks[(sub * 8 + t + 4) * KSP + d0w + g]);
            mma8(cacc[sub & 1], a, b0, b1);
        }
    }
    {
        int qg   = qt * 16;
        int dcol = h * 64 + d0w + 2 * t;
        float2 r0 = make_float2(cacc[0][0] + cacc[1][0], cacc[0][1] + cacc[1][1]);
        float2 r1 = make_float2(cacc[0][2] + cacc[1][2], cacc[0][3] + cacc[1][3]);
        *(float2*)&ctx[((size_t)b * Sq + qg + g) * Dq + dcol]     = r0;
        *(float2*)&ctx[((size_t)b * Sq + qg + g + 8) * Dq + dcol] = r1;
    }
}

// ---------------------------------------------------------------------------
// LayerNorm over last dim (512). One 128-thread block per row.
// ---------------------------------------------------------------------------
__global__ __launch_bounds__(128)
void ln_kernel(const float* __restrict__ x, const float* __restrict__ gamma,
               const float* __restrict__ beta, float* __restrict__ out)
{
    const int row = blockIdx.x;
    const int tid = threadIdx.x;
    const float* xr = x + (size_t)row * 512;

    float4 v = *(const float4*)(xr + tid * 4);
    float s  = v.x + v.y + v.z + v.w;
    float ss = v.x * v.x + v.y * v.y + v.z * v.z + v.w * v.w;

    const int lane = tid & 31, warp = tid >> 5;
#pragma unroll
    for (int o = 16; o; o >>= 1) {
        s  += __shfl_xor_sync(0xffffffffu, s, o);
        ss += __shfl_xor_sync(0xffffffffu, ss, o);
    }
    __shared__ float sh_s[4], sh_ss[4];
    if (lane == 0) { sh_s[warp] = s; sh_ss[warp] = ss; }
    __syncthreads();
    float tot  = sh_s[0] + sh_s[1] + sh_s[2] + sh_s[3];
    float tots = sh_ss[0] + sh_ss[1] + sh_ss[2] + sh_ss[3];

    float mu   = tot * (1.0f / 512.0f);
    float var  = tots * (1.0f / 512.0f) - mu * mu;
    float rstd = rsqrtf(var + LN_EPS);

    float4 g  = *(const float4*)(gamma + tid * 4);
    float4 be = *(const float4*)(beta + tid * 4);
    float4 r;
    r.x = (v.x - mu) * rstd * g.x + be.x;
    r.y = (v.y - mu) * rstd * g.y + be.y;
    r.z = (v.z - mu) * rstd * g.z + be.z;
    r.w = (v.w - mu) * rstd * g.w + be.w;
    *(float4*)&out[(size_t)row * 512 + tid * 4] = r;
}

// ---------------------------------------------------------------------------
extern "C" void kernel_launch(void* const* d_in, const int* in_sizes, int n_in,
                              void* d_out, int out_size)
{
    const float*    inQ   = (const float*)d_in[0];
    const float*    inK   = (const float*)d_in[1];
    const float*    inV   = (const float*)d_in[2];
    const unsigned* mask  = (const unsigned*)d_in[3];
    const float*    WQ    = (const float*)d_in[4];
    const float*    WK    = (const float*)d_in[5];
    const float*    WV    = (const float*)d_in[6];
    const float*    Wfc   = (const float*)d_in[7];
    const float*    gamma = (const float*)d_in[8];
    const float*    beta  = (const float*)d_in[9];
    float* out = (float*)d_out;

    float *gQ, *gK, *gV, *gctx, *gpre;
    cudaGetSymbolAddress((void**)&gQ,   g_Q);
    cudaGetSymbolAddress((void**)&gK,   g_K);
    cudaGetSymbolAddress((void**)&gV,   g_V);
    cudaGetSymbolAddress((void**)&gctx, g_ctx);
    cudaGetSymbolAddress((void**)&gpre, g_pre);

    dim3 ggrid(8, 128), gblk(256);
    gemm64<0><<<ggrid, gblk>>>(inQ, WQ, gQ, nullptr);
    gemm64<0><<<ggrid, gblk>>>(inK, WK, gK, nullptr);
    gemm64<0><<<ggrid, gblk>>>(inV, WV, gV, nullptr);

    const size_t BSD  = (size_t)Bq * Sq * Dq;
    const size_t BHSS = (size_t)Bq * Hq * Sq * Sq;
    float* attn_ptr = ((size_t)out_size >= BSD + BHSS) ? (out + BSD) : nullptr;

    size_t smem = (size_t)(16 * SST + 64 * KSP + 16 * KSP) * sizeof(float);  // 153,344 B
    cudaFuncSetAttribute(attn_kernel, cudaFuncAttributeMaxDynamicSharedMemorySize, (int)smem);
    attn_kernel<<<dim3(32, 128), 256, smem>>>(gQ, gK, gV, mask, attn_ptr, gctx);

    gemm64<1><<<ggrid, gblk>>>(gctx, Wfc, gpre, inQ);
    ln_kernel<<<Bq * Sq, 128>>>(gpre, gamma, beta, out);
}

// round 3
// speedup vs baseline: 2.0625x; 1.6582x over previous
#include <cuda_runtime.h>
#include <cuda_bf16.h>
#include <cstdint>

// Problem constants
#define Bq   4
#define Sq   2048
#define Dq   512
#define Hq   8
#define DKq  64
#define DVq  64
#define LN_EPS 1e-5f

// attn smem layout constants
#define SST  2056   // scores row stride (floats)
#define KSP  68     // K/V tile row stride (floats)
#define TILE (64 * KSP)
#define NBUF 4

// Scratch (device globals: allocation-free rule)
__device__ float g_Q[(size_t)Bq*Hq*Sq*DKq];     // [B,H,S,64]
__device__ float g_K[(size_t)Bq*Hq*Sq*DKq];
__device__ float g_V[(size_t)Bq*Hq*Sq*DVq];
__device__ float g_ctx[(size_t)Bq*Sq*Dq];       // [B,S,512]
__device__ float g_pre[(size_t)Bq*Sq*Dq];       // fc out + residual

// ---------------------------------------------------------------------------
__device__ __forceinline__ uint32_t f2tf(float x) {
    uint32_t r;
    asm("cvt.rna.tf32.f32 %0, %1;" : "=r"(r) : "f"(x));
    return r;
}

__device__ __forceinline__ void mma8(float* c, const uint32_t* a, uint32_t b0, uint32_t b1) {
    asm volatile(
        "mma.sync.aligned.m16n8k8.row.col.f32.tf32.tf32.f32 "
        "{%0,%1,%2,%3}, {%4,%5,%6,%7}, {%8,%9}, {%0,%1,%2,%3};"
        : "+f"(c[0]), "+f"(c[1]), "+f"(c[2]), "+f"(c[3])
        : "r"(a[0]), "r"(a[1]), "r"(a[2]), "r"(a[3]), "r"(b0), "r"(b1));
}

__device__ __forceinline__ void cp16(float* dst, const float* src) {
    uint32_t d = (uint32_t)__cvta_generic_to_shared(dst);
    asm volatile("cp.async.cg.shared.global [%0], [%1], 16;" :: "r"(d), "l"(src));
}
__device__ __forceinline__ void cp_commit() { asm volatile("cp.async.commit_group;"); }
template<int N> __device__ __forceinline__ void cp_wait() {
    asm volatile("cp.async.wait_group %0;" :: "n"(N));
}

// ---------------------------------------------------------------------------
// Tiled fp32 GEMM: C[M=8192, N=512] = A[M,512] @ W[512,512]
// MODE 0: out permuted to [B,H,S,64]; MODE 1: fc + residual
// ---------------------------------------------------------------------------
template <int MODE>
__global__ __launch_bounds__(256)
void gemm64(const float* __restrict__ A, const float* __restrict__ W,
            float* __restrict__ out, const float* __restrict__ resid)
{
    __shared__ float As[32 * 68];
    __shared__ float Bs[32 * 68];

    const int tid = threadIdx.x;
    const int tx  = tid & 15;
    const int ty  = tid >> 4;
    const int n0  = blockIdx.x * 64;
    const int m0b = blockIdx.y * 64;

    float acc[4][4];
#pragma unroll
    for (int i = 0; i < 4; i++)
#pragma unroll
        for (int j = 0; j < 4; j++) acc[i][j] = 0.f;

    for (int k0 = 0; k0 < 512; k0 += 32) {
#pragma unroll
        for (int l = tid; l < 512; l += 256) {
            int m_l = l >> 3;
            int kq  = (l & 7) * 4;
            float4 v = *(const float4*)(A + (size_t)(m0b + m_l) * 512 + k0 + kq);
            As[(kq + 0) * 68 + m_l] = v.x;
            As[(kq + 1) * 68 + m_l] = v.y;
            As[(kq + 2) * 68 + m_l] = v.z;
            As[(kq + 3) * 68 + m_l] = v.w;
        }
#pragma unroll
        for (int l = tid; l < 512; l += 256) {
            int k_l = l >> 4;
            int nq  = (l & 15) * 4;
            float4 v = *(const float4*)(W + (size_t)(k0 + k_l) * 512 + n0 + nq);
            *(float4*)&Bs[k_l * 68 + nq] = v;
        }
        __syncthreads();

#pragma unroll
        for (int k = 0; k < 32; k++) {
            float4 a = *(float4*)&As[k * 68 + ty * 4];
            float4 b = *(float4*)&Bs[k * 68 + tx * 4];
            acc[0][0] += a.x * b.x; acc[0][1] += a.x * b.y; acc[0][2] += a.x * b.z; acc[0][3] += a.x * b.w;
            acc[1][0] += a.y * b.x; acc[1][1] += a.y * b.y; acc[1][2] += a.y * b.z; acc[1][3] += a.y * b.w;
            acc[2][0] += a.z * b.x; acc[2][1] += a.z * b.y; acc[2][2] += a.z * b.z; acc[2][3] += a.z * b.w;
            acc[3][0] += a.w * b.x; acc[3][1] += a.w * b.y; acc[3][2] += a.w * b.z; acc[3][3] += a.w * b.w;
        }
        __syncthreads();
    }

    if (MODE == 0) {
        const int h  = blockIdx.x;
        const int e0 = tx * 4;
#pragma unroll
        for (int i = 0; i < 4; i++) {
            int m = m0b + ty * 4 + i;
            int b = m >> 11;
            int s = m & 2047;
            float4 r = make_float4(acc[i][0], acc[i][1], acc[i][2], acc[i][3]);
            *(float4*)&out[(((size_t)b * Hq + h) * Sq + s) * 64 + e0] = r;
        }
    } else {
#pragma unroll
        for (int i = 0; i < 4; i++) {
            int m = m0b + ty * 4 + i;
            float4 rv = *(const float4*)&resid[(size_t)m * 512 + n0 + tx * 4];
            float4 r = make_float4(acc[i][0] + rv.x, acc[i][1] + rv.y,
                                   acc[i][2] + rv.z, acc[i][3] + rv.w);
            *(float4*)&out[(size_t)m * 512 + n0 + tx * 4] = r;
        }
    }
}

// ---------------------------------------------------------------------------
// Fused attention with mma.sync tf32 + 4-stage cp.async pipeline.
// One CTA per (b*H+h, q-tile of 16). 256 threads = 8 warps.
// smem: scores[16][SST] + 4 kv tile bufs [64][KSP] + q stage [16][KSP]
// ---------------------------------------------------------------------------
__global__ __launch_bounds__(256, 1)
void attn_kernel(const float* __restrict__ Qm, const float* __restrict__ Km,
                 const float* __restrict__ Vm, const unsigned* __restrict__ mask,
                 float* __restrict__ attn_out, float* __restrict__ ctx)
{
    extern __shared__ float sm[];
    float* scores = sm;                          // 16*SST
    float* kv     = sm + 16 * SST;               // NBUF * TILE
    float* qs     = kv + NBUF * TILE;            // 16*KSP

    const int bh  = blockIdx.x;                  // 0..31
    const int qt  = blockIdx.y;                  // 0..127
    const int b   = bh >> 3;
    const int h   = bh & 7;
    const int tid = threadIdx.x;
    const int warp = tid >> 5;
    const int lane = tid & 31;
    const int g = lane >> 2;
    const int t = lane & 3;
    const int n0 = warp * 8;

    const float* Kbh = Km + (size_t)bh * Sq * 64;
    const float* Vbh = Vm + (size_t)bh * Sq * 64;

    // per-thread staging offsets (4 x cp16 per tile)
    const int sr0 = (tid * 4) >> 6;              // row of first chunk
    const int sc0 = (tid * 4) & 63;              // col of first chunk

    // issue K tiles 0..2
#pragma unroll
    for (int p = 0; p < 3; p++) {
        const float* src = Kbh + p * 64 * 64;
        float* dst = kv + p * TILE;
#pragma unroll
        for (int j = 0; j < 4; j++) {
            int i = tid * 4 + j * 1024;
            cp16(&dst[(i >> 6) * KSP + (i & 63)], src + i);
        }
        cp_commit();
    }

    // ---- stage Q tile [16,64] (plain loads, overlapped with K cp.async) ----
    const float* Qbase = Qm + ((size_t)bh * Sq + qt * 16) * 64;
    for (int i = tid; i < 16 * 64; i += 256) {
        qs[(i >> 6) * KSP + (i & 63)] = Qbase[i];
    }
    __syncthreads();

    // ---- Q fragments (hi/lo tf32 split), pre-scaled by 1/8 (exact) ----
    uint32_t qhi[8][4], qlo[8][4];
#pragma unroll
    for (int sub = 0; sub < 8; sub++) {
        int d0 = sub * 8;
        float f0 = qs[g * KSP + d0 + t]       * 0.125f;
        float f1 = qs[(g + 8) * KSP + d0 + t] * 0.125f;
        float f2 = qs[g * KSP + d0 + t + 4]       * 0.125f;
        float f3 = qs[(g + 8) * KSP + d0 + t + 4] * 0.125f;
        qhi[sub][0] = f2tf(f0); qlo[sub][0] = f2tf(f0 - __uint_as_float(qhi[sub][0]));
        qhi[sub][1] = f2tf(f1); qlo[sub][1] = f2tf(f1 - __uint_as_float(qhi[sub][1]));
        qhi[sub][2] = f2tf(f2); qlo[sub][2] = f2tf(f2 - __uint_as_float(qhi[sub][2]));
        qhi[sub][3] = f2tf(f3); qlo[sub][3] = f2tf(f3 - __uint_as_float(qhi[sub][3]));
    }

    // ---- phase 2: scores = Q @ K^T (3xTF32), pipelined ----
#pragma unroll 1
    for (int kt = 0; kt < 32; kt++) {
        cp_wait<2>();
        __syncthreads();
        // stage tile kt+3 into buf (kt+3)%4 (freed by compute(kt-1), guaranteed by bar above)
        if (kt + 3 < 32) {
            const float* src = Kbh + (kt + 3) * 64 * 64;
            float* dst = kv + ((kt + 3) & 3) * TILE;
#pragma unroll
            for (int j = 0; j < 4; j++) {
                int i = tid * 4 + j * 1024;
                cp16(&dst[(i >> 6) * KSP + (i & 63)], src + i);
            }
        }
        cp_commit();   // empty group when no stage -> uniform wait<2>

        const float* ksb = kv + (kt & 3) * TILE;
        float acc[2][4] = {{0.f,0.f,0.f,0.f},{0.f,0.f,0.f,0.f}};
#pragma unroll
        for (int sub = 0; sub < 8; sub++) {
            int d0 = sub * 8;
            float bf0 = ksb[(n0 + g) * KSP + d0 + t];
            float bf1 = ksb[(n0 + g) * KSP + d0 + t + 4];
            uint32_t bH0 = f2tf(bf0), bH1 = f2tf(bf1);
            uint32_t bL0 = f2tf(bf0 - __uint_as_float(bH0));
            uint32_t bL1 = f2tf(bf1 - __uint_as_float(bH1));
            mma8(acc[sub & 1], qhi[sub], bH0, bH1);
            mma8(acc[sub & 1], qlo[sub], bH0, bH1);
            mma8(acc[sub & 1], qhi[sub], bL0, bL1);
        }
        int col = kt * 64 + n0 + 2 * t;
        *(float2*)&scores[g * SST + col]       = make_float2(acc[0][0] + acc[1][0], acc[0][1] + acc[1][1]);
        *(float2*)&scores[(g + 8) * SST + col] = make_float2(acc[0][2] + acc[1][2], acc[0][3] + acc[1][3]);
    }

    // prefetch V tiles 0..2 (bufs 0..2 are free: K28..K30 finished)
#pragma unroll
    for (int p = 0; p < 3; p++) {
        const float* src = Vbh + p * 64 * 64;
        float* dst = kv + p * TILE;
#pragma unroll
        for (int j = 0; j < 4; j++) {
            int i = tid * 4 + j * 1024;
            cp16(&dst[(i >> 6) * KSP + (i & 63)], src + i);
        }
        cp_commit();
    }
    __syncthreads();   // scores visible to all warps

    // ---- phase 3/4: mask + softmax (float2 passes) ----
    {
#pragma unroll
        for (int rr = 0; rr < 2; rr++) {
            int row = warp * 2 + rr;
            int qg  = qt * 16 + row;
            const uint2* mrow2 = (const uint2*)(mask + ((size_t)b * Sq + qg) * Sq);
            float2* srow2 = (float2*)(scores + row * SST);

            float mx = -1e30f;
#pragma unroll 4
            for (int i = lane; i < 1024; i += 32) {
                float2 s = srow2[i];
                uint2  m = mrow2[i];
                s.x = m.x ? -1e9f : s.x;
                s.y = m.y ? -1e9f : s.y;
                srow2[i] = s;
                mx = fmaxf(mx, fmaxf(s.x, s.y));
            }
#pragma unroll
            for (int o = 16; o; o >>= 1) mx = fmaxf(mx, __shfl_xor_sync(0xffffffffu, mx, o));

            float sum = 0.f;
#pragma unroll 4
            for (int i = lane; i < 1024; i += 32) {
                float2 s = srow2[i];
                s.x = __expf(s.x - mx);
                s.y = __expf(s.y - mx);
                srow2[i] = s;
                sum += s.x + s.y;
            }
#pragma unroll
            for (int o = 16; o; o >>= 1) sum += __shfl_xor_sync(0xffffffffu, sum, o);
            float inv = 1.0f / sum;

            if (attn_out) {
                float2* arow2 = (float2*)(attn_out + ((size_t)bh * Sq + qg) * Sq);
#pragma unroll 4
                for (int i = lane; i < 1024; i += 32) {
                    float2 p = srow2[i];
                    float2 pn = make_float2(p.x * inv, p.y * inv);
                    arow2[i] = pn;
                    srow2[i] = make_float2(__uint_as_float(f2tf(pn.x)),
                                           __uint_as_float(f2tf(pn.y)));
                }
            } else {
#pragma unroll 4
                for (int i = lane; i < 1024; i += 32) {
                    float2 p = srow2[i];
                    srow2[i] = make_float2(__uint_as_float(f2tf(p.x * inv)),
                                           __uint_as_float(f2tf(p.y * inv)));
                }
            }
        }
    }

    // ---- phase 5: ctx = P @ V (single tf32), pipelined ----
    float cacc[2][4] = {{0.f,0.f,0.f,0.f},{0.f,0.f,0.f,0.f}};
    const int d0w = warp * 8;
#pragma unroll 1
    for (int kt = 0; kt < 32; kt++) {
        cp_wait<2>();
        __syncthreads();
        if (kt + 3 < 32) {
            const float* src = Vbh + (kt + 3) * 64 * 64;
            float* dst = kv + ((kt + 3) & 3) * TILE;
#pragma unroll
            for (int j = 0; j < 4; j++) {
                int i = tid * 4 + j * 1024;
                cp16(&dst[(i >> 6) * KSP + (i & 63)], src + i);
            }
        }
        cp_commit();

        const float* vsb = kv + (kt & 3) * TILE;
        const int kb = kt * 64;
#pragma unroll
        for (int sub = 0; sub < 8; sub++) {
            int k0 = kb + sub * 8;
            uint32_t a[4];
            a[0] = __float_as_uint(scores[g * SST + k0 + t]);
            a[1] = __float_as_uint(scores[(g + 8) * SST + k0 + t]);
            a[2] = __float_as_uint(scores[g * SST + k0 + t + 4]);
            a[3] = __float_as_uint(scores[(g + 8) * SST + k0 + t + 4]);
            uint32_t b0 = f2tf(vsb[(sub * 8 + t) * KSP + d0w + g]);
            uint32_t b1 = f2tf(vsb[(sub * 8 + t + 4) * KSP + d0w + g]);
            mma8(cacc[sub & 1], a, b0, b1);
        }
    }
    {
        int qg   = qt * 16;
        int dcol = h * 64 + d0w + 2 * t;
        *(float2*)&ctx[((size_t)b * Sq + qg + g) * Dq + dcol] =
            make_float2(cacc[0][0] + cacc[1][0], cacc[0][1] + cacc[1][1]);
        *(float2*)&ctx[((size_t)b * Sq + qg + g + 8) * Dq + dcol] =
            make_float2(cacc[0][2] + cacc[1][2], cacc[0][3] + cacc[1][3]);
    }
}

// ---------------------------------------------------------------------------
__global__ __launch_bounds__(128)
void ln_kernel(const float* __restrict__ x, const float* __restrict__ gamma,
               const float* __restrict__ beta, float* __restrict__ out)
{
    const int row = blockIdx.x;
    const int tid = threadIdx.x;
    const float* xr = x + (size_t)row * 512;

    float4 v = *(const float4*)(xr + tid * 4);
    float s  = v.x + v.y + v.z + v.w;
    float ss = v.x * v.x + v.y * v.y + v.z * v.z + v.w * v.w;

    const int lane = tid & 31, warp = tid >> 5;
#pragma unroll
    for (int o = 16; o; o >>= 1) {
        s  += __shfl_xor_sync(0xffffffffu, s, o);
        ss += __shfl_xor_sync(0xffffffffu, ss, o);
    }
    __shared__ float sh_s[4], sh_ss[4];
    if (lane == 0) { sh_s[warp] = s; sh_ss[warp] = ss; }
    __syncthreads();
    float tot  = sh_s[0] + sh_s[1] + sh_s[2] + sh_s[3];
    float tots = sh_ss[0] + sh_ss[1] + sh_ss[2] + sh_ss[3];

    float mu   = tot * (1.0f / 512.0f);
    float var  = tots * (1.0f / 512.0f) - mu * mu;
    float rstd = rsqrtf(var + LN_EPS);

    float4 g  = *(const float4*)(gamma + tid * 4);
    float4 be = *(const float4*)(beta + tid * 4);
    float4 r;
    r.x = (v.x - mu) * rstd * g.x + be.x;
    r.y = (v.y - mu) * rstd * g.y + be.y;
    r.z = (v.z - mu) * rstd * g.z + be.z;
    r.w = (v.w - mu) * rstd * g.w + be.w;
    *(float4*)&out[(size_t)row * 512 + tid * 4] = r;
}

// ---------------------------------------------------------------------------
extern "C" void kernel_launch(void* const* d_in, const int* in_sizes, int n_in,
                              void* d_out, int out_size)
{
    const float*    inQ   = (const float*)d_in[0];
    const float*    inK   = (const float*)d_in[1];
    const float*    inV   = (const float*)d_in[2];
    const unsigned* mask  = (const unsigned*)d_in[3];
    const float*    WQ    = (const float*)d_in[4];
    const float*    WK    = (const float*)d_in[5];
    const float*    WV    = (const float*)d_in[6];
    const float*    Wfc   = (const float*)d_in[7];
    const float*    gamma = (const float*)d_in[8];
    const float*    beta  = (const float*)d_in[9];
    float* out = (float*)d_out;

    float *gQ, *gK, *gV, *gctx, *gpre;
    cudaGetSymbolAddress((void**)&gQ,   g_Q);
    cudaGetSymbolAddress((void**)&gK,   g_K);
    cudaGetSymbolAddress((void**)&gV,   g_V);
    cudaGetSymbolAddress((void**)&gctx, g_ctx);
    cudaGetSymbolAddress((void**)&gpre, g_pre);

    dim3 ggrid(8, 128), gblk(256);
    gemm64<0><<<ggrid, gblk>>>(inQ, WQ, gQ, nullptr);
    gemm64<0><<<ggrid, gblk>>>(inK, WK, gK, nullptr);
    gemm64<0><<<ggrid, gblk>>>(inV, WV, gV, nullptr);

    const size_t BSD  = (size_t)Bq * Sq * Dq;
    const size_t BHSS = (size_t)Bq * Hq * Sq * Sq;
    float* attn_ptr = ((size_t)out_size >= BSD + BHSS) ? (out + BSD) : nullptr;

    size_t smem = (size_t)(16 * SST + NBUF * TILE + 16 * KSP) * sizeof(float); // 205,568 B
    cudaFuncSetAttribute(attn_kernel, cudaFuncAttributeMaxDynamicSharedMemorySize, (int)smem);
    attn_kernel<<<dim3(32, 128), 256, smem>>>(gQ, gK, gV, mask, attn_ptr, gctx);

    gemm64<1><<<ggrid, gblk>>>(gctx, Wfc, gpre, inQ);
    ln_kernel<<<Bq * Sq, 128>>>(gpre, gamma, beta, out);
}

// round 4
// speedup vs baseline: 2.3027x; 1.1164x over previous
#include <cuda_runtime.h>
#include <cuda_bf16.h>
#include <cstdint>

// Problem constants
#define Bq   4
#define Sq   2048
#define Dq   512
#define Hq   8
#define DKq  64
#define DVq  64
#define LN_EPS 1e-5f

// attn smem layout constants
#define SST  2056            // scores row stride (floats)
#define KSP  68              // K/V tile row stride (floats)
#define TKEYS 128            // keys per tile
#define TILE (TKEYS * KSP)   // floats per tile buffer
#define NT   (Sq / TKEYS)    // 16 tiles

// Scratch (device globals: allocation-free rule)
__device__ float g_Q[(size_t)Bq*Hq*Sq*DKq];     // [B,H,S,64]
__device__ float g_K[(size_t)Bq*Hq*Sq*DKq];
__device__ float g_V[(size_t)Bq*Hq*Sq*DVq];
__device__ float g_ctx[(size_t)Bq*Sq*Dq];       // [B,S,512]
__device__ float g_pre[(size_t)Bq*Sq*Dq];       // fc out + residual

// ---------------------------------------------------------------------------
__device__ __forceinline__ uint32_t f2tf(float x) {
    uint32_t r;
    asm("cvt.rna.tf32.f32 %0, %1;" : "=r"(r) : "f"(x));
    return r;
}

__device__ __forceinline__ void mma8(float* c, const uint32_t* a, uint32_t b0, uint32_t b1) {
    asm volatile(
        "mma.sync.aligned.m16n8k8.row.col.f32.tf32.tf32.f32 "
        "{%0,%1,%2,%3}, {%4,%5,%6,%7}, {%8,%9}, {%0,%1,%2,%3};"
        : "+f"(c[0]), "+f"(c[1]), "+f"(c[2]), "+f"(c[3])
        : "r"(a[0]), "r"(a[1]), "r"(a[2]), "r"(a[3]), "r"(b0), "r"(b1));
}

__device__ __forceinline__ void cp16(float* dst, const float* src) {
    uint32_t d = (uint32_t)__cvta_generic_to_shared(dst);
    asm volatile("cp.async.cg.shared.global [%0], [%1], 16;" :: "r"(d), "l"(src));
}
__device__ __forceinline__ void cp_commit() { asm volatile("cp.async.commit_group;"); }
template<int N> __device__ __forceinline__ void cp_wait() {
    asm volatile("cp.async.wait_group %0;" :: "n"(N));
}

// ---------------------------------------------------------------------------
// Tiled fp32 GEMM: C[M=8192, N=512] = A[M,512] @ W[512,512]
// MODE 0: out permuted to [B,H,S,64]; MODE 1: fc + residual
// ---------------------------------------------------------------------------
template <int MODE>
__global__ __launch_bounds__(256)
void gemm64(const float* __restrict__ A, const float* __restrict__ W,
            float* __restrict__ out, const float* __restrict__ resid)
{
    __shared__ float As[32 * 68];
    __shared__ float Bs[32 * 68];

    const int tid = threadIdx.x;
    const int tx  = tid & 15;
    const int ty  = tid >> 4;
    const int n0  = blockIdx.x * 64;
    const int m0b = blockIdx.y * 64;

    float acc[4][4];
#pragma unroll
    for (int i = 0; i < 4; i++)
#pragma unroll
        for (int j = 0; j < 4; j++) acc[i][j] = 0.f;

    for (int k0 = 0; k0 < 512; k0 += 32) {
#pragma unroll
        for (int l = tid; l < 512; l += 256) {
            int m_l = l >> 3;
            int kq  = (l & 7) * 4;
            float4 v = *(const float4*)(A + (size_t)(m0b + m_l) * 512 + k0 + kq);
            As[(kq + 0) * 68 + m_l] = v.x;
            As[(kq + 1) * 68 + m_l] = v.y;
            As[(kq + 2) * 68 + m_l] = v.z;
            As[(kq + 3) * 68 + m_l] = v.w;
        }
#pragma unroll
        for (int l = tid; l < 512; l += 256) {
            int k_l = l >> 4;
            int nq  = (l & 15) * 4;
            float4 v = *(const float4*)(W + (size_t)(k0 + k_l) * 512 + n0 + nq);
            *(float4*)&Bs[k_l * 68 + nq] = v;
        }
        __syncthreads();

#pragma unroll
        for (int k = 0; k < 32; k++) {
            float4 a = *(float4*)&As[k * 68 + ty * 4];
            float4 b = *(float4*)&Bs[k * 68 + tx * 4];
            acc[0][0] += a.x * b.x; acc[0][1] += a.x * b.y; acc[0][2] += a.x * b.z; acc[0][3] += a.x * b.w;
            acc[1][0] += a.y * b.x; acc[1][1] += a.y * b.y; acc[1][2] += a.y * b.z; acc[1][3] += a.y * b.w;
            acc[2][0] += a.z * b.x; acc[2][1] += a.z * b.y; acc[2][2] += a.z * b.z; acc[2][3] += a.z * b.w;
            acc[3][0] += a.w * b.x; acc[3][1] += a.w * b.y; acc[3][2] += a.w * b.z; acc[3][3] += a.w * b.w;
        }
        __syncthreads();
    }

    if (MODE == 0) {
        const int h  = blockIdx.x;
        const int e0 = tx * 4;
#pragma unroll
        for (int i = 0; i < 4; i++) {
            int m = m0b + ty * 4 + i;
            int b = m >> 11;
            int s = m & 2047;
            float4 r = make_float4(acc[i][0], acc[i][1], acc[i][2], acc[i][3]);
            *(float4*)&out[(((size_t)b * Hq + h) * Sq + s) * 64 + e0] = r;
        }
    } else {
#pragma unroll
        for (int i = 0; i < 4; i++) {
            int m = m0b + ty * 4 + i;
            float4 rv = *(const float4*)&resid[(size_t)m * 512 + n0 + tx * 4];
            float4 r = make_float4(acc[i][0] + rv.x, acc[i][1] + rv.y,
                                   acc[i][2] + rv.z, acc[i][3] + rv.w);
            *(float4*)&out[(size_t)m * 512 + n0 + tx * 4] = r;
        }
    }
}

// ---------------------------------------------------------------------------
// Fused attention, 512 threads = 16 warps, 128-key tiles, 2-stage cp.async.
// phase 2: warp w owns score cols [w*8, w*8+8) of each 128-key tile (3xTF32)
// phase 3: 1 softmax row per warp
// phase 5: warp-group (w>>3) owns key half of tile, (w&7) owns d-slice;
//          cross-group partial reduction through smem (exact fp32 add)
// smem: scores[16][SST] + 2 tile bufs [128][KSP] + q/partial [16][KSP]
// ---------------------------------------------------------------------------
__global__ __launch_bounds__(512, 1)
void attn_kernel(const float* __restrict__ Qm, const float* __restrict__ Km,
                 const float* __restrict__ Vm, const unsigned* __restrict__ mask,
                 float* __restrict__ attn_out, float* __restrict__ ctx)
{
    extern __shared__ float sm[];
    float* scores = sm;                          // 16*SST
    float* kv     = sm + 16 * SST;               // 2 * TILE
    float* qs     = kv + 2 * TILE;               // 16*KSP (Q stage, later P@V partials)

    const int bh  = blockIdx.x;                  // 0..31
    const int qt  = blockIdx.y;                  // 0..127
    const int b   = bh >> 3;
    const int h   = bh & 7;
    const int tid = threadIdx.x;
    const int warp = tid >> 5;                   // 0..15
    const int lane = tid & 31;
    const int g = lane >> 2;                     // 0..7
    const int t = lane & 3;                      // 0..3
    const int wg = warp >> 3;                    // warp group 0/1
    const int wi = warp & 7;                     // warp-in-group

    const float* Kbh = Km + (size_t)bh * Sq * 64;
    const float* Vbh = Vm + (size_t)bh * Sq * 64;

    // tile staging: 128 rows x 64 cols = 8192 floats = 2048 float4; 4 per thread
#define STAGE(dstbuf, srcptr)                                            \
    {                                                                    \
        float* _d = (dstbuf);                                            \
        const float* _s = (srcptr);                                      \
        _Pragma("unroll")                                                \
        for (int _j = 0; _j < 4; _j++) {                                 \
            int _i = tid * 4 + _j * 2048;                                \
            cp16(&_d[(_i >> 6) * KSP + (_i & 63)], _s + _i);             \
        }                                                                \
    }

    // prologue: stage K tile 0
    STAGE(kv, Kbh);
    cp_commit();

    // stage Q tile [16,64] (plain loads, overlap with cp.async)
    const float* Qbase = Qm + ((size_t)bh * Sq + qt * 16) * 64;
    for (int i = tid; i < 16 * 64; i += 512) {
        qs[(i >> 6) * KSP + (i & 63)] = Qbase[i];
    }
    __syncthreads();

    // Q fragments (hi/lo tf32 split), pre-scaled by 1/8 (exact)
    uint32_t qhi[8][4], qlo[8][4];
#pragma unroll
    for (int sub = 0; sub < 8; sub++) {
        int d0 = sub * 8;
        float f0 = qs[g * KSP + d0 + t]           * 0.125f;
        float f1 = qs[(g + 8) * KSP + d0 + t]     * 0.125f;
        float f2 = qs[g * KSP + d0 + t + 4]       * 0.125f;
        float f3 = qs[(g + 8) * KSP + d0 + t + 4] * 0.125f;
        qhi[sub][0] = f2tf(f0); qlo[sub][0] = f2tf(f0 - __uint_as_float(qhi[sub][0]));
        qhi[sub][1] = f2tf(f1); qlo[sub][1] = f2tf(f1 - __uint_as_float(qhi[sub][1]));
        qhi[sub][2] = f2tf(f2); qlo[sub][2] = f2tf(f2 - __uint_as_float(qhi[sub][2]));
        qhi[sub][3] = f2tf(f3); qlo[sub][3] = f2tf(f3 - __uint_as_float(qhi[sub][3]));
    }

    // ---- phase 2: scores = Q @ K^T (3xTF32) ----
    const int n0 = warp * 8;                     // score col slice within 128-key tile
#pragma unroll 1
    for (int kt = 0; kt < NT; kt++) {
        cp_wait<0>();                            // tile kt landed
        __syncthreads();                         // compute(kt-1) done everywhere
        if (kt + 1 < NT) {                       // stage kt+1 into other buffer
            STAGE(kv + ((kt + 1) & 1) * TILE, Kbh + (kt + 1) * TKEYS * 64);
            cp_commit();
        }
        const float* ksb = kv + (kt & 1) * TILE;
        float acc[2][4] = {{0.f,0.f,0.f,0.f},{0.f,0.f,0.f,0.f}};
#pragma unroll
        for (int sub = 0; sub < 8; sub++) {
            int d0 = sub * 8;
            float bf0 = ksb[(n0 + g) * KSP + d0 + t];
            float bf1 = ksb[(n0 + g) * KSP + d0 + t + 4];
            uint32_t bH0 = f2tf(bf0), bH1 = f2tf(bf1);
            uint32_t bL0 = f2tf(bf0 - __uint_as_float(bH0));
            uint32_t bL1 = f2tf(bf1 - __uint_as_float(bH1));
            mma8(acc[sub & 1], qhi[sub], bH0, bH1);
            mma8(acc[sub & 1], qlo[sub], bH0, bH1);
            mma8(acc[sub & 1], qhi[sub], bL0, bL1);
        }
        int col = kt * TKEYS + n0 + 2 * t;
        *(float2*)&scores[g * SST + col]       = make_float2(acc[0][0] + acc[1][0], acc[0][1] + acc[1][1]);
        *(float2*)&scores[(g + 8) * SST + col] = make_float2(acc[0][2] + acc[1][2], acc[0][3] + acc[1][3]);
    }

    // stage V tile 0 into buf 0 (buf0 last used by K tile 14: done by iter-15 barrier)
    STAGE(kv, Vbh);
    cp_commit();
    __syncthreads();   // all scores visible

    // ---- phase 3/4: mask + softmax, one row per warp ----
    {
        const int row = warp;
        const int qg  = qt * 16 + row;
        const uint2* mrow2 = (const uint2*)(mask + ((size_t)b * Sq + qg) * Sq);
        float2* srow2 = (float2*)(scores + row * SST);

        float mx = -1e30f;
#pragma unroll 4
        for (int i = lane; i < 1024; i += 32) {
            float2 s = srow2[i];
            uint2  m = mrow2[i];
            s.x = m.x ? -1e9f : s.x;
            s.y = m.y ? -1e9f : s.y;
            srow2[i] = s;
            mx = fmaxf(mx, fmaxf(s.x, s.y));
        }
#pragma unroll
        for (int o = 16; o; o >>= 1) mx = fmaxf(mx, __shfl_xor_sync(0xffffffffu, mx, o));

        float sum = 0.f;
#pragma unroll 4
        for (int i = lane; i < 1024; i += 32) {
            float2 s = srow2[i];
            s.x = __expf(s.x - mx);
            s.y = __expf(s.y - mx);
            srow2[i] = s;
            sum += s.x + s.y;
        }
#pragma unroll
        for (int o = 16; o; o >>= 1) sum += __shfl_xor_sync(0xffffffffu, sum, o);
        float inv = 1.0f / sum;

        if (attn_out) {
            float2* arow2 = (float2*)(attn_out + ((size_t)bh * Sq + qg) * Sq);
#pragma unroll 4
            for (int i = lane; i < 1024; i += 32) {
                float2 p = srow2[i];
                float2 pn = make_float2(p.x * inv, p.y * inv);
                arow2[i] = pn;                                   // exact fp32
                srow2[i] = make_float2(__uint_as_float(f2tf(pn.x)),
                                       __uint_as_float(f2tf(pn.y)));
            }
        } else {
#pragma unroll 4
            for (int i = lane; i < 1024; i += 32) {
                float2 p = srow2[i];
                srow2[i] = make_float2(__uint_as_float(f2tf(p.x * inv)),
                                       __uint_as_float(f2tf(p.y * inv)));
            }
        }
    }

    // ---- phase 5: ctx = P @ V (single tf32) ----
    float cacc[2][4] = {{0.f,0.f,0.f,0.f},{0.f,0.f,0.f,0.f}};
    const int d0w  = wi * 8;                     // output d-slice
    const int krow = wg * 64;                    // key half within tile
#pragma unroll 1
    for (int kt = 0; kt < NT; kt++) {
        cp_wait<0>();
        __syncthreads();                         // prev compute done; softmax writes visible (kt=0)
        if (kt + 1 < NT) {
            STAGE(kv + ((kt + 1) & 1) * TILE, Vbh + (kt + 1) * TKEYS * 64);
            cp_commit();
        }
        const float* vsb = kv + (kt & 1) * TILE;
        const int kb = kt * TKEYS + krow;
#pragma unroll
        for (int sub = 0; sub < 8; sub++) {
            int k0 = kb + sub * 8;
            uint32_t a[4];
            a[0] = __float_as_uint(scores[g * SST + k0 + t]);
            a[1] = __float_as_uint(scores[(g + 8) * SST + k0 + t]);
            a[2] = __float_as_uint(scores[g * SST + k0 + t + 4]);
            a[3] = __float_as_uint(scores[(g + 8) * SST + k0 + t + 4]);
            uint32_t b0 = f2tf(vsb[(krow + sub * 8 + t) * KSP + d0w + g]);
            uint32_t b1 = f2tf(vsb[(krow + sub * 8 + t + 4) * KSP + d0w + g]);
            mma8(cacc[sub & 1], a, b0, b1);
        }
    }

    // cross-group reduction via qs (16 x KSP floats, exact fp32)
    float2 r0 = make_float2(cacc[0][0] + cacc[1][0], cacc[0][1] + cacc[1][1]);
    float2 r1 = make_float2(cacc[0][2] + cacc[1][2], cacc[0][3] + cacc[1][3]);
    __syncthreads();                             // qs free (Q frags long consumed)
    if (wg == 1) {
        *(float2*)&qs[g * KSP + d0w + 2 * t]       = r0;
        *(float2*)&qs[(g + 8) * KSP + d0w + 2 * t] = r1;
    }
    __syncthreads();
    if (wg == 0) {
        float2 p0 = *(float2*)&qs[g * KSP + d0w + 2 * t];
        float2 p1 = *(float2*)&qs[(g + 8) * KSP + d0w + 2 * t];
        int qg   = qt * 16;
        int dcol = h * 64 + d0w + 2 * t;
        *(float2*)&ctx[((size_t)b * Sq + qg + g) * Dq + dcol] =
            make_float2(r0.x + p0.x, r0.y + p0.y);
        *(float2*)&ctx[((size_t)b * Sq + qg + g + 8) * Dq + dcol] =
            make_float2(r1.x + p1.x, r1.y + p1.y);
    }
#undef STAGE
}

// ---------------------------------------------------------------------------
__global__ __launch_bounds__(128)
void ln_kernel(const float* __restrict__ x, const float* __restrict__ gamma,
               const float* __restrict__ beta, float* __restrict__ out)
{
    const int row = blockIdx.x;
    const int tid = threadIdx.x;
    const float* xr = x + (size_t)row * 512;

    float4 v = *(const float4*)(xr + tid * 4);
    float s  = v.x + v.y + v.z + v.w;
    float ss = v.x * v.x + v.y * v.y + v.z * v.z + v.w * v.w;

    const int lane = tid & 31, warp = tid >> 5;
#pragma unroll
    for (int o = 16; o; o >>= 1) {
        s  += __shfl_xor_sync(0xffffffffu, s, o);
        ss += __shfl_xor_sync(0xffffffffu, ss, o);
    }
    __shared__ float sh_s[4], sh_ss[4];
    if (lane == 0) { sh_s[warp] = s; sh_ss[warp] = ss; }
    __syncthreads();
    float tot  = sh_s[0] + sh_s[1] + sh_s[2] + sh_s[3];
    float tots = sh_ss[0] + sh_ss[1] + sh_ss[2] + sh_ss[3];

    float mu   = tot * (1.0f / 512.0f);
    float var  = tots * (1.0f / 512.0f) - mu * mu;
    float rstd = rsqrtf(var + LN_EPS);

    float4 g  = *(const float4*)(gamma + tid * 4);
    float4 be = *(const float4*)(beta + tid * 4);
    float4 r;
    r.x = (v.x - mu) * rstd * g.x + be.x;
    r.y = (v.y - mu) * rstd * g.y + be.y;
    r.z = (v.z - mu) * rstd * g.z + be.z;
    r.w = (v.w - mu) * rstd * g.w + be.w;
    *(float4*)&out[(size_t)row * 512 + tid * 4] = r;
}

// ---------------------------------------------------------------------------
extern "C" void kernel_launch(void* const* d_in, const int* in_sizes, int n_in,
                              void* d_out, int out_size)
{
    const float*    inQ   = (const float*)d_in[0];
    const float*    inK   = (const float*)d_in[1];
    const float*    inV   = (const float*)d_in[2];
    const unsigned* mask  = (const unsigned*)d_in[3];
    const float*    WQ    = (const float*)d_in[4];
    const float*    WK    = (const float*)d_in[5];
    const float*    WV    = (const float*)d_in[6];
    const float*    Wfc   = (const float*)d_in[7];
    const float*    gamma = (const float*)d_in[8];
    const float*    beta  = (const float*)d_in[9];
    float* out = (float*)d_out;

    float *gQ, *gK, *gV, *gctx, *gpre;
    cudaGetSymbolAddress((void**)&gQ,   g_Q);
    cudaGetSymbolAddress((void**)&gK,   g_K);
    cudaGetSymbolAddress((void**)&gV,   g_V);
    cudaGetSymbolAddress((void**)&gctx, g_ctx);
    cudaGetSymbolAddress((void**)&gpre, g_pre);

    dim3 ggrid(8, 128), gblk(256);
    gemm64<0><<<ggrid, gblk>>>(inQ, WQ, gQ, nullptr);
    gemm64<0><<<ggrid, gblk>>>(inK, WK, gK, nullptr);
    gemm64<0><<<ggrid, gblk>>>(inV, WV, gV, nullptr);

    const size_t BSD  = (size_t)Bq * Sq * Dq;
    const size_t BHSS = (size_t)Bq * Hq * Sq * Sq;
    float* attn_ptr = ((size_t)out_size >= BSD + BHSS) ? (out + BSD) : nullptr;

    size_t smem = (size_t)(16 * SST + 2 * TILE + 16 * KSP) * sizeof(float); // 205,568 B
    cudaFuncSetAttribute(attn_kernel, cudaFuncAttributeMaxDynamicSharedMemorySize, (int)smem);
    attn_kernel<<<dim3(32, 128), 512, smem>>>(gQ, gK, gV, mask, attn_ptr, gctx);

    gemm64<1><<<ggrid, gblk>>>(gctx, Wfc, gpre, inQ);
    ln_kernel<<<Bq * Sq, 128>>>(gpre, gamma, beta, out);
}

// round 5
// speedup vs baseline: 2.6053x; 1.1314x over previous
#include <cuda_runtime.h>
#include <cuda_bf16.h>
#include <cstdint>

// Problem constants
#define Bq   4
#define Sq   2048
#define Dq   512
#define Hq   8
#define LN_EPS 1e-5f

// attn smem layout constants
#define SST   2056           // scores row stride (floats)
#define TKEYS 128            // keys per tile
#define NT    (Sq / TKEYS)   // 16 tiles
#define KHS   72             // bf16 K tile row stride (bf16 units)
#define VSP   68             // fp32 V tile row stride (floats)
#define KVB_BYTES 36864      // per-stage buffer: max(2*128*72*2, 128*68*4)
#define QHS   68             // Q tile row stride (bf16 units)

// Scratch (device globals: allocation-free rule)
__device__ uint16_t g_Qhi[(size_t)Bq*Hq*Sq*64];   // bf16 [B,H,S,64]
__device__ uint16_t g_Qlo[(size_t)Bq*Hq*Sq*64];
__device__ uint16_t g_Khi[(size_t)Bq*Hq*Sq*64];
__device__ uint16_t g_Klo[(size_t)Bq*Hq*Sq*64];
__device__ float    g_V  [(size_t)Bq*Hq*Sq*64];   // tf32-rounded fp32
__device__ float    g_ctx[(size_t)Bq*Sq*Dq];
__device__ float    g_pre[(size_t)Bq*Sq*Dq];

// ---------------------------------------------------------------------------
__device__ __forceinline__ uint32_t f2tf(float x) {
    uint32_t r;
    asm("cvt.rna.tf32.f32 %0, %1;" : "=r"(r) : "f"(x));
    return r;
}

// tf32 m16n8k8
__device__ __forceinline__ void mma8(float* c, const uint32_t* a, uint32_t b0, uint32_t b1) {
    asm volatile(
        "mma.sync.aligned.m16n8k8.row.col.f32.tf32.tf32.f32 "
        "{%0,%1,%2,%3}, {%4,%5,%6,%7}, {%8,%9}, {%0,%1,%2,%3};"
        : "+f"(c[0]), "+f"(c[1]), "+f"(c[2]), "+f"(c[3])
        : "r"(a[0]), "r"(a[1]), "r"(a[2]), "r"(a[3]), "r"(b0), "r"(b1));
}
// bf16 m16n8k16
__device__ __forceinline__ void mma16(float* c, const uint32_t* a, uint32_t b0, uint32_t b1) {
    asm volatile(
        "mma.sync.aligned.m16n8k16.row.col.f32.bf16.bf16.f32 "
        "{%0,%1,%2,%3}, {%4,%5,%6,%7}, {%8,%9}, {%0,%1,%2,%3};"
        : "+f"(c[0]), "+f"(c[1]), "+f"(c[2]), "+f"(c[3])
        : "r"(a[0]), "r"(a[1]), "r"(a[2]), "r"(a[3]), "r"(b0), "r"(b1));
}

__device__ __forceinline__ void cp16g(void* dst, const void* src) {
    uint32_t d = (uint32_t)__cvta_generic_to_shared(dst);
    asm volatile("cp.async.cg.shared.global [%0], [%1], 16;" :: "r"(d), "l"(src));
}
__device__ __forceinline__ void cp_commit() { asm volatile("cp.async.commit_group;"); }
template<int N> __device__ __forceinline__ void cp_wait() {
    asm volatile("cp.async.wait_group %0;" :: "n"(N));
}

// ---------------------------------------------------------------------------
// Tiled fp32 GEMM: C[M=8192, N=512] = A[M,512] @ W[512,512]
// MODE 1: fc + residual (fp32 out)
// MODE 2: projection -> bf16 hi/lo pair, permuted [B,H,S,64], acc *= scale
// MODE 3: projection -> tf32-rounded fp32, permuted [B,H,S,64]
// ---------------------------------------------------------------------------
template <int MODE>
__global__ __launch_bounds__(256)
void gemm64(const float* __restrict__ A, const float* __restrict__ W,
            void* __restrict__ out0, void* __restrict__ out1,
            const float* __restrict__ resid, float scale)
{
    __shared__ float As[32 * 68];
    __shared__ float Bs[32 * 68];

    const int tid = threadIdx.x;
    const int tx  = tid & 15;
    const int ty  = tid >> 4;
    const int n0  = blockIdx.x * 64;
    const int m0b = blockIdx.y * 64;

    float acc[4][4];
#pragma unroll
    for (int i = 0; i < 4; i++)
#pragma unroll
        for (int j = 0; j < 4; j++) acc[i][j] = 0.f;

    for (int k0 = 0; k0 < 512; k0 += 32) {
#pragma unroll
        for (int l = tid; l < 512; l += 256) {
            int m_l = l >> 3;
            int kq  = (l & 7) * 4;
            float4 v = *(const float4*)(A + (size_t)(m0b + m_l) * 512 + k0 + kq);
            As[(kq + 0) * 68 + m_l] = v.x;
            As[(kq + 1) * 68 + m_l] = v.y;
            As[(kq + 2) * 68 + m_l] = v.z;
            As[(kq + 3) * 68 + m_l] = v.w;
        }
#pragma unroll
        for (int l = tid; l < 512; l += 256) {
            int k_l = l >> 4;
            int nq  = (l & 15) * 4;
            float4 v = *(const float4*)(W + (size_t)(k0 + k_l) * 512 + n0 + nq);
            *(float4*)&Bs[k_l * 68 + nq] = v;
        }
        __syncthreads();

#pragma unroll
        for (int k = 0; k < 32; k++) {
            float4 a = *(float4*)&As[k * 68 + ty * 4];
            float4 b = *(float4*)&Bs[k * 68 + tx * 4];
            acc[0][0] += a.x * b.x; acc[0][1] += a.x * b.y; acc[0][2] += a.x * b.z; acc[0][3] += a.x * b.w;
            acc[1][0] += a.y * b.x; acc[1][1] += a.y * b.y; acc[1][2] += a.y * b.z; acc[1][3] += a.y * b.w;
            acc[2][0] += a.z * b.x; acc[2][1] += a.z * b.y; acc[2][2] += a.z * b.z; acc[2][3] += a.z * b.w;
            acc[3][0] += a.w * b.x; acc[3][1] += a.w * b.y; acc[3][2] += a.w * b.z; acc[3][3] += a.w * b.w;
        }
        __syncthreads();
    }

    if (MODE == 1) {
        float* out = (float*)out0;
#pragma unroll
        for (int i = 0; i < 4; i++) {
            int m = m0b + ty * 4 + i;
            float4 rv = *(const float4*)&resid[(size_t)m * 512 + n0 + tx * 4];
            float4 r = make_float4(acc[i][0] + rv.x, acc[i][1] + rv.y,
                                   acc[i][2] + rv.z, acc[i][3] + rv.w);
            *(float4*)&out[(size_t)m * 512 + n0 + tx * 4] = r;
        }
    } else {
        const int h  = blockIdx.x;            // 64-col slice == head
        const int e0 = tx * 4;
#pragma unroll
        for (int i = 0; i < 4; i++) {
            int m = m0b + ty * 4 + i;
            int b = m >> 11;
            int s = m & 2047;
            size_t off = (((size_t)b * Hq + h) * Sq + s) * 64 + e0;
            if (MODE == 2) {
                uint16_t hi[4], lo[4];
#pragma unroll
                for (int j = 0; j < 4; j++) {
                    float v = acc[i][j] * scale;
                    __nv_bfloat16 hb = __float2bfloat16_rn(v);
                    float hf = __bfloat162float(hb);
                    __nv_bfloat16 lb = __float2bfloat16_rn(v - hf);
                    hi[j] = *(uint16_t*)&hb;
                    lo[j] = *(uint16_t*)&lb;
                }
                *(uint2*)((uint16_t*)out0 + off) = *(uint2*)hi;
                *(uint2*)((uint16_t*)out1 + off) = *(uint2*)lo;
            } else {  // MODE 3
                float4 r;
                r.x = __uint_as_float(f2tf(acc[i][0]));
                r.y = __uint_as_float(f2tf(acc[i][1]));
                r.z = __uint_as_float(f2tf(acc[i][2]));
                r.w = __uint_as_float(f2tf(acc[i][3]));
                *(float4*)((float*)out0 + off) = r;
            }
        }
    }
}

// ---------------------------------------------------------------------------
// Fused attention, 512 threads = 16 warps, 128-key tiles, 2-stage cp.async.
// phase 2: bf16 m16n8k16 3-term (Qhi/Qlo x Khi/Klo precomputed) -> fp32 scores
// phase 3: 1 softmax row per warp; exact fp32 attn out; tf32 P in smem
// phase 5: tf32 m16n8k8, V pre-rounded; cross-warpgroup smem reduction
// ---------------------------------------------------------------------------
__global__ __launch_bounds__(512, 1)
void attn_kernel(const uint16_t* __restrict__ Qhi, const uint16_t* __restrict__ Qlo,
                 const uint16_t* __restrict__ Khi, const uint16_t* __restrict__ Klo,
                 const float* __restrict__ Vm, const unsigned* __restrict__ mask,
                 float* __restrict__ attn_out, float* __restrict__ ctx)
{
    extern __shared__ float sm[];
    float* scores = sm;                                  // 16*SST floats
    char*  kvb    = (char*)(sm + 16 * SST);              // 2 * KVB_BYTES
    float* qreg   = (float*)(kvb + 2 * KVB_BYTES);       // 1088 floats

    const int bh  = blockIdx.x;
    const int qt  = blockIdx.y;
    const int b   = bh >> 3;
    const int h   = bh & 7;
    const int tid = threadIdx.x;
    const int warp = tid >> 5;
    const int lane = tid & 31;
    const int g = lane >> 2;
    const int t = lane & 3;
    const int wg = warp >> 3;
    const int wi = warp & 7;

    const size_t bhoff = (size_t)bh * Sq * 64;
    const uint16_t* KhiB = Khi + bhoff;
    const uint16_t* KloB = Klo + bhoff;
    const float*    VB   = Vm  + bhoff;

    // ---- staging helpers ----
    // K tile (hi+lo bf16): 2048 x 16B chunks, 4 per thread
#define STAGE_K(stg, kt_)                                                     \
    {                                                                         \
        char* _base = kvb + (stg) * KVB_BYTES;                                \
        size_t _g0 = (size_t)(kt_) * TKEYS * 64;                              \
        _Pragma("unroll")                                                     \
        for (int _j = 0; _j < 4; _j++) {                                      \
            int _i = tid + _j * 512;                                          \
            int _arr = _i >> 10, _c = _i & 1023;                              \
            int _row = _c >> 3, _col = (_c & 7) * 8;                          \
            const uint16_t* _s = (_arr ? KloB : KhiB) + _g0 + _row * 64 + _col;\
            cp16g(_base + _arr * 18432 + (_row * KHS + _col) * 2, _s);        \
        }                                                                     \
    }
    // V tile (fp32): 2048 x 16B chunks, 4 per thread
#define STAGE_V(stg, kt_)                                                     \
    {                                                                         \
        float* _d = (float*)(kvb + (stg) * KVB_BYTES);                        \
        const float* _s = VB + (size_t)(kt_) * TKEYS * 64;                    \
        _Pragma("unroll")                                                     \
        for (int _j = 0; _j < 4; _j++) {                                      \
            int _i = (tid + _j * 512) * 4;                                    \
            cp16g(&_d[(_i >> 6) * VSP + (_i & 63)], _s + _i);                 \
        }                                                                     \
    }

    // prologue: stage K tile 0
    STAGE_K(0, 0);
    cp_commit();

    // stage Q tiles (bf16 hi/lo, 16x64 each) into qreg
    uint16_t* qhs = (uint16_t*)qreg;              // stride QHS
    uint16_t* qls = qhs + 16 * QHS;
    {
        const size_t qoff = bhoff + (size_t)qt * 16 * 64;
#pragma unroll
        for (int j = 0; j < 2; j++) {
            int i = tid + j * 512;                // 0..1023
            int r = i >> 6, d = i & 63;
            qhs[r * QHS + d] = Qhi[qoff + i];
            qls[r * QHS + d] = Qlo[qoff + i];
        }
    }
    __syncthreads();

    // Q fragments: 4 d-chunks of 16
    uint32_t qh[4][4], ql[4][4];
#pragma unroll
    for (int ch = 0; ch < 4; ch++) {
        int d0 = ch * 16 + 2 * t;
        qh[ch][0] = *(uint32_t*)&qhs[g * QHS + d0];
        qh[ch][1] = *(uint32_t*)&qhs[(g + 8) * QHS + d0];
        qh[ch][2] = *(uint32_t*)&qhs[g * QHS + d0 + 8];
        qh[ch][3] = *(uint32_t*)&qhs[(g + 8) * QHS + d0 + 8];
        ql[ch][0] = *(uint32_t*)&qls[g * QHS + d0];
        ql[ch][1] = *(uint32_t*)&qls[(g + 8) * QHS + d0];
        ql[ch][2] = *(uint32_t*)&qls[g * QHS + d0 + 8];
        ql[ch][3] = *(uint32_t*)&qls[(g + 8) * QHS + d0 + 8];
    }

    // ---- phase 2: scores = Q @ K^T (bf16 3-term) ----
    const int n0 = warp * 8;
#pragma unroll 1
    for (int kt = 0; kt < NT; kt++) {
        cp_wait<0>();
        __syncthreads();
        if (kt + 1 < NT) { STAGE_K((kt + 1) & 1, kt + 1); }
        cp_commit();

        const uint16_t* khib = (const uint16_t*)(kvb + (kt & 1) * KVB_BYTES);
        const uint16_t* klob = khib + 9216;
        float acc[2][4] = {{0.f,0.f,0.f,0.f},{0.f,0.f,0.f,0.f}};
        const int boff0 = (n0 + g) * KHS + 2 * t;
#pragma unroll
        for (int ch = 0; ch < 4; ch++) {
            int boff = boff0 + ch * 16;
            uint32_t bh0 = *(const uint32_t*)&khib[boff];
            uint32_t bh1 = *(const uint32_t*)&khib[boff + 8];
            uint32_t bl0 = *(const uint32_t*)&klob[boff];
            uint32_t bl1 = *(const uint32_t*)&klob[boff + 8];
            mma16(acc[ch & 1], qh[ch], bh0, bh1);
            mma16(acc[ch & 1], ql[ch], bh0, bh1);
            mma16(acc[ch & 1], qh[ch], bl0, bl1);
        }
        int col = kt * TKEYS + n0 + 2 * t;
        *(float2*)&scores[g * SST + col]       = make_float2(acc[0][0] + acc[1][0], acc[0][1] + acc[1][1]);
        *(float2*)&scores[(g + 8) * SST + col] = make_float2(acc[0][2] + acc[1][2], acc[0][3] + acc[1][3]);
    }

    // stage V tile 0
    STAGE_V(0, 0);
    cp_commit();
    __syncthreads();

    // ---- phase 3/4: mask + softmax, one row per warp ----
    {
        const int row = warp;
        const int qg  = qt * 16 + row;
        const uint2* mrow2 = (const uint2*)(mask + ((size_t)b * Sq + qg) * Sq);
        float2* srow2 = (float2*)(scores + row * SST);

        float mx = -1e30f;
#pragma unroll 4
        for (int i = lane; i < 1024; i += 32) {
            float2 s = srow2[i];
            uint2  m = mrow2[i];
            s.x = m.x ? -1e9f : s.x;
            s.y = m.y ? -1e9f : s.y;
            srow2[i] = s;
            mx = fmaxf(mx, fmaxf(s.x, s.y));
        }
#pragma unroll
        for (int o = 16; o; o >>= 1) mx = fmaxf(mx, __shfl_xor_sync(0xffffffffu, mx, o));

        float sum = 0.f;
#pragma unroll 4
        for (int i = lane; i < 1024; i += 32) {
            float2 s = srow2[i];
            s.x = __expf(s.x - mx);
            s.y = __expf(s.y - mx);
            srow2[i] = s;
            sum += s.x + s.y;
        }
#pragma unroll
        for (int o = 16; o; o >>= 1) sum += __shfl_xor_sync(0xffffffffu, sum, o);
        float inv = 1.0f / sum;

        if (attn_out) {
            float2* arow2 = (float2*)(attn_out + ((size_t)bh * Sq + qg) * Sq);
#pragma unroll 4
            for (int i = lane; i < 1024; i += 32) {
                float2 p = srow2[i];
                float2 pn = make_float2(p.x * inv, p.y * inv);
                arow2[i] = pn;
                srow2[i] = make_float2(__uint_as_float(f2tf(pn.x)),
                                       __uint_as_float(f2tf(pn.y)));
            }
        } else {
#pragma unroll 4
            for (int i = lane; i < 1024; i += 32) {
                float2 p = srow2[i];
                srow2[i] = make_float2(__uint_as_float(f2tf(p.x * inv)),
                                       __uint_as_float(f2tf(p.y * inv)));
            }
        }
    }

    // ---- phase 5: ctx = P @ V (tf32; V pre-rounded) ----
    float cacc[2][4] = {{0.f,0.f,0.f,0.f},{0.f,0.f,0.f,0.f}};
    const int d0w  = wi * 8;
    const int krow = wg * 64;
#pragma unroll 1
    for (int kt = 0; kt < NT; kt++) {
        cp_wait<0>();
        __syncthreads();
        if (kt + 1 < NT) { STAGE_V((kt + 1) & 1, kt + 1); }
        cp_commit();

        const float* vsb = (const float*)(kvb + (kt & 1) * KVB_BYTES);
        const int kb = kt * TKEYS + krow;
#pragma unroll
        for (int sub = 0; sub < 8; sub++) {
            int k0 = kb + sub * 8;
            uint32_t a[4];
            a[0] = __float_as_uint(scores[g * SST + k0 + t]);
            a[1] = __float_as_uint(scores[(g + 8) * SST + k0 + t]);
            a[2] = __float_as_uint(scores[g * SST + k0 + t + 4]);
            a[3] = __float_as_uint(scores[(g + 8) * SST + k0 + t + 4]);
            uint32_t b0 = __float_as_uint(vsb[(krow + sub * 8 + t) * VSP + d0w + g]);
            uint32_t b1 = __float_as_uint(vsb[(krow + sub * 8 + t + 4) * VSP + d0w + g]);
            mma8(cacc[sub & 1], a, b0, b1);
        }
    }

    // cross-group reduction via qreg (exact fp32)
    float2 r0 = make_float2(cacc[0][0] + cacc[1][0], cacc[0][1] + cacc[1][1]);
    float2 r1 = make_float2(cacc[0][2] + cacc[1][2], cacc[0][3] + cacc[1][3]);
    __syncthreads();
    if (wg == 1) {
        *(float2*)&qreg[g * VSP + d0w + 2 * t]       = r0;
        *(float2*)&qreg[(g + 8) * VSP + d0w + 2 * t] = r1;
    }
    __syncthreads();
    if (wg == 0) {
        float2 p0 = *(float2*)&qreg[g * VSP + d0w + 2 * t];
        float2 p1 = *(float2*)&qreg[(g + 8) * VSP + d0w + 2 * t];
        int qg   = qt * 16;
        int dcol = h * 64 + d0w + 2 * t;
        *(float2*)&ctx[((size_t)b * Sq + qg + g) * Dq + dcol] =
            make_float2(r0.x + p0.x, r0.y + p0.y);
        *(float2*)&ctx[((size_t)b * Sq + qg + g + 8) * Dq + dcol] =
            make_float2(r1.x + p1.x, r1.y + p1.y);
    }
#undef STAGE_K
#undef STAGE_V
}

// ---------------------------------------------------------------------------
__global__ __launch_bounds__(128)
void ln_kernel(const float* __restrict__ x, const float* __restrict__ gamma,
               const float* __restrict__ beta, float* __restrict__ out)
{
    const int row = blockIdx.x;
    const int tid = threadIdx.x;
    const float* xr = x + (size_t)row * 512;

    float4 v = *(const float4*)(xr + tid * 4);
    float s  = v.x + v.y + v.z + v.w;
    float ss = v.x * v.x + v.y * v.y + v.z * v.z + v.w * v.w;

    const int lane = tid & 31, warp = tid >> 5;
#pragma unroll
    for (int o = 16; o; o >>= 1) {
        s  += __shfl_xor_sync(0xffffffffu, s, o);
        ss += __shfl_xor_sync(0xffffffffu, ss, o);
    }
    __shared__ float sh_s[4], sh_ss[4];
    if (lane == 0) { sh_s[warp] = s; sh_ss[warp] = ss; }
    __syncthreads();
    float tot  = sh_s[0] + sh_s[1] + sh_s[2] + sh_s[3];
    float tots = sh_ss[0] + sh_ss[1] + sh_ss[2] + sh_ss[3];

    float mu   = tot * (1.0f / 512.0f);
    float var  = tots * (1.0f / 512.0f) - mu * mu;
    float rstd = rsqrtf(var + LN_EPS);

    float4 g  = *(const float4*)(gamma + tid * 4);
    float4 be = *(const float4*)(beta + tid * 4);
    float4 r;
    r.x = (v.x - mu) * rstd * g.x + be.x;
    r.y = (v.y - mu) * rstd * g.y + be.y;
    r.z = (v.z - mu) * rstd * g.z + be.z;
    r.w = (v.w - mu) * rstd * g.w + be.w;
    *(float4*)&out[(size_t)row * 512 + tid * 4] = r;
}

// ---------------------------------------------------------------------------
extern "C" void kernel_launch(void* const* d_in, const int* in_sizes, int n_in,
                              void* d_out, int out_size)
{
    const float*    inQ   = (const float*)d_in[0];
    const float*    inK   = (const float*)d_in[1];
    const float*    inV   = (const float*)d_in[2];
    const unsigned* mask  = (const unsigned*)d_in[3];
    const float*    WQ    = (const float*)d_in[4];
    const float*    WK    = (const float*)d_in[5];
    const float*    WV    = (const float*)d_in[6];
    const float*    Wfc   = (const float*)d_in[7];
    const float*    gamma = (const float*)d_in[8];
    const float*    beta  = (const float*)d_in[9];
    float* out = (float*)d_out;

    uint16_t *gQhi, *gQlo, *gKhi, *gKlo;
    float *gV, *gctx, *gpre;
    cudaGetSymbolAddress((void**)&gQhi, g_Qhi);
    cudaGetSymbolAddress((void**)&gQlo, g_Qlo);
    cudaGetSymbolAddress((void**)&gKhi, g_Khi);
    cudaGetSymbolAddress((void**)&gKlo, g_Klo);
    cudaGetSymbolAddress((void**)&gV,   g_V);
    cudaGetSymbolAddress((void**)&gctx, g_ctx);
    cudaGetSymbolAddress((void**)&gpre, g_pre);

    dim3 ggrid(8, 128), gblk(256);
    gemm64<2><<<ggrid, gblk>>>(inQ, WQ, gQhi, gQlo, nullptr, 0.125f);
    gemm64<2><<<ggrid, gblk>>>(inK, WK, gKhi, gKlo, nullptr, 1.0f);
    gemm64<3><<<ggrid, gblk>>>(inV, WV, gV, nullptr, nullptr, 1.0f);

    const size_t BSD  = (size_t)Bq * Sq * Dq;
    const size_t BHSS = (size_t)Bq * Hq * Sq * Sq;
    float* attn_ptr = ((size_t)out_size >= BSD + BHSS) ? (out + BSD) : nullptr;

    size_t smem = 16 * SST * 4 + 2 * KVB_BYTES + 1088 * 4;   // 209,664 B
    cudaFuncSetAttribute(attn_kernel, cudaFuncAttributeMaxDynamicSharedMemorySize, (int)smem);
    attn_kernel<<<dim3(32, 128), 512, smem>>>(gQhi, gQlo, gKhi, gKlo, gV, mask, attn_ptr, gctx);

    gemm64<1><<<ggrid, gblk>>>(gctx, Wfc, gpre, nullptr, inQ, 1.0f);
    ln_kernel<<<Bq * Sq, 128>>>(gpre, gamma, beta, out);
}

// round 6
// speedup vs baseline: 3.2430x; 1.2448x over previous
#include <cuda_runtime.h>
#include <cuda_bf16.h>
#include <cstdint>

// Problem constants
#define Bq   4
#define Sq   2048
#define Dq   512
#define Hq   8
#define LN_EPS 1e-5f

// attn smem layout (bytes)
#define SST        2052                       // scores row stride (floats)
#define OFF_R      (16 * SST * 4)             // 131,328
#define KSTG_BYTES 34816                      // K stage: 128 keys x 272B (hi64|lo64, stride 136 bf16)
#define OFF_VT     (OFF_R + 2 * KSTG_BYTES)   // 200,960
#define VSTG_BYTES 9216                       // V stage: 64 d-rows x 144B (stride 72 bf16)
#define SMEM_ATTN  (OFF_VT + 3 * VSTG_BYTES)  // 228,608
#define PBS        2056                       // pb (bf16 P) row stride in bf16 units (word 1028 == 4 mod 32)
#define NTK        16                         // K tiles (128 keys)
#define NTV        32                         // V tiles (64 keys)

// Scratch (device globals: allocation-free rule)
__device__ uint16_t g_Q[(size_t)Bq*Hq*Sq*128];   // bf16 [B,H,S,(hi64|lo64)]
__device__ uint16_t g_K[(size_t)Bq*Hq*Sq*128];   // bf16 [B,H,S,(hi64|lo64)]
__device__ uint16_t g_V[(size_t)Bq*Hq*64*Sq];    // bf16 transposed [B,H,d,S]
__device__ float    g_ctx[(size_t)Bq*Sq*Dq];
__device__ float    g_pre[(size_t)Bq*Sq*Dq];

// ---------------------------------------------------------------------------
__device__ __forceinline__ uint16_t bfbits(float x) {
    __nv_bfloat16 b = __float2bfloat16_rn(x);
    return *(uint16_t*)&b;
}
__device__ __forceinline__ float bf2f(uint16_t u) {
    __nv_bfloat16 b = *(__nv_bfloat16*)&u;
    return __bfloat162float(b);
}

// bf16 m16n8k16
__device__ __forceinline__ void mma16(float* c, const uint32_t* a, uint32_t b0, uint32_t b1) {
    asm volatile(
        "mma.sync.aligned.m16n8k16.row.col.f32.bf16.bf16.f32 "
        "{%0,%1,%2,%3}, {%4,%5,%6,%7}, {%8,%9}, {%0,%1,%2,%3};"
        : "+f"(c[0]), "+f"(c[1]), "+f"(c[2]), "+f"(c[3])
        : "r"(a[0]), "r"(a[1]), "r"(a[2]), "r"(a[3]), "r"(b0), "r"(b1));
}

__device__ __forceinline__ void cp16g(void* dst, const void* src) {
    uint32_t d = (uint32_t)__cvta_generic_to_shared(dst);
    asm volatile("cp.async.cg.shared.global [%0], [%1], 16;" :: "r"(d), "l"(src));
}
__device__ __forceinline__ void cp_commit() { asm volatile("cp.async.commit_group;"); }
template<int N> __device__ __forceinline__ void cp_wait() {
    asm volatile("cp.async.wait_group %0;" :: "n"(N));
}

// ---------------------------------------------------------------------------
// Tiled fp32 GEMM: C[M=8192, N=512] = A[M,512] @ W[512,512]
// MODE 1: fc + residual (fp32 out)
// MODE 2: projection -> interleaved bf16 hi|lo, [B,H,S,128], acc *= scale
// MODE 3: projection -> transposed bf16, [B,H,64,S]
// ---------------------------------------------------------------------------
template <int MODE>
__global__ __launch_bounds__(256)
void gemm64(const float* __restrict__ A, const float* __restrict__ W,
            void* __restrict__ out0, const float* __restrict__ resid, float scale)
{
    __shared__ float As[32 * 68];
    __shared__ float Bs[32 * 68];

    const int tid = threadIdx.x;
    const int tx  = tid & 15;
    const int ty  = tid >> 4;
    const int n0  = blockIdx.x * 64;
    const int m0b = blockIdx.y * 64;

    float acc[4][4];
#pragma unroll
    for (int i = 0; i < 4; i++)
#pragma unroll
        for (int j = 0; j < 4; j++) acc[i][j] = 0.f;

    for (int k0 = 0; k0 < 512; k0 += 32) {
#pragma unroll
        for (int l = tid; l < 512; l += 256) {
            int m_l = l >> 3;
            int kq  = (l & 7) * 4;
            float4 v = *(const float4*)(A + (size_t)(m0b + m_l) * 512 + k0 + kq);
            As[(kq + 0) * 68 + m_l] = v.x;
            As[(kq + 1) * 68 + m_l] = v.y;
            As[(kq + 2) * 68 + m_l] = v.z;
            As[(kq + 3) * 68 + m_l] = v.w;
        }
#pragma unroll
        for (int l = tid; l < 512; l += 256) {
            int k_l = l >> 4;
            int nq  = (l & 15) * 4;
            float4 v = *(const float4*)(W + (size_t)(k0 + k_l) * 512 + n0 + nq);
            *(float4*)&Bs[k_l * 68 + nq] = v;
        }
        __syncthreads();

#pragma unroll
        for (int k = 0; k < 32; k++) {
            float4 a = *(float4*)&As[k * 68 + ty * 4];
            float4 b = *(float4*)&Bs[k * 68 + tx * 4];
            acc[0][0] += a.x * b.x; acc[0][1] += a.x * b.y; acc[0][2] += a.x * b.z; acc[0][3] += a.x * b.w;
            acc[1][0] += a.y * b.x; acc[1][1] += a.y * b.y; acc[1][2] += a.y * b.z; acc[1][3] += a.y * b.w;
            acc[2][0] += a.z * b.x; acc[2][1] += a.z * b.y; acc[2][2] += a.z * b.z; acc[2][3] += a.z * b.w;
            acc[3][0] += a.w * b.x; acc[3][1] += a.w * b.y; acc[3][2] += a.w * b.z; acc[3][3] += a.w * b.w;
        }
        __syncthreads();
    }

    if (MODE == 1) {
        float* out = (float*)out0;
#pragma unroll
        for (int i = 0; i < 4; i++) {
            int m = m0b + ty * 4 + i;
            float4 rv = *(const float4*)&resid[(size_t)m * 512 + n0 + tx * 4];
            float4 r = make_float4(acc[i][0] + rv.x, acc[i][1] + rv.y,
                                   acc[i][2] + rv.z, acc[i][3] + rv.w);
            *(float4*)&out[(size_t)m * 512 + n0 + tx * 4] = r;
        }
    } else if (MODE == 2) {
        const int h  = blockIdx.x;
        const int e0 = tx * 4;
        uint16_t* o = (uint16_t*)out0;
#pragma unroll
        for (int i = 0; i < 4; i++) {
            int m = m0b + ty * 4 + i;
            int b = m >> 11;
            int s = m & 2047;
            size_t base = (((size_t)b * Hq + h) * Sq + s) * 128 + e0;
            uint16_t hi[4], lo[4];
#pragma unroll
            for (int j = 0; j < 4; j++) {
                float v = acc[i][j] * scale;
                hi[j] = bfbits(v);
                lo[j] = bfbits(v - bf2f(hi[j]));
            }
            *(uint2*)(o + base)      = *(uint2*)hi;
            *(uint2*)(o + base + 64) = *(uint2*)lo;
        }
    } else {  // MODE 3: V transposed bf16 [B,H,d,S]
        const int h  = blockIdx.x;
        const int e0 = tx * 4;
        const int m0 = m0b + ty * 4;
        const int b  = m0 >> 11;
        const int s0 = m0 & 2047;
        uint16_t* o = (uint16_t*)out0;
        size_t rowbase = (size_t)(b * Hq + h) * 64;
#pragma unroll
        for (int j = 0; j < 4; j++) {
            uint16_t pk[4];
            pk[0] = bfbits(acc[0][j]);
            pk[1] = bfbits(acc[1][j]);
            pk[2] = bfbits(acc[2][j]);
            pk[3] = bfbits(acc[3][j]);
            *(uint2*)(o + (rowbase + e0 + j) * Sq + s0) = *(uint2*)pk;
        }
    }
}

// ---------------------------------------------------------------------------
// Fused attention, 512 threads = 16 warps.
// phase 2: 128-key K tiles (hi|lo bf16), m16n8k16 3-term -> fp32 scores
// phase 3: fused mask+exp+sum, then normalize + attn write + bf16 P pack (2 passes)
// phase 5: 64-key transposed-V tiles (bf16), m16n8k16, conflict-free LDS,
//          3-buffer cp.async ring; cross-warpgroup fp32 reduction
// ---------------------------------------------------------------------------
__global__ __launch_bounds__(512, 1)
void attn_kernel(const uint16_t* __restrict__ Qm, const uint16_t* __restrict__ Km,
                 const uint16_t* __restrict__ Vt, const unsigned* __restrict__ mask,
                 float* __restrict__ attn_out, float* __restrict__ ctx)
{
    extern __shared__ char smc[];
    float*    scores = (float*)smc;              // 16 x SST fp32
    char*     Rb     = smc + OFF_R;              // K double buffer, then pb
    uint16_t* pb     = (uint16_t*)Rb;            // bf16 P, 16 x PBS
    char*     vtb    = smc + OFF_VT;             // Q stage / V ring / reduction
    uint16_t* qs     = (uint16_t*)vtb;           // Q stage: 16 x 136 bf16

    const int bh  = blockIdx.x;
    const int qt  = blockIdx.y;
    const int b   = bh >> 3;
    const int h   = bh & 7;
    const int tid = threadIdx.x;
    const int warp = tid >> 5;
    const int lane = tid & 31;
    const int g = lane >> 2;
    const int t = lane & 3;
    const int wg = warp >> 3;
    const int wi = warp & 7;

    const uint16_t* KB = Km + (size_t)bh * Sq * 128;
    const uint16_t* VB = Vt + (size_t)bh * 64 * Sq;

#define STAGE_K(stg, kt_)                                                  \
    {                                                                      \
        char* _d = Rb + (stg) * KSTG_BYTES;                                \
        const uint16_t* _s = KB + (size_t)(kt_) * 128 * 128;               \
        _Pragma("unroll")                                                  \
        for (int _j = 0; _j < 4; _j++) {                                   \
            int _c = tid + _j * 512;                                       \
            int _r = _c >> 4, _c16 = _c & 15;                              \
            cp16g(_d + _r * 272 + _c16 * 16, _s + _r * 128 + _c16 * 8);    \
        }                                                                  \
    }
#define STAGE_V(stg, kt_)                                                  \
    {                                                                      \
        char* _d = vtb + (stg) * VSTG_BYTES;                               \
        const uint16_t* _s = VB + (size_t)(kt_) * 64;                      \
        int _dd = tid >> 3, _c = tid & 7;                                  \
        cp16g(_d + _dd * 144 + _c * 16, _s + (size_t)_dd * Sq + _c * 8);   \
    }

    // prologue: K tile 0, Q tile
    STAGE_K(0, 0);
    cp_commit();
    if (tid < 256) {
        int r = tid >> 4, c16 = tid & 15;
        cp16g(vtb + r * 272 + c16 * 16,
              Qm + (size_t)bh * Sq * 128 + (size_t)(qt * 16 + r) * 128 + c16 * 8);
    }
    cp_commit();
    cp_wait<0>();
    __syncthreads();

    // Q fragments (hi/lo bf16)
    uint32_t qh[4][4], ql[4][4];
#pragma unroll
    for (int ch = 0; ch < 4; ch++) {
        int c0 = ch * 16 + 2 * t;
        qh[ch][0] = *(uint32_t*)&qs[g * 136 + c0];
        qh[ch][1] = *(uint32_t*)&qs[(g + 8) * 136 + c0];
        qh[ch][2] = *(uint32_t*)&qs[g * 136 + c0 + 8];
        qh[ch][3] = *(uint32_t*)&qs[(g + 8) * 136 + c0 + 8];
        ql[ch][0] = *(uint32_t*)&qs[g * 136 + c0 + 64];
        ql[ch][1] = *(uint32_t*)&qs[(g + 8) * 136 + c0 + 64];
        ql[ch][2] = *(uint32_t*)&qs[g * 136 + c0 + 72];
        ql[ch][3] = *(uint32_t*)&qs[(g + 8) * 136 + c0 + 72];
    }

    // ---- phase 2: scores = Q @ K^T ----
    const int n0 = warp * 8;
#pragma unroll 1
    for (int kt = 0; kt < NTK; kt++) {
        if (kt + 1 < NTK) { STAGE_K((kt + 1) & 1, kt + 1); cp_commit(); }

        const uint16_t* kb_ = (const uint16_t*)(Rb + (kt & 1) * KSTG_BYTES);
        float acc[2][4] = {{0.f,0.f,0.f,0.f},{0.f,0.f,0.f,0.f}};
#pragma unroll
        for (int ch = 0; ch < 4; ch++) {
            const uint16_t* kr = &kb_[(n0 + g) * 136 + ch * 16 + 2 * t];
            uint32_t bh0 = *(const uint32_t*)kr;
            uint32_t bh1 = *(const uint32_t*)(kr + 8);
            uint32_t bl0 = *(const uint32_t*)(kr + 64);
            uint32_t bl1 = *(const uint32_t*)(kr + 72);
            mma16(acc[ch & 1], qh[ch], bh0, bh1);
            mma16(acc[ch & 1], ql[ch], bh0, bh1);
            mma16(acc[ch & 1], qh[ch], bl0, bl1);
        }
        int col = kt * 128 + n0 + 2 * t;
        *(float2*)&scores[g * SST + col]       = make_float2(acc[0][0] + acc[1][0], acc[0][1] + acc[1][1]);
        *(float2*)&scores[(g + 8) * SST + col] = make_float2(acc[0][2] + acc[1][2], acc[0][3] + acc[1][3]);

        if (kt + 1 < NTK) { cp_wait<0>(); __syncthreads(); }
    }

    // stage V tiles 0,1
    STAGE_V(0, 0); cp_commit();
    STAGE_V(1, 1); cp_commit();
    __syncthreads();   // all phase-2 done; scores visible; Rb free for pb

    // ---- phase 3/4: fused mask+exp+sum, then normalize+write (1 row/warp) ----
    {
        const int row = warp;
        const int qg  = qt * 16 + row;
        const uint2* mrow2 = (const uint2*)(mask + ((size_t)b * Sq + qg) * Sq);
        float2* srow2 = (float2*)(scores + row * SST);

        float sum = 0.f;
#pragma unroll 4
        for (int i = lane; i < 1024; i += 32) {
            float2 s = srow2[i];
            uint2  m = mrow2[i];
            float px = m.x ? 0.f : __expf(s.x);
            float py = m.y ? 0.f : __expf(s.y);
            srow2[i] = make_float2(px, py);
            sum += px + py;
        }
#pragma unroll
        for (int o = 16; o; o >>= 1) sum += __shfl_xor_sync(0xffffffffu, sum, o);
        float inv = 1.0f / sum;

        uint32_t* prow = (uint32_t*)&pb[row * PBS];
        if (attn_out) {
            float2* arow2 = (float2*)(attn_out + ((size_t)bh * Sq + qg) * Sq);
#pragma unroll 4
            for (int i = lane; i < 1024; i += 32) {
                float2 p = srow2[i];
                float2 pn = make_float2(p.x * inv, p.y * inv);
                arow2[i] = pn;
                __nv_bfloat162 h2 = __float22bfloat162_rn(pn);
                prow[i] = *(uint32_t*)&h2;
            }
        } else {
#pragma unroll 4
            for (int i = lane; i < 1024; i += 32) {
                float2 p = srow2[i];
                float2 pn = make_float2(p.x * inv, p.y * inv);
                __nv_bfloat162 h2 = __float22bfloat162_rn(pn);
                prow[i] = *(uint32_t*)&h2;
            }
        }
    }

    // ---- phase 5: ctx = P @ V (bf16) ----
    float cacc[2][4] = {{0.f,0.f,0.f,0.f},{0.f,0.f,0.f,0.f}};
    const int d0w = wi * 8;
#pragma unroll 1
    for (int kt = 0; kt < NTV; kt++) {
        cp_wait<1>();
        __syncthreads();
        if (kt + 2 < NTV) { STAGE_V((kt + 2) % 3, kt + 2); }
        cp_commit();   // unconditional -> uniform wait<1>

        const uint16_t* vb_ = (const uint16_t*)(vtb + (kt % 3) * VSTG_BYTES);
        const int kb0 = kt * 64 + wg * 32;
#pragma unroll
        for (int sub = 0; sub < 2; sub++) {
            int k0 = kb0 + sub * 16;
            uint32_t a[4];
            const uint16_t* p0 = &pb[g * PBS + k0 + 2 * t];
            const uint16_t* p1 = &pb[(g + 8) * PBS + k0 + 2 * t];
            a[0] = *(const uint32_t*)p0;
            a[1] = *(const uint32_t*)p1;
            a[2] = *(const uint32_t*)(p0 + 8);
            a[3] = *(const uint32_t*)(p1 + 8);
            int kl = wg * 32 + sub * 16;              // local key within tile
            const uint16_t* vr = &vb_[(d0w + g) * 72 + kl + 2 * t];
            uint32_t b0 = *(const uint32_t*)vr;
            uint32_t b1 = *(const uint32_t*)(vr + 8);
            mma16(cacc[sub], a, b0, b1);
        }
    }

    // cross-group reduction via vtb (exact fp32)
    float2 r0 = make_float2(cacc[0][0] + cacc[1][0], cacc[0][1] + cacc[1][1]);
    float2 r1 = make_float2(cacc[0][2] + cacc[1][2], cacc[0][3] + cacc[1][3]);
    float* red = (float*)vtb;
    __syncthreads();
    if (wg == 1) {
        *(float2*)&red[g * 68 + d0w + 2 * t]       = r0;
        *(float2*)&red[(g + 8) * 68 + d0w + 2 * t] = r1;
    }
    __syncthreads();
    if (wg == 0) {
        float2 p0 = *(float2*)&red[g * 68 + d0w + 2 * t];
        float2 p1 = *(float2*)&red[(g + 8) * 68 + d0w + 2 * t];
        int qg   = qt * 16;
        int dcol = h * 64 + d0w + 2 * t;
        *(float2*)&ctx[((size_t)b * Sq + qg + g) * Dq + dcol] =
            make_float2(r0.x + p0.x, r0.y + p0.y);
        *(float2*)&ctx[((size_t)b * Sq + qg + g + 8) * Dq + dcol] =
            make_float2(r1.x + p1.x, r1.y + p1.y);
    }
#undef STAGE_K
#undef STAGE_V
}

// ---------------------------------------------------------------------------
__global__ __launch_bounds__(128)
void ln_kernel(const float* __restrict__ x, const float* __restrict__ gamma,
               const float* __restrict__ beta, float* __restrict__ out)
{
    const int row = blockIdx.x;
    const int tid = threadIdx.x;
    const float* xr = x + (size_t)row * 512;

    float4 v = *(const float4*)(xr + tid * 4);
    float s  = v.x + v.y + v.z + v.w;
    float ss = v.x * v.x + v.y * v.y + v.z * v.z + v.w * v.w;

    const int lane = tid & 31, warp = tid >> 5;
#pragma unroll
    for (int o = 16; o; o >>= 1) {
        s  += __shfl_xor_sync(0xffffffffu, s, o);
        ss += __shfl_xor_sync(0xffffffffu, ss, o);
    }
    __shared__ float sh_s[4], sh_ss[4];
    if (lane == 0) { sh_s[warp] = s; sh_ss[warp] = ss; }
    __syncthreads();
    float tot  = sh_s[0] + sh_s[1] + sh_s[2] + sh_s[3];
    float tots = sh_ss[0] + sh_ss[1] + sh_ss[2] + sh_ss[3];

    float mu   = tot * (1.0f / 512.0f);
    float var  = tots * (1.0f / 512.0f) - mu * mu;
    float rstd = rsqrtf(var + LN_EPS);

    float4 g  = *(const float4*)(gamma + tid * 4);
    float4 be = *(const float4*)(beta + tid * 4);
    float4 r;
    r.x = (v.x - mu) * rstd * g.x + be.x;
    r.y = (v.y - mu) * rstd * g.y + be.y;
    r.z = (v.z - mu) * rstd * g.z + be.z;
    r.w = (v.w - mu) * rstd * g.w + be.w;
    *(float4*)&out[(size_t)row * 512 + tid * 4] = r;
}

// ---------------------------------------------------------------------------
extern "C" void kernel_launch(void* const* d_in, const int* in_sizes, int n_in,
                              void* d_out, int out_size)
{
    const float*    inQ   = (const float*)d_in[0];
    const float*    inK   = (const float*)d_in[1];
    const float*    inV   = (const float*)d_in[2];
    const unsigned* mask  = (const unsigned*)d_in[3];
    const float*    WQ    = (const float*)d_in[4];
    const float*    WK    = (const float*)d_in[5];
    const float*    WV    = (const float*)d_in[6];
    const float*    Wfc   = (const float*)d_in[7];
    const float*    gamma = (const float*)d_in[8];
    const float*    beta  = (const float*)d_in[9];
    float* out = (float*)d_out;

    uint16_t *gQ, *gK, *gV;
    float *gctx, *gpre;
    cudaGetSymbolAddress((void**)&gQ,   g_Q);
    cudaGetSymbolAddress((void**)&gK,   g_K);
    cudaGetSymbolAddress((void**)&gV,   g_V);
    cudaGetSymbolAddress((void**)&gctx, g_ctx);
    cudaGetSymbolAddress((void**)&gpre, g_pre);

    dim3 ggrid(8, 128), gblk(256);
    gemm64<2><<<ggrid, gblk>>>(inQ, WQ, gQ, nullptr, 0.125f);
    gemm64<2><<<ggrid, gblk>>>(inK, WK, gK, nullptr, 1.0f);
    gemm64<3><<<ggrid, gblk>>>(inV, WV, gV, nullptr, 1.0f);

    const size_t BSD  = (size_t)Bq * Sq * Dq;
    const size_t BHSS = (size_t)Bq * Hq * Sq * Sq;
    float* attn_ptr = ((size_t)out_size >= BSD + BHSS) ? (out + BSD) : nullptr;

    cudaFuncSetAttribute(attn_kernel, cudaFuncAttributeMaxDynamicSharedMemorySize, SMEM_ATTN);
    attn_kernel<<<dim3(32, 128), 512, SMEM_ATTN>>>(gQ, gK, gV, mask, attn_ptr, gctx);

    gemm64<1><<<ggrid, gblk>>>(gctx, Wfc, gpre, inQ, 1.0f);
    ln_kernel<<<Bq * Sq, 128>>>(gpre, gamma, beta, out);
}

// round 8
// speedup vs baseline: 3.5355x; 1.0902x over previous
#include <cuda_runtime.h>
#include <cuda_bf16.h>
#include <cstdint>

// Problem constants
#define Bq   4
#define Sq   2048
#define Dq   512
#define Hq   8
#define LN_EPS 1e-5f

// attn smem layout (bytes) — round-6 proven
#define SST        2052
#define OFF_R      (16 * SST * 4)             // 131,328
#define KSTG_BYTES 34816
#define OFF_VT     (OFF_R + 2 * KSTG_BYTES)   // 200,960
#define VSTG_BYTES 9216
#define SMEM_ATTN  (OFF_VT + 3 * VSTG_BYTES)  // 228,608
#define PBS        2056
#define NTK        16
#define NTV        32

// Scratch (device globals)
__device__ __align__(16) uint16_t g_Q[(size_t)Bq*Hq*Sq*128];   // bf16 [B,H,S,(hi64|lo64)]
__device__ __align__(16) uint16_t g_K[(size_t)Bq*Hq*Sq*128];
__device__ __align__(16) uint16_t g_V[(size_t)Bq*Hq*64*Sq];    // bf16 transposed [B,H,d,S]
__device__ float    g_ctx[(size_t)Bq*Sq*Dq];                   // fp32 context (round-6)
__device__ float    g_pre[(size_t)Bq*Sq*Dq];
// bf16 splits for Q/K GEMM inputs
__device__ __align__(16) uint16_t s_Qh[(size_t)Bq*Sq*Dq], s_Ql[(size_t)Bq*Sq*Dq];
__device__ __align__(16) uint16_t s_Kh[(size_t)Bq*Sq*Dq], s_Kl[(size_t)Bq*Sq*Dq];
__device__ __align__(16) uint16_t w_Qh[512*512], w_Ql[512*512];
__device__ __align__(16) uint16_t w_Kh[512*512], w_Kl[512*512];

// ---------------------------------------------------------------------------
__device__ __forceinline__ uint16_t bfbits(float x) {
    __nv_bfloat16 b = __float2bfloat16_rn(x);
    return *(uint16_t*)&b;
}
__device__ __forceinline__ float bf2f(uint16_t u) {
    __nv_bfloat16 b = *(__nv_bfloat16*)&u;
    return __bfloat162float(b);
}

__device__ __forceinline__ void mma16(float* c, const uint32_t* a, uint32_t b0, uint32_t b1) {
    asm volatile(
        "mma.sync.aligned.m16n8k16.row.col.f32.bf16.bf16.f32 "
        "{%0,%1,%2,%3}, {%4,%5,%6,%7}, {%8,%9}, {%0,%1,%2,%3};"
        : "+f"(c[0]), "+f"(c[1]), "+f"(c[2]), "+f"(c[3])
        : "r"(a[0]), "r"(a[1]), "r"(a[2]), "r"(a[3]), "r"(b0), "r"(b1));
}

__device__ __forceinline__ void cp16g(void* dst, const void* src) {
    uint32_t d = (uint32_t)__cvta_generic_to_shared(dst);
    asm volatile("cp.async.cg.shared.global [%0], [%1], 16;" :: "r"(d), "l"(src));
}
__device__ __forceinline__ void cp_commit() { asm volatile("cp.async.commit_group;"); }
template<int N> __device__ __forceinline__ void cp_wait() {
    asm volatile("cp.async.wait_group %0;" :: "n"(N));
}

// ---------------------------------------------------------------------------
// Split kernels
// ---------------------------------------------------------------------------
__global__ __launch_bounds__(512)
void split_hl(const float4* __restrict__ x, uint2* __restrict__ hi,
              uint2* __restrict__ lo, int n4)
{
    int i = blockIdx.x * 512 + threadIdx.x;
    if (i >= n4) return;
    float4 v = x[i];
    float vv[4] = {v.x, v.y, v.z, v.w};
    uint16_t h[4], l[4];
#pragma unroll
    for (int k = 0; k < 4; k++) {
        h[k] = bfbits(vv[k]);
        l[k] = bfbits(vv[k] - bf2f(h[k]));
    }
    hi[i] = *(uint2*)h;
    lo[i] = *(uint2*)l;
}

// W [512 k][512 n] -> bf16 hi/lo transposed [512 n][512 k]
__global__ __launch_bounds__(256)
void splitW(const float* __restrict__ W, uint16_t* __restrict__ th,
            uint16_t* __restrict__ tl)
{
    __shared__ float tile[32][33];
    const int bx = blockIdx.x;   // n block
    const int by = blockIdx.y;   // k block
    const int x = threadIdx.x, y = threadIdx.y;
#pragma unroll
    for (int i = 0; i < 32; i += 8)
        tile[y + i][x] = W[(size_t)(by * 32 + y + i) * 512 + bx * 32 + x];
    __syncthreads();
#pragma unroll
    for (int i = 0; i < 32; i += 8) {
        float v = tile[x][y + i];
        uint16_t hb = bfbits(v);
        size_t o = (size_t)(bx * 32 + y + i) * 512 + by * 32 + x;
        th[o] = hb;
        tl[o] = bfbits(v - bf2f(hb));
    }
}

// ---------------------------------------------------------------------------
// bf16 tensor-core GEMM for Q/K projections (4-term exact split product).
// C[8192,512] = A @ W ; A: bf16 hi+lo [8192][512]; W: transposed bf16 [n][k].
// BM=128 BN=64 BK=32, 256 thr (8 warps: 4m x 2n of 32x32).
// Epilogue: scale, bf16 hi/lo interleaved [B,H,S,128], head = blockIdx.x.
// ---------------------------------------------------------------------------
__global__ __launch_bounds__(256)
void gemm_qk(const uint16_t* __restrict__ Ah, const uint16_t* __restrict__ Al,
             const uint16_t* __restrict__ Bh, const uint16_t* __restrict__ Bl,
             uint16_t* __restrict__ out, float scale)
{
    extern __shared__ uint16_t sb[];
    const int AU = 128 * 40, BU = 64 * 40;
    const int BUF = 2 * AU + 2 * BU;     // 15360 units per stage

    const int tid = threadIdx.x;
    const int warp = tid >> 5, lane = tid & 31;
    const int g = lane >> 2, t = lane & 3;
    const int wm = warp >> 1, wn = warp & 1;
    const int h  = blockIdx.x;
    const int n0 = h * 64;
    const int m0 = blockIdx.y * 128;

#define QK_STAGE(buf, kk_)                                                      \
    {                                                                           \
        uint16_t* _Ash = sb + (buf) * BUF;                                      \
        uint16_t* _Asl = _Ash + AU;                                             \
        uint16_t* _Bsh = _Ash + 2 * AU;                                         \
        uint16_t* _Bsl = _Bsh + BU;                                             \
        const int _k0 = (kk_) * 32;                                             \
        _Pragma("unroll")                                                       \
        for (int _j = 0; _j < 2; _j++) {                                        \
            int _c = tid + _j * 256, _r = _c >> 2, _q = _c & 3;                 \
            cp16g(_Ash + _r * 40 + _q * 8, Ah + (size_t)(m0 + _r) * 512 + _k0 + _q * 8); \
            cp16g(_Asl + _r * 40 + _q * 8, Al + (size_t)(m0 + _r) * 512 + _k0 + _q * 8); \
        }                                                                       \
        {                                                                       \
            int _r = tid >> 2, _q = tid & 3;                                    \
            cp16g(_Bsh + _r * 40 + _q * 8, Bh + (size_t)(n0 + _r) * 512 + _k0 + _q * 8); \
            cp16g(_Bsl + _r * 40 + _q * 8, Bl + (size_t)(n0 + _r) * 512 + _k0 + _q * 8); \
        }                                                                       \
    }

    float acc[2][4][4];
#pragma unroll
    for (int i = 0; i < 2; i++)
#pragma unroll
        for (int j = 0; j < 4; j++)
#pragma unroll
            for (int r = 0; r < 4; r++) acc[i][j][r] = 0.f;

    QK_STAGE(0, 0);
    cp_commit();

#pragma unroll 1
    for (int kk = 0; kk < 16; kk++) {
        cp_wait<0>();
        __syncthreads();
        if (kk < 15) { QK_STAGE((kk + 1) & 1, kk + 1); }
        cp_commit();

        const uint16_t* Ash = sb + (kk & 1) * BUF;
        const uint16_t* Asl = Ash + AU;
        const uint16_t* Bsh = Ash + 2 * AU;
        const uint16_t* Bsl = Bsh + BU;

#pragma unroll
        for (int kc = 0; kc < 2; kc++) {
            uint32_t ah_[2][4], al_[2][4];
#pragma unroll
            for (int mi = 0; mi < 2; mi++) {
                int base = (wm * 32 + mi * 16 + g) * 40 + kc * 16 + 2 * t;
                ah_[mi][0] = *(const uint32_t*)&Ash[base];
                ah_[mi][1] = *(const uint32_t*)&Ash[base + 320];
                ah_[mi][2] = *(const uint32_t*)&Ash[base + 8];
                ah_[mi][3] = *(const uint32_t*)&Ash[base + 328];
                al_[mi][0] = *(const uint32_t*)&Asl[base];
                al_[mi][1] = *(const uint32_t*)&Asl[base + 320];
                al_[mi][2] = *(const uint32_t*)&Asl[base + 8];
                al_[mi][3] = *(const uint32_t*)&Asl[base + 328];
            }
#pragma unroll
            for (int nj = 0; nj < 4; nj++) {
                int nb = (wn * 32 + nj * 8 + g) * 40 + kc * 16 + 2 * t;
                uint32_t bh0 = *(const uint32_t*)&Bsh[nb];
                uint32_t bh1 = *(const uint32_t*)&Bsh[nb + 8];
                uint32_t bl0 = *(const uint32_t*)&Bsl[nb];
                uint32_t bl1 = *(const uint32_t*)&Bsl[nb + 8];
#pragma unroll
                for (int mi = 0; mi < 2; mi++) {
                    mma16(acc[mi][nj], ah_[mi], bh0, bh1);
                    mma16(acc[mi][nj], al_[mi], bh0, bh1);
                    mma16(acc[mi][nj], ah_[mi], bl0, bl1);
                    mma16(acc[mi][nj], al_[mi], bl0, bl1);
                }
            }
        }
    }

    // epilogue: scale -> bf16 hi/lo interleaved [B,H,S,128]
#pragma unroll
    for (int mi = 0; mi < 2; mi++)
#pragma unroll
        for (int nj = 0; nj < 4; nj++) {
            int e = wn * 32 + nj * 8 + 2 * t;
#pragma unroll
            for (int half = 0; half < 2; half++) {
                int m = m0 + wm * 32 + mi * 16 + g + half * 8;
                int b = m >> 11, s = m & 2047;
                size_t base = (((size_t)b * Hq + h) * Sq + s) * 128 + e;
                float v0 = acc[mi][nj][half * 2]     * scale;
                float v1 = acc[mi][nj][half * 2 + 1] * scale;
                uint16_t h0 = bfbits(v0), h1 = bfbits(v1);
                uint16_t l0 = bfbits(v0 - bf2f(h0)), l1 = bfbits(v1 - bf2f(h1));
                *(uint32_t*)(out + base)      = (uint32_t)h0 | ((uint32_t)h1 << 16);
                *(uint32_t*)(out + base + 64) = (uint32_t)l0 | ((uint32_t)l1 << 16);
            }
        }
#undef QK_STAGE
}

// ---------------------------------------------------------------------------
// Round-6 proven fp32 SIMT GEMM (V projection + fc).
// MODE 1: fc + residual (fp32 out)
// MODE 3: projection -> transposed bf16, [B,H,64,S]
// ---------------------------------------------------------------------------
template <int MODE>
__global__ __launch_bounds__(256)
void gemm64(const float* __restrict__ A, const float* __restrict__ W,
            void* __restrict__ out0, const float* __restrict__ resid, float scale)
{
    __shared__ float As[32 * 68];
    __shared__ float Bs[32 * 68];

    const int tid = threadIdx.x;
    const int tx  = tid & 15;
    const int ty  = tid >> 4;
    const int n0  = blockIdx.x * 64;
    const int m0b = blockIdx.y * 64;

    float acc[4][4];
#pragma unroll
    for (int i = 0; i < 4; i++)
#pragma unroll
        for (int j = 0; j < 4; j++) acc[i][j] = 0.f;

    for (int k0 = 0; k0 < 512; k0 += 32) {
#pragma unroll
        for (int l = tid; l < 512; l += 256) {
            int m_l = l >> 3;
            int kq  = (l & 7) * 4;
            float4 v = *(const float4*)(A + (size_t)(m0b + m_l) * 512 + k0 + kq);
            As[(kq + 0) * 68 + m_l] = v.x;
            As[(kq + 1) * 68 + m_l] = v.y;
            As[(kq + 2) * 68 + m_l] = v.z;
            As[(kq + 3) * 68 + m_l] = v.w;
        }
#pragma unroll
        for (int l = tid; l < 512; l += 256) {
            int k_l = l >> 4;
            int nq  = (l & 15) * 4;
            float4 v = *(const float4*)(W + (size_t)(k0 + k_l) * 512 + n0 + nq);
            *(float4*)&Bs[k_l * 68 + nq] = v;
        }
        __syncthreads();

#pragma unroll
        for (int k = 0; k < 32; k++) {
            float4 a = *(float4*)&As[k * 68 + ty * 4];
            float4 b = *(float4*)&Bs[k * 68 + tx * 4];
            acc[0][0] += a.x * b.x; acc[0][1] += a.x * b.y; acc[0][2] += a.x * b.z; acc[0][3] += a.x * b.w;
            acc[1][0] += a.y * b.x; acc[1][1] += a.y * b.y; acc[1][2] += a.y * b.z; acc[1][3] += a.y * b.w;
            acc[2][0] += a.z * b.x; acc[2][1] += a.z * b.y; acc[2][2] += a.z * b.z; acc[2][3] += a.z * b.w;
            acc[3][0] += a.w * b.x; acc[3][1] += a.w * b.y; acc[3][2] += a.w * b.z; acc[3][3] += a.w * b.w;
        }
        __syncthreads();
    }

    if (MODE == 1) {
        float* out = (float*)out0;
#pragma unroll
        for (int i = 0; i < 4; i++) {
            int m = m0b + ty * 4 + i;
            float4 rv = *(const float4*)&resid[(size_t)m * 512 + n0 + tx * 4];
            float4 r = make_float4(acc[i][0] + rv.x, acc[i][1] + rv.y,
                                   acc[i][2] + rv.z, acc[i][3] + rv.w);
            *(float4*)&out[(size_t)m * 512 + n0 + tx * 4] = r;
        }
    } else {  // MODE 3: V transposed bf16 [B,H,d,S]
        const int h  = blockIdx.x;
        const int e0 = tx * 4;
        const int m0 = m0b + ty * 4;
        const int b  = m0 >> 11;
        const int s0 = m0 & 2047;
        uint16_t* o = (uint16_t*)out0;
        size_t rowbase = (size_t)(b * Hq + h) * 64;
#pragma unroll
        for (int j = 0; j < 4; j++) {
            uint16_t pk[4];
            pk[0] = bfbits(acc[0][j]);
            pk[1] = bfbits(acc[1][j]);
            pk[2] = bfbits(acc[2][j]);
            pk[3] = bfbits(acc[3][j]);
            *(uint2*)(o + (rowbase + e0 + j) * Sq + s0) = *(uint2*)pk;
        }
    }
}

// ---------------------------------------------------------------------------
// Fused attention — round-6 proven version verbatim (fp32 ctx output).
// ---------------------------------------------------------------------------
__global__ __launch_bounds__(512, 1)
void attn_kernel(const uint16_t* __restrict__ Qm, const uint16_t* __restrict__ Km,
                 const uint16_t* __restrict__ Vt, const unsigned* __restrict__ mask,
                 float* __restrict__ attn_out, float* __restrict__ ctx)
{
    extern __shared__ char smc[];
    float*    scores = (float*)smc;
    char*     Rb     = smc + OFF_R;
    uint16_t* pb     = (uint16_t*)Rb;
    char*     vtb    = smc + OFF_VT;
    uint16_t* qs     = (uint16_t*)vtb;

    const int bh  = blockIdx.x;
    const int qt  = blockIdx.y;
    const int b   = bh >> 3;
    const int h   = bh & 7;
    const int tid = threadIdx.x;
    const int warp = tid >> 5;
    const int lane = tid & 31;
    const int g = lane >> 2;
    const int t = lane & 3;
    const int wg = warp >> 3;
    const int wi = warp & 7;

    const uint16_t* KB = Km + (size_t)bh * Sq * 128;
    const uint16_t* VB = Vt + (size_t)bh * 64 * Sq;

#define STAGE_K(stg, kt_)                                                  \
    {                                                                      \
        char* _d = Rb + (stg) * KSTG_BYTES;                                \
        const uint16_t* _s = KB + (size_t)(kt_) * 128 * 128;               \
        _Pragma("unroll")                                                  \
        for (int _j = 0; _j < 4; _j++) {                                   \
            int _c = tid + _j * 512;                                       \
            int _r = _c >> 4, _c16 = _c & 15;                              \
            cp16g(_d + _r * 272 + _c16 * 16, _s + _r * 128 + _c16 * 8);    \
        }                                                                  \
    }
#define STAGE_V(stg, kt_)                                                  \
    {                                                                      \
        char* _d = vtb + (stg) * VSTG_BYTES;                               \
        const uint16_t* _s = VB + (size_t)(kt_) * 64;                      \
        int _dd = tid >> 3, _c = tid & 7;                                  \
        cp16g(_d + _dd * 144 + _c * 16, _s + (size_t)_dd * Sq + _c * 8);   \
    }

    STAGE_K(0, 0);
    cp_commit();
    if (tid < 256) {
        int r = tid >> 4, c16 = tid & 15;
        cp16g(vtb + r * 272 + c16 * 16,
              Qm + (size_t)bh * Sq * 128 + (size_t)(qt * 16 + r) * 128 + c16 * 8);
    }
    cp_commit();
    cp_wait<0>();
    __syncthreads();

    uint32_t qh[4][4], ql[4][4];
#pragma unroll
    for (int ch = 0; ch < 4; ch++) {
        int c0 = ch * 16 + 2 * t;
        qh[ch][0] = *(uint32_t*)&qs[g * 136 + c0];
        qh[ch][1] = *(uint32_t*)&qs[(g + 8) * 136 + c0];
        qh[ch][2] = *(uint32_t*)&qs[g * 136 + c0 + 8];
        qh[ch][3] = *(uint32_t*)&qs[(g + 8) * 136 + c0 + 8];
        ql[ch][0] = *(uint32_t*)&qs[g * 136 + c0 + 64];
        ql[ch][1] = *(uint32_t*)&qs[(g + 8) * 136 + c0 + 64];
        ql[ch][2] = *(uint32_t*)&qs[g * 136 + c0 + 72];
        ql[ch][3] = *(uint32_t*)&qs[(g + 8) * 136 + c0 + 72];
    }

    const int n0 = warp * 8;
#pragma unroll 1
    for (int kt = 0; kt < NTK; kt++) {
        if (kt + 1 < NTK) { STAGE_K((kt + 1) & 1, kt + 1); cp_commit(); }

        const uint16_t* kb_ = (const uint16_t*)(Rb + (kt & 1) * KSTG_BYTES);
        float acc[2][4] = {{0.f,0.f,0.f,0.f},{0.f,0.f,0.f,0.f}};
#pragma unroll
        for (int ch = 0; ch < 4; ch++) {
            const uint16_t* kr = &kb_[(n0 + g) * 136 + ch * 16 + 2 * t];
            uint32_t bh0 = *(const uint32_t*)kr;
            uint32_t bh1 = *(const uint32_t*)(kr + 8);
            uint32_t bl0 = *(const uint32_t*)(kr + 64);
            uint32_t bl1 = *(const uint32_t*)(kr + 72);
            mma16(acc[ch & 1], qh[ch], bh0, bh1);
            mma16(acc[ch & 1], ql[ch], bh0, bh1);
            mma16(acc[ch & 1], qh[ch], bl0, bl1);
        }
        int col = kt * 128 + n0 + 2 * t;
        *(float2*)&scores[g * SST + col]       = make_float2(acc[0][0] + acc[1][0], acc[0][1] + acc[1][1]);
        *(float2*)&scores[(g + 8) * SST + col] = make_float2(acc[0][2] + acc[1][2], acc[0][3] + acc[1][3]);

        if (kt + 1 < NTK) { cp_wait<0>(); __syncthreads(); }
    }

    STAGE_V(0, 0); cp_commit();
    STAGE_V(1, 1); cp_commit();
    __syncthreads();

    {
        const int row = warp;
        const int qg  = qt * 16 + row;
        const uint2* mrow2 = (const uint2*)(mask + ((size_t)b * Sq + qg) * Sq);
        float2* srow2 = (float2*)(scores + row * SST);

        float sum = 0.f;
#pragma unroll 4
        for (int i = lane; i < 1024; i += 32) {
            float2 s = srow2[i];
            uint2  m = mrow2[i];
            float px = m.x ? 0.f : __expf(s.x);
            float py = m.y ? 0.f : __expf(s.y);
            srow2[i] = make_float2(px, py);
            sum += px + py;
        }
#pragma unroll
        for (int o = 16; o; o >>= 1) sum += __shfl_xor_sync(0xffffffffu, sum, o);
        float inv = 1.0f / sum;

        uint32_t* prow = (uint32_t*)&pb[row * PBS];
        if (attn_out) {
            float2* arow2 = (float2*)(attn_out + ((size_t)bh * Sq + qg) * Sq);
#pragma unroll 4
            for (int i = lane; i < 1024; i += 32) {
                float2 p = srow2[i];
                float2 pn = make_float2(p.x * inv, p.y * inv);
                arow2[i] = pn;
                __nv_bfloat162 h2 = __float22bfloat162_rn(pn);
                prow[i] = *(uint32_t*)&h2;
            }
        } else {
#pragma unroll 4
            for (int i = lane; i < 1024; i += 32) {
                float2 p = srow2[i];
                float2 pn = make_float2(p.x * inv, p.y * inv);
                __nv_bfloat162 h2 = __float22bfloat162_rn(pn);
                prow[i] = *(uint32_t*)&h2;
            }
        }
    }

    float cacc[2][4] = {{0.f,0.f,0.f,0.f},{0.f,0.f,0.f,0.f}};
    const int d0w = wi * 8;
#pragma unroll 1
    for (int kt = 0; kt < NTV; kt++) {
        cp_wait<1>();
        __syncthreads();
        if (kt + 2 < NTV) { STAGE_V((kt + 2) % 3, kt + 2); }
        cp_commit();

        const uint16_t* vb_ = (const uint16_t*)(vtb + (kt % 3) * VSTG_BYTES);
        const int kb0 = kt * 64 + wg * 32;
#pragma unroll
        for (int sub = 0; sub < 2; sub++) {
            int k0 = kb0 + sub * 16;
            uint32_t a[4];
            const uint16_t* p0 = &pb[g * PBS + k0 + 2 * t];
            const uint16_t* p1 = &pb[(g + 8) * PBS + k0 + 2 * t];
            a[0] = *(const uint32_t*)p0;
            a[1] = *(const uint32_t*)p1;
            a[2] = *(const uint32_t*)(p0 + 8);
            a[3] = *(const uint32_t*)(p1 + 8);
            int kl = wg * 32 + sub * 16;
            const uint16_t* vr = &vb_[(d0w + g) * 72 + kl + 2 * t];
            uint32_t b0 = *(const uint32_t*)vr;
            uint32_t b1 = *(const uint32_t*)(vr + 8);
            mma16(cacc[sub], a, b0, b1);
        }
    }

    float2 r0 = make_float2(cacc[0][0] + cacc[1][0], cacc[0][1] + cacc[1][1]);
    float2 r1 = make_float2(cacc[0][2] + cacc[1][2], cacc[0][3] + cacc[1][3]);
    float* red = (float*)vtb;
    __syncthreads();
    if (wg == 1) {
        *(float2*)&red[g * 68 + d0w + 2 * t]       = r0;
        *(float2*)&red[(g + 8) * 68 + d0w + 2 * t] = r1;
    }
    __syncthreads();
    if (wg == 0) {
        float2 p0 = *(float2*)&red[g * 68 + d0w + 2 * t];
        float2 p1 = *(float2*)&red[(g + 8) * 68 + d0w + 2 * t];
        int qg   = qt * 16;
        int dcol = h * 64 + d0w + 2 * t;
        *(float2*)&ctx[((size_t)b * Sq + qg + g) * Dq + dcol] =
            make_float2(r0.x + p0.x, r0.y + p0.y);
        *(float2*)&ctx[((size_t)b * Sq + qg + g + 8) * Dq + dcol] =
            make_float2(r1.x + p1.x, r1.y + p1.y);
    }
#undef STAGE_K
#undef STAGE_V
}

// ---------------------------------------------------------------------------
__global__ __launch_bounds__(128)
void ln_kernel(const float* __restrict__ x, const float* __restrict__ gamma,
               const float* __restrict__ beta, float* __restrict__ out)
{
    const int row = blockIdx.x;
    const int tid = threadIdx.x;
    const float* xr = x + (size_t)row * 512;

    float4 v = *(const float4*)(xr + tid * 4);
    float s  = v.x + v.y + v.z + v.w;
    float ss = v.x * v.x + v.y * v.y + v.z * v.z + v.w * v.w;

    const int lane = tid & 31, warp = tid >> 5;
#pragma unroll
    for (int o = 16; o; o >>= 1) {
        s  += __shfl_xor_sync(0xffffffffu, s, o);
        ss += __shfl_xor_sync(0xffffffffu, ss, o);
    }
    __shared__ float sh_s[4], sh_ss[4];
    if (lane == 0) { sh_s[warp] = s; sh_ss[warp] = ss; }
    __syncthreads();
    float tot  = sh_s[0] + sh_s[1] + sh_s[2] + sh_s[3];
    float tots = sh_ss[0] + sh_ss[1] + sh_ss[2] + sh_ss[3];

    float mu   = tot * (1.0f / 512.0f);
    float var  = tots * (1.0f / 512.0f) - mu * mu;
    float rstd = rsqrtf(var + LN_EPS);

    float4 g  = *(const float4*)(gamma + tid * 4);
    float4 be = *(const float4*)(beta + tid * 4);
    float4 r;
    r.x = (v.x - mu) * rstd * g.x + be.x;
    r.y = (v.y - mu) * rstd * g.y + be.y;
    r.z = (v.z - mu) * rstd * g.z + be.z;
    r.w = (v.w - mu) * rstd * g.w + be.w;
    *(float4*)&out[(size_t)row * 512 + tid * 4] = r;
}

// ---------------------------------------------------------------------------
extern "C" void kernel_launch(void* const* d_in, const int* in_sizes, int n_in,
                              void* d_out, int out_size)
{
    const float*    inQ   = (const float*)d_in[0];
    const float*    inK   = (const float*)d_in[1];
    const float*    inV   = (const float*)d_in[2];
    const unsigned* mask  = (const unsigned*)d_in[3];
    const float*    WQ    = (const float*)d_in[4];
    const float*    WK    = (const float*)d_in[5];
    const float*    WV    = (const float*)d_in[6];
    const float*    Wfc   = (const float*)d_in[7];
    const float*    gamma = (const float*)d_in[8];
    const float*    beta  = (const float*)d_in[9];
    float* out = (float*)d_out;

    uint16_t *gQ, *gK, *gV;
    uint16_t *sQh, *sQl, *sKh, *sKl;
    uint16_t *wQh, *wQl, *wKh, *wKl;
    float *gctx, *gpre;
    cudaGetSymbolAddress((void**)&gQ,   g_Q);
    cudaGetSymbolAddress((void**)&gK,   g_K);
    cudaGetSymbolAddress((void**)&gV,   g_V);
    cudaGetSymbolAddress((void**)&gctx, g_ctx);
    cudaGetSymbolAddress((void**)&gpre, g_pre);
    cudaGetSymbolAddress((void**)&sQh, s_Qh);  cudaGetSymbolAddress((void**)&sQl, s_Ql);
    cudaGetSymbolAddress((void**)&sKh, s_Kh);  cudaGetSymbolAddress((void**)&sKl, s_Kl);
    cudaGetSymbolAddress((void**)&wQh, w_Qh);  cudaGetSymbolAddress((void**)&wQl, w_Ql);
    cudaGetSymbolAddress((void**)&wKh, w_Kh);  cudaGetSymbolAddress((void**)&wKl, w_Kl);

    const int n4 = (Bq * Sq * Dq) / 4;
    split_hl<<<(n4 + 511) / 512, 512>>>((const float4*)inQ, (uint2*)sQh, (uint2*)sQl, n4);
    split_hl<<<(n4 + 511) / 512, 512>>>((const float4*)inK, (uint2*)sKh, (uint2*)sKl, n4);
    splitW<<<dim3(16, 16), dim3(32, 8)>>>(WQ, wQh, wQl);
    splitW<<<dim3(16, 16), dim3(32, 8)>>>(WK, wKh, wKl);

    const int SMQK = (2 * 128 * 40 + 2 * 64 * 40) * 2 * 2;   // 61,440 B
    cudaFuncSetAttribute(gemm_qk, cudaFuncAttributeMaxDynamicSharedMemorySize, SMQK);

    gemm_qk<<<dim3(8, 64), 256, SMQK>>>(sQh, sQl, wQh, wQl, gQ, 0.125f);
    gemm_qk<<<dim3(8, 64), 256, SMQK>>>(sKh, sKl, wKh, wKl, gK, 1.0f);
    gemm64<3><<<dim3(8, 128), 256>>>(inV, WV, (void*)gV, nullptr, 1.0f);

    const size_t BSD  = (size_t)Bq * Sq * Dq;
    const size_t BHSS = (size_t)Bq * Hq * Sq * Sq;
    float* attn_ptr = ((size_t)out_size >= BSD + BHSS) ? (out + BSD) : nullptr;

    cudaFuncSetAttribute(attn_kernel, cudaFuncAttributeMaxDynamicSharedMemorySize, SMEM_ATTN);
    attn_kernel<<<dim3(32, 128), 512, SMEM_ATTN>>>(gQ, gK, gV, mask, attn_ptr, gctx);

    gemm64<1><<<dim3(8, 128), 256>>>(gctx, Wfc, (void*)gpre, inQ, 1.0f);
    ln_kernel<<<Bq * Sq, 128>>>(gpre, gamma, beta, out);
}

// round 9
// speedup vs baseline: 3.8802x; 1.0975x over previous
#include <cuda_runtime.h>
#include <cuda_bf16.h>
#include <cstdint>

// Problem constants
#define Bq   4
#define Sq   2048
#define Dq   512
#define Hq   8
#define LN_EPS 1e-5f

// attn smem layout (bytes) — round-6 proven
#define SST        2052
#define OFF_R      (16 * SST * 4)             // 131,328
#define KSTG_BYTES 34816
#define OFF_VT     (OFF_R + 2 * KSTG_BYTES)   // 200,960
#define VSTG_BYTES 9216
#define SMEM_ATTN  (OFF_VT + 3 * VSTG_BYTES)  // 228,608
#define PBS        2056
#define NTK        16
#define NTV        32

// Scratch (device globals)
__device__ __align__(16) uint16_t g_Q[(size_t)Bq*Hq*Sq*128];   // bf16 [B,H,S,(hi64|lo64)]
__device__ __align__(16) uint16_t g_K[(size_t)Bq*Hq*Sq*128];
__device__ __align__(16) uint16_t g_V[(size_t)Bq*Hq*64*Sq];    // bf16 transposed [B,H,d,S]
__device__ float    g_ctx[(size_t)Bq*Sq*Dq];                   // fp32 context
__device__ float    g_pre[(size_t)Bq*Sq*Dq];
// bf16 hi/lo splits
__device__ __align__(16) uint16_t s_Qh[(size_t)Bq*Sq*Dq], s_Ql[(size_t)Bq*Sq*Dq];
__device__ __align__(16) uint16_t s_Kh[(size_t)Bq*Sq*Dq], s_Kl[(size_t)Bq*Sq*Dq];
__device__ __align__(16) uint16_t s_Vh[(size_t)Bq*Sq*Dq], s_Vl[(size_t)Bq*Sq*Dq];
__device__ __align__(16) uint16_t s_Ch[(size_t)Bq*Sq*Dq], s_Cl[(size_t)Bq*Sq*Dq];
__device__ __align__(16) uint16_t w_Qh[512*512], w_Ql[512*512];
__device__ __align__(16) uint16_t w_Kh[512*512], w_Kl[512*512];
__device__ __align__(16) uint16_t w_Vh[512*512], w_Vl[512*512];
__device__ __align__(16) uint16_t w_Fh[512*512], w_Fl[512*512];

// ---------------------------------------------------------------------------
__device__ __forceinline__ uint16_t bfbits(float x) {
    __nv_bfloat16 b = __float2bfloat16_rn(x);
    return *(uint16_t*)&b;
}
__device__ __forceinline__ float bf2f(uint16_t u) {
    __nv_bfloat16 b = *(__nv_bfloat16*)&u;
    return __bfloat162float(b);
}

__device__ __forceinline__ void mma16(float* c, const uint32_t* a, uint32_t b0, uint32_t b1) {
    asm volatile(
        "mma.sync.aligned.m16n8k16.row.col.f32.bf16.bf16.f32 "
        "{%0,%1,%2,%3}, {%4,%5,%6,%7}, {%8,%9}, {%0,%1,%2,%3};"
        : "+f"(c[0]), "+f"(c[1]), "+f"(c[2]), "+f"(c[3])
        : "r"(a[0]), "r"(a[1]), "r"(a[2]), "r"(a[3]), "r"(b0), "r"(b1));
}

__device__ __forceinline__ void cp16g(void* dst, const void* src) {
    uint32_t d = (uint32_t)__cvta_generic_to_shared(dst);
    asm volatile("cp.async.cg.shared.global [%0], [%1], 16;" :: "r"(d), "l"(src));
}
__device__ __forceinline__ void cp_commit() { asm volatile("cp.async.commit_group;"); }
template<int N> __device__ __forceinline__ void cp_wait() {
    asm volatile("cp.async.wait_group %0;" :: "n"(N));
}

// ---------------------------------------------------------------------------
// Split kernels
// ---------------------------------------------------------------------------
__global__ __launch_bounds__(512)
void split_hl(const float4* __restrict__ x, uint2* __restrict__ hi,
              uint2* __restrict__ lo, int n4)
{
    int i = blockIdx.x * 512 + threadIdx.x;
    if (i >= n4) return;
    float4 v = x[i];
    float vv[4] = {v.x, v.y, v.z, v.w};
    uint16_t h[4], l[4];
#pragma unroll
    for (int k = 0; k < 4; k++) {
        h[k] = bfbits(vv[k]);
        l[k] = bfbits(vv[k] - bf2f(h[k]));
    }
    hi[i] = *(uint2*)h;
    lo[i] = *(uint2*)l;
}

// W [512 k][512 n] -> bf16 hi/lo transposed [512 n][512 k]
__global__ __launch_bounds__(256)
void splitW(const float* __restrict__ W, uint16_t* __restrict__ th,
            uint16_t* __restrict__ tl)
{
    __shared__ float tile[32][33];
    const int bx = blockIdx.x;   // n block
    const int by = blockIdx.y;   // k block
    const int x = threadIdx.x, y = threadIdx.y;
#pragma unroll
    for (int i = 0; i < 32; i += 8)
        tile[y + i][x] = W[(size_t)(by * 32 + y + i) * 512 + bx * 32 + x];
    __syncthreads();
#pragma unroll
    for (int i = 0; i < 32; i += 8) {
        float v = tile[x][y + i];
        uint16_t hb = bfbits(v);
        size_t o = (size_t)(bx * 32 + y + i) * 512 + by * 32 + x;
        th[o] = hb;
        tl[o] = bfbits(v - bf2f(hb));
    }
}

// ---------------------------------------------------------------------------
// bf16 tensor-core GEMM, 4-term exact split product (round-8 PROVEN mainloop).
// C[8192,512] = A @ W ; A: bf16 hi+lo [8192][512]; W: transposed bf16 [n][k] hi+lo.
// BM=128 BN=64 BK=32, 256 thr (8 warps: 4m x 2n of 32x32).
// MODE 0: scale -> bf16 hi/lo interleaved [B,H,S,128]   (Q/K, proven)
// MODE 1: direct scalar bf16 stores -> transposed [B,H,64,S]   (V)
// MODE 2: fp32 + residual -> [8192][512]   (fc)
// ---------------------------------------------------------------------------
template <int MODE>
__global__ __launch_bounds__(256)
void gemm4t(const uint16_t* __restrict__ Ah, const uint16_t* __restrict__ Al,
            const uint16_t* __restrict__ Bh, const uint16_t* __restrict__ Bl,
            void* __restrict__ out, const float* __restrict__ resid, float scale)
{
    extern __shared__ uint16_t sb[];
    const int AU = 128 * 40, BU = 64 * 40;
    const int BUF = 2 * AU + 2 * BU;

    const int tid = threadIdx.x;
    const int warp = tid >> 5, lane = tid & 31;
    const int g = lane >> 2, t = lane & 3;
    const int wm = warp >> 1, wn = warp & 1;
    const int h  = blockIdx.x;
    const int n0 = h * 64;
    const int m0 = blockIdx.y * 128;

#define QK_STAGE(buf, kk_)                                                      \
    {                                                                           \
        uint16_t* _Ash = sb + (buf) * BUF;                                      \
        uint16_t* _Asl = _Ash + AU;                                             \
        uint16_t* _Bsh = _Ash + 2 * AU;                                         \
        uint16_t* _Bsl = _Bsh + BU;                                             \
        const int _k0 = (kk_) * 32;                                             \
        _Pragma("unroll")                                                       \
        for (int _j = 0; _j < 2; _j++) {                                        \
            int _c = tid + _j * 256, _r = _c >> 2, _q = _c & 3;                 \
            cp16g(_Ash + _r * 40 + _q * 8, Ah + (size_t)(m0 + _r) * 512 + _k0 + _q * 8); \
            cp16g(_Asl + _r * 40 + _q * 8, Al + (size_t)(m0 + _r) * 512 + _k0 + _q * 8); \
        }                                                                       \
        {                                                                       \
            int _r = tid >> 2, _q = tid & 3;                                    \
            cp16g(_Bsh + _r * 40 + _q * 8, Bh + (size_t)(n0 + _r) * 512 + _k0 + _q * 8); \
            cp16g(_Bsl + _r * 40 + _q * 8, Bl + (size_t)(n0 + _r) * 512 + _k0 + _q * 8); \
        }                                                                       \
    }

    float acc[2][4][4];
#pragma unroll
    for (int i = 0; i < 2; i++)
#pragma unroll
        for (int j = 0; j < 4; j++)
#pragma unroll
            for (int r = 0; r < 4; r++) acc[i][j][r] = 0.f;

    QK_STAGE(0, 0);
    cp_commit();

#pragma unroll 1
    for (int kk = 0; kk < 16; kk++) {
        cp_wait<0>();
        __syncthreads();
        if (kk < 15) { QK_STAGE((kk + 1) & 1, kk + 1); }
        cp_commit();

        const uint16_t* Ash = sb + (kk & 1) * BUF;
        const uint16_t* Asl = Ash + AU;
        const uint16_t* Bsh = Ash + 2 * AU;
        const uint16_t* Bsl = Bsh + BU;

#pragma unroll
        for (int kc = 0; kc < 2; kc++) {
            uint32_t ah_[2][4], al_[2][4];
#pragma unroll
            for (int mi = 0; mi < 2; mi++) {
                int base = (wm * 32 + mi * 16 + g) * 40 + kc * 16 + 2 * t;
                ah_[mi][0] = *(const uint32_t*)&Ash[base];
                ah_[mi][1] = *(const uint32_t*)&Ash[base + 320];
                ah_[mi][2] = *(const uint32_t*)&Ash[base + 8];
                ah_[mi][3] = *(const uint32_t*)&Ash[base + 328];
                al_[mi][0] = *(const uint32_t*)&Asl[base];
                al_[mi][1] = *(const uint32_t*)&Asl[base + 320];
                al_[mi][2] = *(const uint32_t*)&Asl[base + 8];
                al_[mi][3] = *(const uint32_t*)&Asl[base + 328];
            }
#pragma unroll
            for (int nj = 0; nj < 4; nj++) {
                int nb = (wn * 32 + nj * 8 + g) * 40 + kc * 16 + 2 * t;
                uint32_t bh0 = *(const uint32_t*)&Bsh[nb];
                uint32_t bh1 = *(const uint32_t*)&Bsh[nb + 8];
                uint32_t bl0 = *(const uint32_t*)&Bsl[nb];
                uint32_t bl1 = *(const uint32_t*)&Bsl[nb + 8];
#pragma unroll
                for (int mi = 0; mi < 2; mi++) {
                    mma16(acc[mi][nj], ah_[mi], bh0, bh1);
                    mma16(acc[mi][nj], al_[mi], bh0, bh1);
                    mma16(acc[mi][nj], ah_[mi], bl0, bl1);
                    mma16(acc[mi][nj], al_[mi], bl0, bl1);
                }
            }
        }
    }

    if (MODE == 0) {
        // scale -> bf16 hi/lo interleaved [B,H,S,128]  (proven)
        uint16_t* o = (uint16_t*)out;
#pragma unroll
        for (int mi = 0; mi < 2; mi++)
#pragma unroll
            for (int nj = 0; nj < 4; nj++) {
                int e = wn * 32 + nj * 8 + 2 * t;
#pragma unroll
                for (int half = 0; half < 2; half++) {
                    int m = m0 + wm * 32 + mi * 16 + g + half * 8;
                    int b = m >> 11, s = m & 2047;
                    size_t base = (((size_t)b * Hq + h) * Sq + s) * 128 + e;
                    float v0 = acc[mi][nj][half * 2]     * scale;
                    float v1 = acc[mi][nj][half * 2 + 1] * scale;
                    uint16_t h0 = bfbits(v0), h1 = bfbits(v1);
                    uint16_t l0 = bfbits(v0 - bf2f(h0)), l1 = bfbits(v1 - bf2f(h1));
                    *(uint32_t*)(o + base)      = (uint32_t)h0 | ((uint32_t)h1 << 16);
                    *(uint32_t*)(o + base + 64) = (uint32_t)l0 | ((uint32_t)l1 << 16);
                }
            }
    } else if (MODE == 1) {
        // direct scalar bf16 stores -> [B,H,64,S]
        uint16_t* o = (uint16_t*)out;
        const int b  = m0 >> 11;
        const size_t hb64 = (size_t)(b * Hq + h) * 64;
#pragma unroll
        for (int mi = 0; mi < 2; mi++)
#pragma unroll
            for (int nj = 0; nj < 4; nj++) {
#pragma unroll
                for (int r = 0; r < 4; r++) {
                    int m = m0 + wm * 32 + mi * 16 + g + (r >> 1) * 8;
                    int d = wn * 32 + nj * 8 + 2 * t + (r & 1);
                    int s = m & 2047;
                    o[(hb64 + d) * Sq + s] = bfbits(acc[mi][nj][r]);
                }
            }
    } else {
        // fp32 + residual
        float* o = (float*)out;
#pragma unroll
        for (int mi = 0; mi < 2; mi++)
#pragma unroll
            for (int nj = 0; nj < 4; nj++) {
                int n = n0 + wn * 32 + nj * 8 + 2 * t;
#pragma unroll
                for (int half = 0; half < 2; half++) {
                    int m = m0 + wm * 32 + mi * 16 + g + half * 8;
                    float2 rv = *(const float2*)&resid[(size_t)m * 512 + n];
                    *(float2*)&o[(size_t)m * 512 + n] =
                        make_float2(acc[mi][nj][half * 2] + rv.x,
                                    acc[mi][nj][half * 2 + 1] + rv.y);
                }
            }
    }
#undef QK_STAGE
}

// ---------------------------------------------------------------------------
// Fused attention — round-6/8 proven version verbatim (fp32 ctx output).
// ---------------------------------------------------------------------------
__global__ __launch_bounds__(512, 1)
void attn_kernel(const uint16_t* __restrict__ Qm, const uint16_t* __restrict__ Km,
                 const uint16_t* __restrict__ Vt, const unsigned* __restrict__ mask,
                 float* __restrict__ attn_out, float* __restrict__ ctx)
{
    extern __shared__ char smc[];
    float*    scores = (float*)smc;
    char*     Rb     = smc + OFF_R;
    uint16_t* pb     = (uint16_t*)Rb;
    char*     vtb    = smc + OFF_VT;
    uint16_t* qs     = (uint16_t*)vtb;

    const int bh  = blockIdx.x;
    const int qt  = blockIdx.y;
    const int b   = bh >> 3;
    const int h   = bh & 7;
    const int tid = threadIdx.x;
    const int warp = tid >> 5;
    const int lane = tid & 31;
    const int g = lane >> 2;
    const int t = lane & 3;
    const int wg = warp >> 3;
    const int wi = warp & 7;

    const uint16_t* KB = Km + (size_t)bh * Sq * 128;
    const uint16_t* VB = Vt + (size_t)bh * 64 * Sq;

#define STAGE_K(stg, kt_)                                                  \
    {                                                                      \
        char* _d = Rb + (stg) * KSTG_BYTES;                                \
        const uint16_t* _s = KB + (size_t)(kt_) * 128 * 128;               \
        _Pragma("unroll")                                                  \
        for (int _j = 0; _j < 4; _j++) {                                   \
            int _c = tid + _j * 512;                                       \
            int _r = _c >> 4, _c16 = _c & 15;                              \
            cp16g(_d + _r * 272 + _c16 * 16, _s + _r * 128 + _c16 * 8);    \
        }                                                                  \
    }
#define STAGE_V(stg, kt_)                                                  \
    {                                                                      \
        char* _d = vtb + (stg) * VSTG_BYTES;                               \
        const uint16_t* _s = VB + (size_t)(kt_) * 64;                      \
        int _dd = tid >> 3, _c = tid & 7;                                  \
        cp16g(_d + _dd * 144 + _c * 16, _s + (size_t)_dd * Sq + _c * 8);   \
    }

    STAGE_K(0, 0);
    cp_commit();
    if (tid < 256) {
        int r = tid >> 4, c16 = tid & 15;
        cp16g(vtb + r * 272 + c16 * 16,
              Qm + (size_t)bh * Sq * 128 + (size_t)(qt * 16 + r) * 128 + c16 * 8);
    }
    cp_commit();
    cp_wait<0>();
    __syncthreads();

    uint32_t qh[4][4], ql[4][4];
#pragma unroll
    for (int ch = 0; ch < 4; ch++) {
        int c0 = ch * 16 + 2 * t;
        qh[ch][0] = *(uint32_t*)&qs[g * 136 + c0];
        qh[ch][1] = *(uint32_t*)&qs[(g + 8) * 136 + c0];
        qh[ch][2] = *(uint32_t*)&qs[g * 136 + c0 + 8];
        qh[ch][3] = *(uint32_t*)&qs[(g + 8) * 136 + c0 + 8];
        ql[ch][0] = *(uint32_t*)&qs[g * 136 + c0 + 64];
        ql[ch][1] = *(uint32_t*)&qs[(g + 8) * 136 + c0 + 64];
        ql[ch][2] = *(uint32_t*)&qs[g * 136 + c0 + 72];
        ql[ch][3] = *(uint32_t*)&qs[(g + 8) * 136 + c0 + 72];
    }

    const int n0 = warp * 8;
#pragma unroll 1
    for (int kt = 0; kt < NTK; kt++) {
        if (kt + 1 < NTK) { STAGE_K((kt + 1) & 1, kt + 1); cp_commit(); }

        const uint16_t* kb_ = (const uint16_t*)(Rb + (kt & 1) * KSTG_BYTES);
        float acc[2][4] = {{0.f,0.f,0.f,0.f},{0.f,0.f,0.f,0.f}};
#pragma unroll
        for (int ch = 0; ch < 4; ch++) {
            const uint16_t* kr = &kb_[(n0 + g) * 136 + ch * 16 + 2 * t];
            uint32_t bh0 = *(const uint32_t*)kr;
            uint32_t bh1 = *(const uint32_t*)(kr + 8);
            uint32_t bl0 = *(const uint32_t*)(kr + 64);
            uint32_t bl1 = *(const uint32_t*)(kr + 72);
            mma16(acc[ch & 1], qh[ch], bh0, bh1);
            mma16(acc[ch & 1], ql[ch], bh0, bh1);
            mma16(acc[ch & 1], qh[ch], bl0, bl1);
        }
        int col = kt * 128 + n0 + 2 * t;
        *(float2*)&scores[g * SST + col]       = make_float2(acc[0][0] + acc[1][0], acc[0][1] + acc[1][1]);
        *(float2*)&scores[(g + 8) * SST + col] = make_float2(acc[0][2] + acc[1][2], acc[0][3] + acc[1][3]);

        if (kt + 1 < NTK) { cp_wait<0>(); __syncthreads(); }
    }

    STAGE_V(0, 0); cp_commit();
    STAGE_V(1, 1); cp_commit();
    __syncthreads();

    {
        const int row = warp;
        const int qg  = qt * 16 + row;
        const uint2* mrow2 = (const uint2*)(mask + ((size_t)b * Sq + qg) * Sq);
        float2* srow2 = (float2*)(scores + row * SST);

        float sum = 0.f;
#pragma unroll 4
        for (int i = lane; i < 1024; i += 32) {
            float2 s = srow2[i];
            uint2  m = mrow2[i];
            float px = m.x ? 0.f : __expf(s.x);
            float py = m.y ? 0.f : __expf(s.y);
            srow2[i] = make_float2(px, py);
            sum += px + py;
        }
#pragma unroll
        for (int o = 16; o; o >>= 1) sum += __shfl_xor_sync(0xffffffffu, sum, o);
        float inv = 1.0f / sum;

        uint32_t* prow = (uint32_t*)&pb[row * PBS];
        if (attn_out) {
            float2* arow2 = (float2*)(attn_out + ((size_t)bh * Sq + qg) * Sq);
#pragma unroll 4
            for (int i = lane; i < 1024; i += 32) {
                float2 p = srow2[i];
                float2 pn = make_float2(p.x * inv, p.y * inv);
                arow2[i] = pn;
                __nv_bfloat162 h2 = __float22bfloat162_rn(pn);
                prow[i] = *(uint32_t*)&h2;
            }
        } else {
#pragma unroll 4
            for (int i = lane; i < 1024; i += 32) {
                float2 p = srow2[i];
                float2 pn = make_float2(p.x * inv, p.y * inv);
                __nv_bfloat162 h2 = __float22bfloat162_rn(pn);
                prow[i] = *(uint32_t*)&h2;
            }
        }
    }

    float cacc[2][4] = {{0.f,0.f,0.f,0.f},{0.f,0.f,0.f,0.f}};
    const int d0w = wi * 8;
#pragma unroll 1
    for (int kt = 0; kt < NTV; kt++) {
        cp_wait<1>();
        __syncthreads();
        if (kt + 2 < NTV) { STAGE_V((kt + 2) % 3, kt + 2); }
        cp_commit();

        const uint16_t* vb_ = (const uint16_t*)(vtb + (kt % 3) * VSTG_BYTES);
        const int kb0 = kt * 64 + wg * 32;
#pragma unroll
        for (int sub = 0; sub < 2; sub++) {
            int k0 = kb0 + sub * 16;
            uint32_t a[4];
            const uint16_t* p0 = &pb[g * PBS + k0 + 2 * t];
            const uint16_t* p1 = &pb[(g + 8) * PBS + k0 + 2 * t];
            a[0] = *(const uint32_t*)p0;
            a[1] = *(const uint32_t*)p1;
            a[2] = *(const uint32_t*)(p0 + 8);
            a[3] = *(const uint32_t*)(p1 + 8);
            int kl = wg * 32 + sub * 16;
            const uint16_t* vr = &vb_[(d0w + g) * 72 + kl + 2 * t];
            uint32_t b0 = *(const uint32_t*)vr;
            uint32_t b1 = *(const uint32_t*)(vr + 8);
            mma16(cacc[sub], a, b0, b1);
        }
    }

    float2 r0 = make_float2(cacc[0][0] + cacc[1][0], cacc[0][1] + cacc[1][1]);
    float2 r1 = make_float2(cacc[0][2] + cacc[1][2], cacc[0][3] + cacc[1][3]);
    float* red = (float*)vtb;
    __syncthreads();
    if (wg == 1) {
        *(float2*)&red[g * 68 + d0w + 2 * t]       = r0;
        *(float2*)&red[(g + 8) * 68 + d0w + 2 * t] = r1;
    }
    __syncthreads();
    if (wg == 0) {
        float2 p0 = *(float2*)&red[g * 68 + d0w + 2 * t];
        float2 p1 = *(float2*)&red[(g + 8) * 68 + d0w + 2 * t];
        int qg   = qt * 16;
        int dcol = h * 64 + d0w + 2 * t;
        *(float2*)&ctx[((size_t)b * Sq + qg + g) * Dq + dcol] =
            make_float2(r0.x + p0.x, r0.y + p0.y);
        *(float2*)&ctx[((size_t)b * Sq + qg + g + 8) * Dq + dcol] =
            make_float2(r1.x + p1.x, r1.y + p1.y);
    }
#undef STAGE_K
#undef STAGE_V
}

// ---------------------------------------------------------------------------
__global__ __launch_bounds__(128)
void ln_kernel(const float* __restrict__ x, const float* __restrict__ gamma,
               const float* __restrict__ beta, float* __restrict__ out)
{
    const int row = blockIdx.x;
    const int tid = threadIdx.x;
    const float* xr = x + (size_t)row * 512;

    float4 v = *(const float4*)(xr + tid * 4);
    float s  = v.x + v.y + v.z + v.w;
    float ss = v.x * v.x + v.y * v.y + v.z * v.z + v.w * v.w;

    const int lane = tid & 31, warp = tid >> 5;
#pragma unroll
    for (int o = 16; o; o >>= 1) {
        s  += __shfl_xor_sync(0xffffffffu, s, o);
        ss += __shfl_xor_sync(0xffffffffu, ss, o);
    }
    __shared__ float sh_s[4], sh_ss[4];
    if (lane == 0) { sh_s[warp] = s; sh_ss[warp] = ss; }
    __syncthreads();
    float tot  = sh_s[0] + sh_s[1] + sh_s[2] + sh_s[3];
    float tots = sh_ss[0] + sh_ss[1] + sh_ss[2] + sh_ss[3];

    float mu   = tot * (1.0f / 512.0f);
    float var  = tots * (1.0f / 512.0f) - mu * mu;
    float rstd = rsqrtf(var + LN_EPS);

    float4 g  = *(const float4*)(gamma + tid * 4);
    float4 be = *(const float4*)(beta + tid * 4);
    float4 r;
    r.x = (v.x - mu) * rstd * g.x + be.x;
    r.y = (v.y - mu) * rstd * g.y + be.y;
    r.z = (v.z - mu) * rstd * g.z + be.z;
    r.w = (v.w - mu) * rstd * g.w + be.w;
    *(float4*)&out[(size_t)row * 512 + tid * 4] = r;
}

// ---------------------------------------------------------------------------
extern "C" void kernel_launch(void* const* d_in, const int* in_sizes, int n_in,
                              void* d_out, int out_size)
{
    const float*    inQ   = (const float*)d_in[0];
    const float*    inK   = (const float*)d_in[1];
    const float*    inV   = (const float*)d_in[2];
    const unsigned* mask  = (const unsigned*)d_in[3];
    const float*    WQ    = (const float*)d_in[4];
    const float*    WK    = (const float*)d_in[5];
    const float*    WV    = (const float*)d_in[6];
    const float*    Wfc   = (const float*)d_in[7];
    const float*    gamma = (const float*)d_in[8];
    const float*    beta  = (const float*)d_in[9];
    float* out = (float*)d_out;

    uint16_t *gQ, *gK, *gV;
    uint16_t *sQh, *sQl, *sKh, *sKl, *sVh, *sVl, *sCh, *sCl;
    uint16_t *wQh, *wQl, *wKh, *wKl, *wVh, *wVl, *wFh, *wFl;
    float *gctx, *gpre;
    cudaGetSymbolAddress((void**)&gQ,   g_Q);
    cudaGetSymbolAddress((void**)&gK,   g_K);
    cudaGetSymbolAddress((void**)&gV,   g_V);
    cudaGetSymbolAddress((void**)&gctx, g_ctx);
    cudaGetSymbolAddress((void**)&gpre, g_pre);
    cudaGetSymbolAddress((void**)&sQh, s_Qh);  cudaGetSymbolAddress((void**)&sQl, s_Ql);
    cudaGetSymbolAddress((void**)&sKh, s_Kh);  cudaGetSymbolAddress((void**)&sKl, s_Kl);
    cudaGetSymbolAddress((void**)&sVh, s_Vh);  cudaGetSymbolAddress((void**)&sVl, s_Vl);
    cudaGetSymbolAddress((void**)&sCh, s_Ch);  cudaGetSymbolAddress((void**)&sCl, s_Cl);
    cudaGetSymbolAddress((void**)&wQh, w_Qh);  cudaGetSymbolAddress((void**)&wQl, w_Ql);
    cudaGetSymbolAddress((void**)&wKh, w_Kh);  cudaGetSymbolAddress((void**)&wKl, w_Kl);
    cudaGetSymbolAddress((void**)&wVh, w_Vh);  cudaGetSymbolAddress((void**)&wVl, w_Vl);
    cudaGetSymbolAddress((void**)&wFh, w_Fh);  cudaGetSymbolAddress((void**)&wFl, w_Fl);

    const int n4 = (Bq * Sq * Dq) / 4;
    split_hl<<<(n4 + 511) / 512, 512>>>((const float4*)inQ, (uint2*)sQh, (uint2*)sQl, n4);
    split_hl<<<(n4 + 511) / 512, 512>>>((const float4*)inK, (uint2*)sKh, (uint2*)sKl, n4);
    split_hl<<<(n4 + 511) / 512, 512>>>((const float4*)inV, (uint2*)sVh, (uint2*)sVl, n4);
    splitW<<<dim3(16, 16), dim3(32, 8)>>>(WQ,  wQh, wQl);
    splitW<<<dim3(16, 16), dim3(32, 8)>>>(WK,  wKh, wKl);
    splitW<<<dim3(16, 16), dim3(32, 8)>>>(WV,  wVh, wVl);
    splitW<<<dim3(16, 16), dim3(32, 8)>>>(Wfc, wFh, wFl);

    const int SMG = (2 * 128 * 40 + 2 * 64 * 40) * 2 * 2;   // 61,440 B
    cudaFuncSetAttribute(gemm4t<0>, cudaFuncAttributeMaxDynamicSharedMemorySize, SMG);
    cudaFuncSetAttribute(gemm4t<1>, cudaFuncAttributeMaxDynamicSharedMemorySize, SMG);
    cudaFuncSetAttribute(gemm4t<2>, cudaFuncAttributeMaxDynamicSharedMemorySize, SMG);

    gemm4t<0><<<dim3(8, 64), 256, SMG>>>(sQh, sQl, wQh, wQl, (void*)gQ, nullptr, 0.125f);
    gemm4t<0><<<dim3(8, 64), 256, SMG>>>(sKh, sKl, wKh, wKl, (void*)gK, nullptr, 1.0f);
    gemm4t<1><<<dim3(8, 64), 256, SMG>>>(sVh, sVl, wVh, wVl, (void*)gV, nullptr, 1.0f);

    const size_t BSD  = (size_t)Bq * Sq * Dq;
    const size_t BHSS = (size_t)Bq * Hq * Sq * Sq;
    float* attn_ptr = ((size_t)out_size >= BSD + BHSS) ? (out + BSD) : nullptr;

    cudaFuncSetAttribute(attn_kernel, cudaFuncAttributeMaxDynamicSharedMemorySize, SMEM_ATTN);
    attn_kernel<<<dim3(32, 128), 512, SMEM_ATTN>>>(gQ, gK, gV, mask, attn_ptr, gctx);

    split_hl<<<(n4 + 511) / 512, 512>>>((const float4*)gctx, (uint2*)sCh, (uint2*)sCl, n4);
    gemm4t<2><<<dim3(8, 64), 256, SMG>>>(sCh, sCl, wFh, wFl, (void*)gpre, inQ, 1.0f);
    ln_kernel<<<Bq * Sq, 128>>>(gpre, gamma, beta, out);
}

// round 10
// speedup vs baseline: 4.1127x; 1.0599x over previous
#include <cuda_runtime.h>
#include <cuda_bf16.h>
#include <cstdint>

// Problem constants
#define Bq   4
#define Sq   2048
#define Dq   512
#define Hq   8
#define LN_EPS 1e-5f

// attn smem layout (bytes)
#define SST        2052
#define OFF_R      (16 * SST * 4)             // 131,328
#define KSTG_BYTES 34816                      // K stage: 128 keys x 272B
#define VSTG2      17408                      // V stage: 64 d-rows x 272B (128 keys)
#define OFF_V0     (OFF_R + 65792)            // 197,120 (starts right after pb)
#define OFF_V1     (OFF_V0 + VSTG2)           // 214,528
#define SMEM_ATTN  (OFF_V1 + VSTG2)           // 231,936
#define PBS        2056
#define NTK        16
#define NTV        16                         // V tiles now 128 keys

// Scratch (device globals)
__device__ __align__(16) uint16_t g_Q[(size_t)Bq*Hq*Sq*128];   // bf16 [B,H,S,(hi64|lo64)]
__device__ __align__(16) uint16_t g_K[(size_t)Bq*Hq*Sq*128];
__device__ __align__(16) uint16_t g_V[(size_t)Bq*Hq*64*Sq];    // bf16 transposed [B,H,d,S]
__device__ float    g_ctx[(size_t)Bq*Sq*Dq];
__device__ float    g_pre[(size_t)Bq*Sq*Dq];
// bf16 hi/lo splits
__device__ __align__(16) uint16_t s_Qh[(size_t)Bq*Sq*Dq], s_Ql[(size_t)Bq*Sq*Dq];
__device__ __align__(16) uint16_t s_Kh[(size_t)Bq*Sq*Dq], s_Kl[(size_t)Bq*Sq*Dq];
__device__ __align__(16) uint16_t s_Vh[(size_t)Bq*Sq*Dq], s_Vl[(size_t)Bq*Sq*Dq];
__device__ __align__(16) uint16_t s_Ch[(size_t)Bq*Sq*Dq], s_Cl[(size_t)Bq*Sq*Dq];
__device__ __align__(16) uint16_t w_Qh[512*512], w_Ql[512*512];
__device__ __align__(16) uint16_t w_Kh[512*512], w_Kl[512*512];
__device__ __align__(16) uint16_t w_Vh[512*512], w_Vl[512*512];
__device__ __align__(16) uint16_t w_Fh[512*512], w_Fl[512*512];

// ---------------------------------------------------------------------------
__device__ __forceinline__ uint16_t bfbits(float x) {
    __nv_bfloat16 b = __float2bfloat16_rn(x);
    return *(uint16_t*)&b;
}
__device__ __forceinline__ float bf2f(uint16_t u) {
    __nv_bfloat16 b = *(__nv_bfloat16*)&u;
    return __bfloat162float(b);
}

__device__ __forceinline__ void mma16(float* c, const uint32_t* a, uint32_t b0, uint32_t b1) {
    asm volatile(
        "mma.sync.aligned.m16n8k16.row.col.f32.bf16.bf16.f32 "
        "{%0,%1,%2,%3}, {%4,%5,%6,%7}, {%8,%9}, {%0,%1,%2,%3};"
        : "+f"(c[0]), "+f"(c[1]), "+f"(c[2]), "+f"(c[3])
        : "r"(a[0]), "r"(a[1]), "r"(a[2]), "r"(a[3]), "r"(b0), "r"(b1));
}

__device__ __forceinline__ void cp16g(void* dst, const void* src) {
    uint32_t d = (uint32_t)__cvta_generic_to_shared(dst);
    asm volatile("cp.async.cg.shared.global [%0], [%1], 16;" :: "r"(d), "l"(src));
}
__device__ __forceinline__ void cp_commit() { asm volatile("cp.async.commit_group;"); }
template<int N> __device__ __forceinline__ void cp_wait() {
    asm volatile("cp.async.wait_group %0;" :: "n"(N));
}

// ---------------------------------------------------------------------------
// Merged split kernels
// ---------------------------------------------------------------------------
__global__ __launch_bounds__(512)
void split_in3(const float4* __restrict__ xQ, const float4* __restrict__ xK,
               const float4* __restrict__ xV,
               uint2* __restrict__ hQ, uint2* __restrict__ lQ,
               uint2* __restrict__ hK, uint2* __restrict__ lK,
               uint2* __restrict__ hV, uint2* __restrict__ lV, int n4)
{
    int i = blockIdx.x * 512 + threadIdx.x;
    if (i >= n4) return;
    const int y = blockIdx.y;
    const float4* x = (y == 0) ? xQ : (y == 1) ? xK : xV;
    uint2* hi = (y == 0) ? hQ : (y == 1) ? hK : hV;
    uint2* lo = (y == 0) ? lQ : (y == 1) ? lK : lV;
    float4 v = x[i];
    float vv[4] = {v.x, v.y, v.z, v.w};
    uint16_t h[4], l[4];
#pragma unroll
    for (int k = 0; k < 4; k++) {
        h[k] = bfbits(vv[k]);
        l[k] = bfbits(vv[k] - bf2f(h[k]));
    }
    hi[i] = *(uint2*)h;
    lo[i] = *(uint2*)l;
}

__global__ __launch_bounds__(512)
void split_hl(const float4* __restrict__ x, uint2* __restrict__ hi,
              uint2* __restrict__ lo, int n4)
{
    int i = blockIdx.x * 512 + threadIdx.x;
    if (i >= n4) return;
    float4 v = x[i];
    float vv[4] = {v.x, v.y, v.z, v.w};
    uint16_t h[4], l[4];
#pragma unroll
    for (int k = 0; k < 4; k++) {
        h[k] = bfbits(vv[k]);
        l[k] = bfbits(vv[k] - bf2f(h[k]));
    }
    hi[i] = *(uint2*)h;
    lo[i] = *(uint2*)l;
}

// 4 weights, transposed split: W [512 k][512 n] -> bf16 hi/lo [512 n][512 k]
__global__ __launch_bounds__(256)
void splitW4(const float* __restrict__ W0, const float* __restrict__ W1,
             const float* __restrict__ W2, const float* __restrict__ W3,
             uint16_t* __restrict__ h0, uint16_t* __restrict__ l0,
             uint16_t* __restrict__ h1, uint16_t* __restrict__ l1,
             uint16_t* __restrict__ h2, uint16_t* __restrict__ l2,
             uint16_t* __restrict__ h3, uint16_t* __restrict__ l3)
{
    __shared__ float tile[32][33];
    const int z = blockIdx.z;
    const float* W = (z == 0) ? W0 : (z == 1) ? W1 : (z == 2) ? W2 : W3;
    uint16_t* th = (z == 0) ? h0 : (z == 1) ? h1 : (z == 2) ? h2 : h3;
    uint16_t* tl = (z == 0) ? l0 : (z == 1) ? l1 : (z == 2) ? l2 : l3;
    const int bx = blockIdx.x;   // n block
    const int by = blockIdx.y;   // k block
    const int x = threadIdx.x, y = threadIdx.y;
#pragma unroll
    for (int i = 0; i < 32; i += 8)
        tile[y + i][x] = W[(size_t)(by * 32 + y + i) * 512 + bx * 32 + x];
    __syncthreads();
#pragma unroll
    for (int i = 0; i < 32; i += 8) {
        float v = tile[x][y + i];
        uint16_t hb = bfbits(v);
        size_t o = (size_t)(bx * 32 + y + i) * 512 + by * 32 + x;
        th[o] = hb;
        tl[o] = bfbits(v - bf2f(hb));
    }
}

// ---------------------------------------------------------------------------
// PROVEN 4-term bf16 mainloop as a device function.
// ---------------------------------------------------------------------------
__device__ __forceinline__ void gemm4t_mainloop(
    uint16_t* sb,
    const uint16_t* __restrict__ Ah, const uint16_t* __restrict__ Al,
    const uint16_t* __restrict__ Bh, const uint16_t* __restrict__ Bl,
    int m0, int n0, int tid, int wm, int wn, int g, int t,
    float acc[2][4][4])
{
    const int AU = 128 * 40, BU = 64 * 40;
    const int BUF = 2 * AU + 2 * BU;

#define QK_STAGE(buf, kk_)                                                      \
    {                                                                           \
        uint16_t* _Ash = sb + (buf) * BUF;                                      \
        uint16_t* _Asl = _Ash + AU;                                             \
        uint16_t* _Bsh = _Ash + 2 * AU;                                         \
        uint16_t* _Bsl = _Bsh + BU;                                             \
        const int _k0 = (kk_) * 32;                                             \
        _Pragma("unroll")                                                       \
        for (int _j = 0; _j < 2; _j++) {                                        \
            int _c = tid + _j * 256, _r = _c >> 2, _q = _c & 3;                 \
            cp16g(_Ash + _r * 40 + _q * 8, Ah + (size_t)(m0 + _r) * 512 + _k0 + _q * 8); \
            cp16g(_Asl + _r * 40 + _q * 8, Al + (size_t)(m0 + _r) * 512 + _k0 + _q * 8); \
        }                                                                       \
        {                                                                       \
            int _r = tid >> 2, _q = tid & 3;                                    \
            cp16g(_Bsh + _r * 40 + _q * 8, Bh + (size_t)(n0 + _r) * 512 + _k0 + _q * 8); \
            cp16g(_Bsl + _r * 40 + _q * 8, Bl + (size_t)(n0 + _r) * 512 + _k0 + _q * 8); \
        }                                                                       \
    }

    QK_STAGE(0, 0);
    cp_commit();

#pragma unroll 1
    for (int kk = 0; kk < 16; kk++) {
        cp_wait<0>();
        __syncthreads();
        if (kk < 15) { QK_STAGE((kk + 1) & 1, kk + 1); }
        cp_commit();

        const uint16_t* Ash = sb + (kk & 1) * BUF;
        const uint16_t* Asl = Ash + AU;
        const uint16_t* Bsh = Ash + 2 * AU;
        const uint16_t* Bsl = Bsh + BU;

#pragma unroll
        for (int kc = 0; kc < 2; kc++) {
            uint32_t ah_[2][4], al_[2][4];
#pragma unroll
            for (int mi = 0; mi < 2; mi++) {
                int base = (wm * 32 + mi * 16 + g) * 40 + kc * 16 + 2 * t;
                ah_[mi][0] = *(const uint32_t*)&Ash[base];
                ah_[mi][1] = *(const uint32_t*)&Ash[base + 320];
                ah_[mi][2] = *(const uint32_t*)&Ash[base + 8];
                ah_[mi][3] = *(const uint32_t*)&Ash[base + 328];
                al_[mi][0] = *(const uint32_t*)&Asl[base];
                al_[mi][1] = *(const uint32_t*)&Asl[base + 320];
                al_[mi][2] = *(const uint32_t*)&Asl[base + 8];
                al_[mi][3] = *(const uint32_t*)&Asl[base + 328];
            }
#pragma unroll
            for (int nj = 0; nj < 4; nj++) {
                int nb = (wn * 32 + nj * 8 + g) * 40 + kc * 16 + 2 * t;
                uint32_t bh0 = *(const uint32_t*)&Bsh[nb];
                uint32_t bh1 = *(const uint32_t*)&Bsh[nb + 8];
                uint32_t bl0 = *(const uint32_t*)&Bsl[nb];
                uint32_t bl1 = *(const uint32_t*)&Bsl[nb + 8];
#pragma unroll
                for (int mi = 0; mi < 2; mi++) {
                    mma16(acc[mi][nj], ah_[mi], bh0, bh1);
                    mma16(acc[mi][nj], al_[mi], bh0, bh1);
                    mma16(acc[mi][nj], ah_[mi], bl0, bl1);
                    mma16(acc[mi][nj], al_[mi], bl0, bl1);
                }
            }
        }
    }
#undef QK_STAGE
}

// ---------------------------------------------------------------------------
// Merged Q/K/V projection GEMM. z=0:Q (scale 1/8), z=1:K, z=2:V (transposed out).
// ---------------------------------------------------------------------------
__global__ __launch_bounds__(256)
void gemm_qkv(const uint16_t* __restrict__ Qh, const uint16_t* __restrict__ Ql_,
              const uint16_t* __restrict__ WQh, const uint16_t* __restrict__ WQl,
              uint16_t* __restrict__ outQ,
              const uint16_t* __restrict__ Kh, const uint16_t* __restrict__ Kl_,
              const uint16_t* __restrict__ WKh, const uint16_t* __restrict__ WKl,
              uint16_t* __restrict__ outK,
              const uint16_t* __restrict__ Vh, const uint16_t* __restrict__ Vl_,
              const uint16_t* __restrict__ WVh, const uint16_t* __restrict__ WVl,
              uint16_t* __restrict__ outV)
{
    extern __shared__ uint16_t sb[];
    const int z = blockIdx.z;
    const uint16_t* Ah = (z == 0) ? Qh : (z == 1) ? Kh : Vh;
    const uint16_t* Al = (z == 0) ? Ql_ : (z == 1) ? Kl_ : Vl_;
    const uint16_t* Bh = (z == 0) ? WQh : (z == 1) ? WKh : WVh;
    const uint16_t* Bl = (z == 0) ? WQl : (z == 1) ? WKl : WVl;
    uint16_t* out      = (z == 0) ? outQ : (z == 1) ? outK : outV;
    const float scale  = (z == 0) ? 0.125f : 1.0f;

    const int tid = threadIdx.x;
    const int warp = tid >> 5, lane = tid & 31;
    const int g = lane >> 2, t = lane & 3;
    const int wm = warp >> 1, wn = warp & 1;
    const int h  = blockIdx.x;
    const int n0 = h * 64;
    const int m0 = blockIdx.y * 128;

    float acc[2][4][4];
#pragma unroll
    for (int i = 0; i < 2; i++)
#pragma unroll
        for (int j = 0; j < 4; j++)
#pragma unroll
            for (int r = 0; r < 4; r++) acc[i][j][r] = 0.f;

    gemm4t_mainloop(sb, Ah, Al, Bh, Bl, m0, n0, tid, wm, wn, g, t, acc);

    if (z < 2) {
        // proven MODE 0: scale -> bf16 hi/lo interleaved [B,H,S,128]
#pragma unroll
        for (int mi = 0; mi < 2; mi++)
#pragma unroll
            for (int nj = 0; nj < 4; nj++) {
                int e = wn * 32 + nj * 8 + 2 * t;
#pragma unroll
                for (int half = 0; half < 2; half++) {
                    int m = m0 + wm * 32 + mi * 16 + g + half * 8;
                    int b = m >> 11, s = m & 2047;
                    size_t base = (((size_t)b * Hq + h) * Sq + s) * 128 + e;
                    float v0 = acc[mi][nj][half * 2]     * scale;
                    float v1 = acc[mi][nj][half * 2 + 1] * scale;
                    uint16_t h0 = bfbits(v0), h1 = bfbits(v1);
                    uint16_t l0 = bfbits(v0 - bf2f(h0)), l1 = bfbits(v1 - bf2f(h1));
                    *(uint32_t*)(out + base)      = (uint32_t)h0 | ((uint32_t)h1 << 16);
                    *(uint32_t*)(out + base + 64) = (uint32_t)l0 | ((uint32_t)l1 << 16);
                }
            }
    } else {
        // proven MODE 1: direct scalar bf16 stores -> [B,H,64,S]
        const int b  = m0 >> 11;
        const size_t hb64 = (size_t)(b * Hq + h) * 64;
#pragma unroll
        for (int mi = 0; mi < 2; mi++)
#pragma unroll
            for (int nj = 0; nj < 4; nj++) {
#pragma unroll
                for (int r = 0; r < 4; r++) {
                    int m = m0 + wm * 32 + mi * 16 + g + (r >> 1) * 8;
                    int d = wn * 32 + nj * 8 + 2 * t + (r & 1);
                    int s = m & 2047;
                    out[(hb64 + d) * Sq + s] = bfbits(acc[mi][nj][r]);
                }
            }
    }
}

// fc GEMM (proven MODE 2: fp32 + residual)
__global__ __launch_bounds__(256)
void gemm_fc(const uint16_t* __restrict__ Ah, const uint16_t* __restrict__ Al,
             const uint16_t* __restrict__ Bh, const uint16_t* __restrict__ Bl,
             float* __restrict__ out, const float* __restrict__ resid)
{
    extern __shared__ uint16_t sb[];
    const int tid = threadIdx.x;
    const int warp = tid >> 5, lane = tid & 31;
    const int g = lane >> 2, t = lane & 3;
    const int wm = warp >> 1, wn = warp & 1;
    const int n0 = blockIdx.x * 64;
    const int m0 = blockIdx.y * 128;

    float acc[2][4][4];
#pragma unroll
    for (int i = 0; i < 2; i++)
#pragma unroll
        for (int j = 0; j < 4; j++)
#pragma unroll
            for (int r = 0; r < 4; r++) acc[i][j][r] = 0.f;

    gemm4t_mainloop(sb, Ah, Al, Bh, Bl, m0, n0, tid, wm, wn, g, t, acc);

#pragma unroll
    for (int mi = 0; mi < 2; mi++)
#pragma unroll
        for (int nj = 0; nj < 4; nj++) {
            int n = n0 + wn * 32 + nj * 8 + 2 * t;
#pragma unroll
            for (int half = 0; half < 2; half++) {
                int m = m0 + wm * 32 + mi * 16 + g + half * 8;
                float2 rv = *(const float2*)&resid[(size_t)m * 512 + n];
                *(float2*)&out[(size_t)m * 512 + n] =
                    make_float2(acc[mi][nj][half * 2] + rv.x,
                                acc[mi][nj][half * 2 + 1] + rv.y);
            }
        }
}

// ---------------------------------------------------------------------------
// Fused attention. Phase 2 proven (buf parity flipped so tile15 -> buf0).
// Phase 5: 128-key V tiles, double-buffered (16 iterations).
// ---------------------------------------------------------------------------
__global__ __launch_bounds__(512, 1)
void attn_kernel(const uint16_t* __restrict__ Qm, const uint16_t* __restrict__ Km,
                 const uint16_t* __restrict__ Vt, const unsigned* __restrict__ mask,
                 float* __restrict__ attn_out, float* __restrict__ ctx)
{
    extern __shared__ char smc[];
    float*    scores = (float*)smc;
    char*     Rb     = smc + OFF_R;              // K double buffer / pb
    uint16_t* pb     = (uint16_t*)Rb;
    char*     Vbuf   = smc + OFF_V0;             // 2 x VSTG2
    uint16_t* qs     = (uint16_t*)(smc + OFF_V1); // Q stage (prologue only)

    const int bh  = blockIdx.x;
    const int qt  = blockIdx.y;
    const int b   = bh >> 3;
    const int h   = bh & 7;
    const int tid = threadIdx.x;
    const int warp = tid >> 5;
    const int lane = tid & 31;
    const int g = lane >> 2;
    const int t = lane & 3;
    const int wg = warp >> 3;
    const int wi = warp & 7;

    const uint16_t* KB = Km + (size_t)bh * Sq * 128;
    const uint16_t* VB = Vt + (size_t)bh * 64 * Sq;

#define STAGE_K(stg, kt_)                                                  \
    {                                                                      \
        char* _d = Rb + (stg) * KSTG_BYTES;                                \
        const uint16_t* _s = KB + (size_t)(kt_) * 128 * 128;               \
        _Pragma("unroll")                                                  \
        for (int _j = 0; _j < 4; _j++) {                                   \
            int _c = tid + _j * 512;                                       \
            int _r = _c >> 4, _c16 = _c & 15;                              \
            cp16g(_d + _r * 272 + _c16 * 16, _s + _r * 128 + _c16 * 8);    \
        }                                                                  \
    }
// V tile: 64 d-rows x 128 keys (256B data + 16B pad per row)
#define STAGE_V(stg, kt_)                                                  \
    {                                                                      \
        char* _d = Vbuf + (stg) * VSTG2;                                   \
        const uint16_t* _s = VB + (size_t)(kt_) * 128;                     \
        _Pragma("unroll")                                                  \
        for (int _j = 0; _j < 2; _j++) {                                   \
            int _i = tid + _j * 512;                                       \
            int _dd = _i >> 4, _c = _i & 15;                               \
            cp16g(_d + _dd * 272 + _c * 16, _s + (size_t)_dd * Sq + _c * 8);\
        }                                                                  \
    }

    // prologue: K tile 0 -> buf1 (so tile15 lands in buf0), Q -> OFF_V1
    STAGE_K(1, 0);
    cp_commit();
    if (tid < 256) {
        int r = tid >> 4, c16 = tid & 15;
        cp16g((char*)qs + r * 272 + c16 * 16,
              Qm + (size_t)bh * Sq * 128 + (size_t)(qt * 16 + r) * 128 + c16 * 8);
    }
    cp_commit();
    cp_wait<0>();
    __syncthreads();

    uint32_t qh[4][4], ql[4][4];
#pragma unroll
    for (int ch = 0; ch < 4; ch++) {
        int c0 = ch * 16 + 2 * t;
        qh[ch][0] = *(uint32_t*)&qs[g * 136 + c0];
        qh[ch][1] = *(uint32_t*)&qs[(g + 8) * 136 + c0];
        qh[ch][2] = *(uint32_t*)&qs[g * 136 + c0 + 8];
        qh[ch][3] = *(uint32_t*)&qs[(g + 8) * 136 + c0 + 8];
        ql[ch][0] = *(uint32_t*)&qs[g * 136 + c0 + 64];
        ql[ch][1] = *(uint32_t*)&qs[(g + 8) * 136 + c0 + 64];
        ql[ch][2] = *(uint32_t*)&qs[g * 136 + c0 + 72];
        ql[ch][3] = *(uint32_t*)&qs[(g + 8) * 136 + c0 + 72];
    }

    // ---- phase 2: scores = Q @ K^T ----
    const int n0 = warp * 8;
#pragma unroll 1
    for (int kt = 0; kt < NTK; kt++) {
        if (kt + 1 < NTK) { STAGE_K(kt & 1, kt + 1); cp_commit(); }

        const uint16_t* kb_ = (const uint16_t*)(Rb + ((kt & 1) ^ 1) * KSTG_BYTES);
        float acc[2][4] = {{0.f,0.f,0.f,0.f},{0.f,0.f,0.f,0.f}};
#pragma unroll
        for (int ch = 0; ch < 4; ch++) {
            const uint16_t* kr = &kb_[(n0 + g) * 136 + ch * 16 + 2 * t];
            uint32_t bh0 = *(const uint32_t*)kr;
            uint32_t bh1 = *(const uint32_t*)(kr + 8);
            uint32_t bl0 = *(const uint32_t*)(kr + 64);
            uint32_t bl1 = *(const uint32_t*)(kr + 72);
            mma16(acc[ch & 1], qh[ch], bh0, bh1);
            mma16(acc[ch & 1], ql[ch], bh0, bh1);
            mma16(acc[ch & 1], qh[ch], bl0, bl1);
        }
        int col = kt * 128 + n0 + 2 * t;
        *(float2*)&scores[g * SST + col]       = make_float2(acc[0][0] + acc[1][0], acc[0][1] + acc[1][1]);
        *(float2*)&scores[(g + 8) * SST + col] = make_float2(acc[0][2] + acc[1][2], acc[0][3] + acc[1][3]);

        if (kt + 1 < NTK) { cp_wait<0>(); __syncthreads(); }
    }

    // stage V tile 0 (V0 overlaps only the tail of K buf1 = tile14, already consumed)
    STAGE_V(0, 0); cp_commit();
    __syncthreads();   // all phase-2 done; scores visible; pb region free

    // ---- phase 3/4: mask+exp+sum, then normalize + attn write + bf16 P pack ----
    {
        const int row = warp;
        const int qg  = qt * 16 + row;
        const uint2* mrow2 = (const uint2*)(mask + ((size_t)b * Sq + qg) * Sq);
        float2* srow2 = (float2*)(scores + row * SST);

        float sum = 0.f;
#pragma unroll 4
        for (int i = lane; i < 1024; i += 32) {
            float2 s = srow2[i];
            uint2  m = mrow2[i];
            float px = m.x ? 0.f : __expf(s.x);
            float py = m.y ? 0.f : __expf(s.y);
            srow2[i] = make_float2(px, py);
            sum += px + py;
        }
#pragma unroll
        for (int o = 16; o; o >>= 1) sum += __shfl_xor_sync(0xffffffffu, sum, o);
        float inv = 1.0f / sum;

        uint32_t* prow = (uint32_t*)&pb[row * PBS];
        if (attn_out) {
            float2* arow2 = (float2*)(attn_out + ((size_t)bh * Sq + qg) * Sq);
#pragma unroll 4
            for (int i = lane; i < 1024; i += 32) {
                float2 p = srow2[i];
                float2 pn = make_float2(p.x * inv, p.y * inv);
                arow2[i] = pn;
                __nv_bfloat162 h2 = __float22bfloat162_rn(pn);
                prow[i] = *(uint32_t*)&h2;
            }
        } else {
#pragma unroll 4
            for (int i = lane; i < 1024; i += 32) {
                float2 p = srow2[i];
                float2 pn = make_float2(p.x * inv, p.y * inv);
                __nv_bfloat162 h2 = __float22bfloat162_rn(pn);
                prow[i] = *(uint32_t*)&h2;
            }
        }
    }

    // ---- phase 5: ctx = P @ V (128-key tiles, double-buffered) ----
    float cacc[2][4] = {{0.f,0.f,0.f,0.f},{0.f,0.f,0.f,0.f}};
    const int d0w = wi * 8;
#pragma unroll 1
    for (int kt = 0; kt < NTV; kt++) {
        cp_wait<0>();
        __syncthreads();
        if (kt + 1 < NTV) { STAGE_V((kt + 1) & 1, kt + 1); }
        cp_commit();

        const uint16_t* vb_ = (const uint16_t*)(Vbuf + (kt & 1) * VSTG2);
        const int kb0 = kt * 128 + wg * 64;
#pragma unroll
        for (int sub = 0; sub < 4; sub++) {
            int k0 = kb0 + sub * 16;
            uint32_t a[4];
            const uint16_t* p0 = &pb[g * PBS + k0 + 2 * t];
            const uint16_t* p1 = &pb[(g + 8) * PBS + k0 + 2 * t];
            a[0] = *(const uint32_t*)p0;
            a[1] = *(const uint32_t*)p1;
            a[2] = *(const uint32_t*)(p0 + 8);
            a[3] = *(const uint32_t*)(p1 + 8);
            int kl = wg * 64 + sub * 16;              // local key within 128-key tile
            const uint16_t* vr = &vb_[(d0w + g) * 136 + kl + 2 * t];
            uint32_t b0 = *(const uint32_t*)vr;
            uint32_t b1 = *(const uint32_t*)(vr + 8);
            mma16(cacc[sub & 1], a, b0, b1);
        }
    }

    // cross-group reduction via V0 region (exact fp32)
    float2 r0 = make_float2(cacc[0][0] + cacc[1][0], cacc[0][1] + cacc[1][1]);
    float2 r1 = make_float2(cacc[0][2] + cacc[1][2], cacc[0][3] + cacc[1][3]);
    float* red = (float*)Vbuf;
    __syncthreads();
    if (wg == 1) {
        *(float2*)&red[g * 68 + d0w + 2 * t]       = r0;
        *(float2*)&red[(g + 8) * 68 + d0w + 2 * t] = r1;
    }
    __syncthreads();
    if (wg == 0) {
        float2 p0 = *(float2*)&red[g * 68 + d0w + 2 * t];
        float2 p1 = *(float2*)&red[(g + 8) * 68 + d0w + 2 * t];
        int qg   = qt * 16;
        int dcol = h * 64 + d0w + 2 * t;
        *(float2*)&ctx[((size_t)b * Sq + qg + g) * Dq + dcol] =
            make_float2(r0.x + p0.x, r0.y + p0.y);
        *(float2*)&ctx[((size_t)b * Sq + qg + g + 8) * Dq + dcol] =
            make_float2(r1.x + p1.x, r1.y + p1.y);
    }
#undef STAGE_K
#undef STAGE_V
}

// ---------------------------------------------------------------------------
__global__ __launch_bounds__(128)
void ln_kernel(const float* __restrict__ x, const float* __restrict__ gamma,
               const float* __restrict__ beta, float* __restrict__ out)
{
    const int row = blockIdx.x;
    const int tid = threadIdx.x;
    const float* xr = x + (size_t)row * 512;

    float4 v = *(const float4*)(xr + tid * 4);
    float s  = v.x + v.y + v.z + v.w;
    float ss = v.x * v.x + v.y * v.y + v.z * v.z + v.w * v.w;

    const int lane = tid & 31, warp = tid >> 5;
#pragma unroll
    for (int o = 16; o; o >>= 1) {
        s  += __shfl_xor_sync(0xffffffffu, s, o);
        ss += __shfl_xor_sync(0xffffffffu, ss, o);
    }
    __shared__ float sh_s[4], sh_ss[4];
    if (lane == 0) { sh_s[warp] = s; sh_ss[warp] = ss; }
    __syncthreads();
    float tot  = sh_s[0] + sh_s[1] + sh_s[2] + sh_s[3];
    float tots = sh_ss[0] + sh_ss[1] + sh_ss[2] + sh_ss[3];

    float mu   = tot * (1.0f / 512.0f);
    float var  = tots * (1.0f / 512.0f) - mu * mu;
    float rstd = rsqrtf(var + LN_EPS);

    float4 g  = *(const float4*)(gamma + tid * 4);
    float4 be = *(const float4*)(beta + tid * 4);
    float4 r;
    r.x = (v.x - mu) * rstd * g.x + be.x;
    r.y = (v.y - mu) * rstd * g.y + be.y;
    r.z = (v.z - mu) * rstd * g.z + be.z;
    r.w = (v.w - mu) * rstd * g.w + be.w;
    *(float4*)&out[(size_t)row * 512 + tid * 4] = r;
}

// ---------------------------------------------------------------------------
extern "C" void kernel_launch(void* const* d_in, const int* in_sizes, int n_in,
                              void* d_out, int out_size)
{
    const float*    inQ   = (const float*)d_in[0];
    const float*    inK   = (const float*)d_in[1];
    const float*    inV   = (const float*)d_in[2];
    const unsigned* mask  = (const unsigned*)d_in[3];
    const float*    WQ    = (const float*)d_in[4];
    const float*    WK    = (const float*)d_in[5];
    const float*    WV    = (const float*)d_in[6];
    const float*    Wfc   = (const float*)d_in[7];
    const float*    gamma = (const float*)d_in[8];
    const float*    beta  = (const float*)d_in[9];
    float* out = (float*)d_out;

    uint16_t *gQ, *gK, *gV;
    uint16_t *sQh, *sQl, *sKh, *sKl, *sVh, *sVl, *sCh, *sCl;
    uint16_t *wQh, *wQl, *wKh, *wKl, *wVh, *wVl, *wFh, *wFl;
    float *gctx, *gpre;
    cudaGetSymbolAddress((void**)&gQ,   g_Q);
    cudaGetSymbolAddress((void**)&gK,   g_K);
    cudaGetSymbolAddress((void**)&gV,   g_V);
    cudaGetSymbolAddress((void**)&gctx, g_ctx);
    cudaGetSymbolAddress((void**)&gpre, g_pre);
    cudaGetSymbolAddress((void**)&sQh, s_Qh);  cudaGetSymbolAddress((void**)&sQl, s_Ql);
    cudaGetSymbolAddress((void**)&sKh, s_Kh);  cudaGetSymbolAddress((void**)&sKl, s_Kl);
    cudaGetSymbolAddress((void**)&sVh, s_Vh);  cudaGetSymbolAddress((void**)&sVl, s_Vl);
    cudaGetSymbolAddress((void**)&sCh, s_Ch);  cudaGetSymbolAddress((void**)&sCl, s_Cl);
    cudaGetSymbolAddress((void**)&wQh, w_Qh);  cudaGetSymbolAddress((void**)&wQl, w_Ql);
    cudaGetSymbolAddress((void**)&wKh, w_Kh);  cudaGetSymbolAddress((void**)&wKl, w_Kl);
    cudaGetSymbolAddress((void**)&wVh, w_Vh);  cudaGetSymbolAddress((void**)&wVl, w_Vl);
    cudaGetSymbolAddress((void**)&wFh, w_Fh);  cudaGetSymbolAddress((void**)&wFl, w_Fl);

    const int n4 = (Bq * Sq * Dq) / 4;
    split_in3<<<dim3((n4 + 511) / 512, 3), 512>>>(
        (const float4*)inQ, (const float4*)inK, (const float4*)inV,
        (uint2*)sQh, (uint2*)sQl, (uint2*)sKh, (uint2*)sKl,
        (uint2*)sVh, (uint2*)sVl, n4);
    splitW4<<<dim3(16, 16, 4), dim3(32, 8)>>>(WQ, WK, WV, Wfc,
        wQh, wQl, wKh, wKl, wVh, wVl, wFh, wFl);

    const int SMG = (2 * 128 * 40 + 2 * 64 * 40) * 2 * 2;   // 61,440 B
    cudaFuncSetAttribute(gemm_qkv, cudaFuncAttributeMaxDynamicSharedMemorySize, SMG);
    cudaFuncSetAttribute(gemm_fc,  cudaFuncAttributeMaxDynamicSharedMemorySize, SMG);

    gemm_qkv<<<dim3(8, 64, 3), 256, SMG>>>(
        sQh, sQl, wQh, wQl, gQ,
        sKh, sKl, wKh, wKl, gK,
        sVh, sVl, wVh, wVl, gV);

    const size_t BSD  = (size_t)Bq * Sq * Dq;
    const size_t BHSS = (size_t)Bq * Hq * Sq * Sq;
    float* attn_ptr = ((size_t)out_size >= BSD + BHSS) ? (out + BSD) : nullptr;

    cudaFuncSetAttribute(attn_kernel, cudaFuncAttributeMaxDynamicSharedMemorySize, SMEM_ATTN);
    attn_kernel<<<dim3(32, 128), 512, SMEM_ATTN>>>(gQ, gK, gV, mask, attn_ptr, gctx);

    split_hl<<<(n4 + 511) / 512, 512>>>((const float4*)gctx, (uint2*)sCh, (uint2*)sCl, n4);
    gemm_fc<<<dim3(8, 64), 256, SMG>>>(sCh, sCl, wFh, wFl, gpre, inQ);
    ln_kernel<<<Bq * Sq, 128>>>(gpre, gamma, beta, out);
}